// round 1
// baseline (speedup 1.0000x reference)
#include <cuda_runtime.h>
#include <cuda_bf16.h>
#include <math.h>

#define NND 100000
#define NE  1600000
#define DF  128
#define HEADS 4
#define OUTC 32
#define NG  64
#define NCLS 10
#define NEG 0.2f

// ---------------- scratch (device globals; no allocation allowed) -----------
__device__ float    g_XW[NND * DF];       // x @ W for current layer
__device__ float    g_H [NND * DF];       // layer output / next-layer input
__device__ float    g_al[NND * HEADS];
__device__ float    g_ar[NND * HEADS];
__device__ unsigned g_menc[NND * HEADS];  // float-ordered encoded max
__device__ float    g_z [NND * HEADS];
__device__ float    g_pool[NG * DF];
__device__ int      g_cnt[NG];

// ---------------- helpers ---------------------------------------------------
__device__ __forceinline__ unsigned fenc(float f) {
    unsigned u = __float_as_uint(f);
    return (u & 0x80000000u) ? ~u : (u | 0x80000000u);
}
__device__ __forceinline__ float fdec(unsigned u) {
    return (u & 0x80000000u) ? __uint_as_float(u & 0x7FFFFFFFu)
                             : __uint_as_float(~u);
}
__device__ __forceinline__ float lrelu(float x) { return x > 0.f ? x : NEG * x; }

__device__ __forceinline__ void redAdd4(float* p, float4 v) {
    asm volatile("red.global.add.v4.f32 [%0], {%1,%2,%3,%4};"
                 :: "l"(p), "f"(v.x), "f"(v.y), "f"(v.z), "f"(v.w) : "memory");
}

// ---------------- GEMM: C[n,128] = (relu?)(A[n,128]) @ W[128,128] ------------
__global__ void gemm_nk128(const float* __restrict__ A, const float* __restrict__ W,
                           float* __restrict__ C, int n, int reluIn) {
    __shared__ float Xs[64][33];
    __shared__ float Ws[32][128];
    int t   = threadIdx.x;          // 256 threads
    int row0 = blockIdx.x * 64;
    int cg  = t & 31;               // column group: cols 4*cg..4*cg+3
    int rg  = t >> 5;               // row group: rows rg*8..rg*8+7
    float acc[8][4];
#pragma unroll
    for (int r = 0; r < 8; r++) { acc[r][0]=acc[r][1]=acc[r][2]=acc[r][3]=0.f; }

    for (int k0 = 0; k0 < 128; k0 += 32) {
#pragma unroll
        for (int j = 0; j < 8; j++) {
            int idx = t + j * 256;
            int r = idx >> 5, c = idx & 31;
            int row = row0 + r;
            float v = (row < n) ? A[row * 128 + k0 + c] : 0.f;
            if (reluIn) v = fmaxf(v, 0.f);
            Xs[r][c] = v;
        }
#pragma unroll
        for (int j = 0; j < 16; j++) {
            int idx = t + j * 256;
            int r = idx >> 7, c = idx & 127;
            Ws[r][c] = W[(k0 + r) * 128 + c];
        }
        __syncthreads();
#pragma unroll
        for (int kk = 0; kk < 32; kk++) {
            float4 w = *(float4*)&Ws[kk][cg * 4];
#pragma unroll
            for (int r = 0; r < 8; r++) {
                float xv = Xs[rg * 8 + r][kk];
                acc[r][0] += xv * w.x; acc[r][1] += xv * w.y;
                acc[r][2] += xv * w.z; acc[r][3] += xv * w.w;
            }
        }
        __syncthreads();
    }
#pragma unroll
    for (int r = 0; r < 8; r++) {
        int row = row0 + rg * 8 + r;
        if (row < n)
            *(float4*)&C[row * 128 + cg * 4] =
                make_float4(acc[r][0], acc[r][1], acc[r][2], acc[r][3]);
    }
}

// ---------------- al/ar per node + m init with self-loop logit ---------------
__global__ void alar_kernel(const float* __restrict__ attl,
                            const float* __restrict__ attr, int n) {
    int wid = (blockIdx.x * blockDim.x + threadIdx.x) >> 5;
    int l = threadIdx.x & 31;
    if (wid >= n) return;
    float alh[HEADS], arh[HEADS];
#pragma unroll
    for (int h = 0; h < HEADS; h++) {
        float v  = g_XW[wid * 128 + h * 32 + l];
        float pa = v * attl[h * 32 + l];
        float pb = v * attr[h * 32 + l];
#pragma unroll
        for (int o = 16; o > 0; o >>= 1) {
            pa += __shfl_xor_sync(0xFFFFFFFFu, pa, o);
            pb += __shfl_xor_sync(0xFFFFFFFFu, pb, o);
        }
        alh[h] = pa; arh[h] = pb;  // all lanes hold full sums
    }
    if (l == 0) {
        *(float4*)&g_al[wid * 4] = make_float4(alh[0], alh[1], alh[2], alh[3]);
        *(float4*)&g_ar[wid * 4] = make_float4(arh[0], arh[1], arh[2], arh[3]);
    }
    if (l < HEADS) {
        // self-loop logit initializes the segment max (every node has one)
        g_menc[wid * 4 + l] = fenc(lrelu(alh[l] + arh[l]));
    }
}

// ---------------- edge pass A: segment max ----------------------------------
__global__ void edge_max(const int* __restrict__ src, const int* __restrict__ dst, int E) {
    int e = blockIdx.x * blockDim.x + threadIdx.x;
    if (e >= E) return;
    int s = src[e], d = dst[e];
    float4 a = *(const float4*)&g_al[s * 4];
    float4 b = *(const float4*)&g_ar[d * 4];
    unsigned* mp = &g_menc[d * 4];
    atomicMax(mp + 0, fenc(lrelu(a.x + b.x)));
    atomicMax(mp + 1, fenc(lrelu(a.y + b.y)));
    atomicMax(mp + 2, fenc(lrelu(a.z + b.z)));
    atomicMax(mp + 3, fenc(lrelu(a.w + b.w)));
}

// ---------------- z init with self-loop term --------------------------------
__global__ void z_init(int n) {
    int i = blockIdx.x * blockDim.x + threadIdx.x;
    if (i >= n) return;
    float4 a = *(const float4*)&g_al[i * 4];
    float4 b = *(const float4*)&g_ar[i * 4];
    float lg[4] = { lrelu(a.x + b.x), lrelu(a.y + b.y),
                    lrelu(a.z + b.z), lrelu(a.w + b.w) };
#pragma unroll
    for (int h = 0; h < HEADS; h++) {
        float m = fdec(g_menc[i * 4 + h]);
        g_z[i * 4 + h] = __expf(lg[h] - m);
    }
}

// ---------------- edge pass B: segment sum of exp ----------------------------
__global__ void edge_sum(const int* __restrict__ src, const int* __restrict__ dst, int E) {
    int e = blockIdx.x * blockDim.x + threadIdx.x;
    if (e >= E) return;
    int s = src[e], d = dst[e];
    float4 a = *(const float4*)&g_al[s * 4];
    float4 b = *(const float4*)&g_ar[d * 4];
    float lg[4] = { lrelu(a.x + b.x), lrelu(a.y + b.y),
                    lrelu(a.z + b.z), lrelu(a.w + b.w) };
#pragma unroll
    for (int h = 0; h < HEADS; h++) {
        float m = fdec(g_menc[d * 4 + h]);
        atomicAdd(&g_z[d * 4 + h], __expf(lg[h] - m));
    }
}

// ---------------- out init: self-loop message + bias ------------------------
__global__ void out_init(const float* __restrict__ bias, int n) {
    int wid = (blockIdx.x * blockDim.x + threadIdx.x) >> 5;
    int l = threadIdx.x & 31;
    if (wid >= n) return;
    int h = l >> 3;
    float als = g_al[wid * 4 + h], ard = g_ar[wid * 4 + h];
    float lg = lrelu(als + ard);
    float m  = fdec(g_menc[wid * 4 + h]);
    float z  = g_z[wid * 4 + h];
    float alpha = __expf(lg - m) / z;
    float4 xv = *(const float4*)&g_XW[wid * 128 + 4 * l];
    float4 bb = *(const float4*)&bias[4 * l];
    float4 o  = make_float4(xv.x * alpha + bb.x, xv.y * alpha + bb.y,
                            xv.z * alpha + bb.z, xv.w * alpha + bb.w);
    *(float4*)&g_H[wid * 128 + 4 * l] = o;
}

// ---------------- edge pass C: scatter messages (warp per edge) --------------
__global__ void edge_scatter(const int* __restrict__ src, const int* __restrict__ dst, int E) {
    int e = (blockIdx.x * blockDim.x + threadIdx.x) >> 5;
    int l = threadIdx.x & 31;
    if (e >= E) return;
    int s = src[e], d = dst[e];
    int h = l >> 3;
    float als = __ldg(&g_al[s * 4 + h]);
    float ard = __ldg(&g_ar[d * 4 + h]);
    float lg = lrelu(als + ard);
    float m  = fdec(__ldg(&g_menc[d * 4 + h]));
    float z  = __ldg(&g_z[d * 4 + h]);
    float alpha = __expf(lg - m) / z;
    float4 xv = *(const float4*)&g_XW[s * 128 + 4 * l];
    float4 v = make_float4(xv.x * alpha, xv.y * alpha, xv.z * alpha, xv.w * alpha);
    redAdd4(&g_H[d * 128 + 4 * l], v);
}

// ---------------- zero pool accumulators ------------------------------------
__global__ void zero_pool() {
    int i = blockIdx.x * blockDim.x + threadIdx.x;
    if (i < NG * DF) g_pool[i] = 0.f;
    if (i < NG) g_cnt[i] = 0;
}

// ---------------- pooling + write "last" output (relu fused) ----------------
__global__ void pool_copy(const int* __restrict__ batch, float* __restrict__ outLast, int n) {
    int wid = (blockIdx.x * blockDim.x + threadIdx.x) >> 5;
    int l = threadIdx.x & 31;
    if (wid >= n) return;
    float4 v = *(const float4*)&g_H[wid * 128 + 4 * l];
    v.x = fmaxf(v.x, 0.f); v.y = fmaxf(v.y, 0.f);
    v.z = fmaxf(v.z, 0.f); v.w = fmaxf(v.w, 0.f);
    *(float4*)&outLast[wid * 128 + 4 * l] = v;
    int b = batch[wid];
    redAdd4(&g_pool[b * 128 + 4 * l], v);
    if (l == 0) atomicAdd(&g_cnt[b], 1);
}

// ---------------- final MLP + log_softmax (block per graph) -----------------
__global__ void mlp_kernel(const float* __restrict__ lin1w, const float* __restrict__ lin1b,
                           const float* __restrict__ lin2w, const float* __restrict__ lin2b,
                           float* __restrict__ out) {
    __shared__ float pr[128];
    __shared__ float gg[128];
    __shared__ float lo[NCLS];
    int gr = blockIdx.x;
    int c = threadIdx.x;   // 128 threads
    float cnt = (float)max(g_cnt[gr], 1);
    pr[c] = g_pool[gr * 128 + c] / cnt;
    __syncthreads();
    float acc = lin1b[c];
#pragma unroll 8
    for (int k = 0; k < 128; k++) acc += pr[k] * lin1w[k * 128 + c];
    gg[c] = fmaxf(acc, 0.f);
    __syncthreads();
    if (c < NCLS) {
        float a = lin2b[c];
#pragma unroll 8
        for (int k = 0; k < 128; k++) a += gg[k] * lin2w[k * NCLS + c];
        lo[c] = a;
    }
    __syncthreads();
    if (c == 0) {
        float mx = lo[0];
#pragma unroll
        for (int j = 1; j < NCLS; j++) mx = fmaxf(mx, lo[j]);
        float s = 0.f;
#pragma unroll
        for (int j = 0; j < NCLS; j++) s += expf(lo[j] - mx);
        float lse = mx + logf(s);
#pragma unroll
        for (int j = 0; j < NCLS; j++) out[gr * NCLS + j] = lo[j] - lse;
    }
}

// ---------------- host launcher ---------------------------------------------
extern "C" void kernel_launch(void* const* d_in, const int* in_sizes, int n_in,
                              void* d_out, int out_size) {
    const float* x    = (const float*)d_in[0];
    const int*   eidx = (const int*)d_in[1];
    const int*   batch= (const int*)d_in[2];
    const float* W[3]  = { (const float*)d_in[3], (const float*)d_in[7],  (const float*)d_in[11] };
    const float* al[3] = { (const float*)d_in[4], (const float*)d_in[8],  (const float*)d_in[12] };
    const float* ar[3] = { (const float*)d_in[5], (const float*)d_in[9],  (const float*)d_in[13] };
    const float* bb[3] = { (const float*)d_in[6], (const float*)d_in[10], (const float*)d_in[14] };
    const float* lin1w = (const float*)d_in[15];
    const float* lin1b = (const float*)d_in[16];
    const float* lin2w = (const float*)d_in[17];
    const float* lin2b = (const float*)d_in[18];

    int n = in_sizes[0] / DF;          // 100000
    int E = in_sizes[1] / 2;           // 1600000
    const int* src = eidx;
    const int* dst = eidx + E;

    float* out_logits = (float*)d_out;                 // [64,10]
    float* out_last   = (float*)d_out + NG * NCLS;     // [N,128]

    float* xw; cudaGetSymbolAddress((void**)&xw, g_XW);
    float* hh; cudaGetSymbolAddress((void**)&hh, g_H);

    int gB = (n + 63) / 64;
    int warpNB = (n * 32 + 255) / 256;
    int edgeTB = (E + 255) / 256;
    int edgeWB = (E * 32 + 255) / 256;
    int nodeTB = (n + 255) / 256;

    for (int L = 0; L < 3; L++) {
        const float* A = (L == 0) ? x : hh;
        gemm_nk128<<<gB, 256>>>(A, W[L], xw, n, L > 0 ? 1 : 0);
        alar_kernel<<<warpNB, 256>>>(al[L], ar[L], n);
        edge_max<<<edgeTB, 256>>>(src, dst, E);
        z_init<<<nodeTB, 256>>>(n);
        edge_sum<<<edgeTB, 256>>>(src, dst, E);
        out_init<<<warpNB, 256>>>(bb[L], n);
        edge_scatter<<<edgeWB, 256>>>(src, dst, E);
    }

    zero_pool<<<(NG * DF + 255) / 256, 256>>>();
    pool_copy<<<warpNB, 256>>>(batch, out_last, n);
    mlp_kernel<<<NG, 128>>>(lin1w, lin1b, lin2w, lin2b, out_logits);
}

// round 2
// speedup vs baseline: 1.9472x; 1.9472x over previous
#include <cuda_runtime.h>
#include <cuda_bf16.h>
#include <math.h>

#define NND 100000
#define NE  1600000
#define DF  128
#define HEADS 4
#define NG  64
#define NCLS 10
#define NEG 0.2f
#define SCANB 512

// ---------------- scratch (device globals; no allocation allowed) -----------
__device__ __align__(16) float g_XW[NND * DF];   // x @ W for current layer
__device__ __align__(16) float g_H [NND * DF];   // layer output / next input
__device__ __align__(16) float g_al[NND * HEADS];
__device__ __align__(16) float g_ar[NND * HEADS];
__device__ int   g_deg[NND];
__device__ int   g_rowptr[NND + 1];
__device__ int   g_pos[NND];
__device__ int   g_bsum[(NND + SCANB - 1) / SCANB];
__device__ int   g_csr[NE];
__device__ float g_pool[NG * DF];
__device__ int   g_cnt[NG];

// ---------------- helpers ---------------------------------------------------
__device__ __forceinline__ float lrelu(float x) { return x > 0.f ? x : NEG * x; }

__device__ __forceinline__ void redAdd4(float* p, float4 v) {
    asm volatile("red.global.add.v4.f32 [%0], {%1,%2,%3,%4};"
                 :: "l"(p), "f"(v.x), "f"(v.y), "f"(v.z), "f"(v.w) : "memory");
}

// ---------------- CSR build --------------------------------------------------
__global__ void zero_deg(int n) {
    int i = blockIdx.x * blockDim.x + threadIdx.x;
    if (i < n) g_deg[i] = 0;
}
__global__ void count_deg(const int* __restrict__ dst, int E) {
    int e = blockIdx.x * blockDim.x + threadIdx.x;
    if (e < E) atomicAdd(&g_deg[dst[e]], 1);
}
__global__ void scanA(int n) {
    __shared__ int sh[SCANB];
    int i = blockIdx.x * SCANB + threadIdx.x;
    int v = (i < n) ? g_deg[i] : 0;
    sh[threadIdx.x] = v;
    __syncthreads();
    for (int off = 1; off < SCANB; off <<= 1) {
        int t = (threadIdx.x >= off) ? sh[threadIdx.x - off] : 0;
        __syncthreads();
        sh[threadIdx.x] += t;
        __syncthreads();
    }
    if (i < n) g_rowptr[i] = sh[threadIdx.x] - v;  // exclusive within block
    if (threadIdx.x == SCANB - 1) g_bsum[blockIdx.x] = sh[SCANB - 1];
}
__global__ void scanB(int nb) {
    __shared__ int sh[256];
    int v = (threadIdx.x < nb) ? g_bsum[threadIdx.x] : 0;
    sh[threadIdx.x] = v;
    __syncthreads();
    for (int off = 1; off < 256; off <<= 1) {
        int t = (threadIdx.x >= off) ? sh[threadIdx.x - off] : 0;
        __syncthreads();
        sh[threadIdx.x] += t;
        __syncthreads();
    }
    if (threadIdx.x < nb) g_bsum[threadIdx.x] = sh[threadIdx.x] - v;  // exclusive
}
__global__ void scanC(int n, int E) {
    int i = blockIdx.x * blockDim.x + threadIdx.x;
    if (i < n) {
        int r = g_rowptr[i] + g_bsum[i / SCANB];
        g_rowptr[i] = r;
        g_pos[i] = r;
    }
    if (i == 0) g_rowptr[n] = E;
}
__global__ void csr_fill(const int* __restrict__ src, const int* __restrict__ dst, int E) {
    int e = blockIdx.x * blockDim.x + threadIdx.x;
    if (e >= E) return;
    int p = atomicAdd(&g_pos[dst[e]], 1);
    g_csr[p] = src[e];
}

// ---------------- GEMM: C[n,128] = (relu?)(A[n,128]) @ W[128,128] ------------
__global__ void gemm_nk128(const float* __restrict__ A, const float* __restrict__ W,
                           float* __restrict__ C, int n, int reluIn) {
    __shared__ float Xs[64][33];
    __shared__ float Ws[32][128];
    int t    = threadIdx.x;          // 256 threads
    int row0 = blockIdx.x * 64;
    int cg   = t & 31;
    int rg   = t >> 5;
    float acc[8][4];
#pragma unroll
    for (int r = 0; r < 8; r++) { acc[r][0]=acc[r][1]=acc[r][2]=acc[r][3]=0.f; }

    for (int k0 = 0; k0 < 128; k0 += 32) {
#pragma unroll
        for (int j = 0; j < 8; j++) {
            int idx = t + j * 256;
            int r = idx >> 5, c = idx & 31;
            int row = row0 + r;
            float v = (row < n) ? A[row * 128 + k0 + c] : 0.f;
            if (reluIn) v = fmaxf(v, 0.f);
            Xs[r][c] = v;
        }
#pragma unroll
        for (int j = 0; j < 16; j++) {
            int idx = t + j * 256;
            int r = idx >> 7, c = idx & 127;
            Ws[r][c] = W[(k0 + r) * 128 + c];
        }
        __syncthreads();
#pragma unroll
        for (int kk = 0; kk < 32; kk++) {
            float4 w = *(float4*)&Ws[kk][cg * 4];
#pragma unroll
            for (int r = 0; r < 8; r++) {
                float xv = Xs[rg * 8 + r][kk];
                acc[r][0] += xv * w.x; acc[r][1] += xv * w.y;
                acc[r][2] += xv * w.z; acc[r][3] += xv * w.w;
            }
        }
        __syncthreads();
    }
#pragma unroll
    for (int r = 0; r < 8; r++) {
        int row = row0 + rg * 8 + r;
        if (row < n)
            *(float4*)&C[row * 128 + cg * 4] =
                make_float4(acc[r][0], acc[r][1], acc[r][2], acc[r][3]);
    }
}

// ---------------- al/ar per node ---------------------------------------------
__global__ void alar_kernel(const float* __restrict__ attl,
                            const float* __restrict__ attr, int n) {
    int wid = (blockIdx.x * blockDim.x + threadIdx.x) >> 5;
    int l = threadIdx.x & 31;
    if (wid >= n) return;
    float alh[HEADS], arh[HEADS];
#pragma unroll
    for (int h = 0; h < HEADS; h++) {
        float v  = g_XW[wid * 128 + h * 32 + l];
        float pa = v * attl[h * 32 + l];
        float pb = v * attr[h * 32 + l];
#pragma unroll
        for (int o = 16; o > 0; o >>= 1) {
            pa += __shfl_xor_sync(0xFFFFFFFFu, pa, o);
            pb += __shfl_xor_sync(0xFFFFFFFFu, pb, o);
        }
        alh[h] = pa; arh[h] = pb;
    }
    if (l == 0) {
        *(float4*)&g_al[wid * 4] = make_float4(alh[0], alh[1], alh[2], alh[3]);
        *(float4*)&g_ar[wid * 4] = make_float4(arh[0], arh[1], arh[2], arh[3]);
    }
}

// ---------------- fused per-node GAT aggregation (warp per node) -------------
// Computes segment-softmax over in-edges + self loop, aggregates messages,
// adds bias; writes g_H[node]. Zero atomics.
__global__ void gat_node(const float* __restrict__ bias, int n) {
    int wid = (blockIdx.x * blockDim.x + threadIdx.x) >> 5;
    int l = threadIdx.x & 31;
    if (wid >= n) return;
    int rp = g_rowptr[wid], re = g_rowptr[wid + 1];

    float4 ad = *(const float4*)&g_al[wid * 4];   // al[d] (self src)
    float4 bd = *(const float4*)&g_ar[wid * 4];   // ar[d]
    float slg0 = lrelu(ad.x + bd.x), slg1 = lrelu(ad.y + bd.y);
    float slg2 = lrelu(ad.z + bd.z), slg3 = lrelu(ad.w + bd.w);

    // --- pass 1: per-head max over {self} ∪ in-edges, lanes parallel over edges
    float m0 = slg0, m1 = slg1, m2 = slg2, m3 = slg3;
    for (int j = rp + l; j < re; j += 32) {
        int s = g_csr[j];
        float4 a = *(const float4*)&g_al[s * 4];
        m0 = fmaxf(m0, lrelu(a.x + bd.x));
        m1 = fmaxf(m1, lrelu(a.y + bd.y));
        m2 = fmaxf(m2, lrelu(a.z + bd.z));
        m3 = fmaxf(m3, lrelu(a.w + bd.w));
    }
#pragma unroll
    for (int o = 16; o > 0; o >>= 1) {
        m0 = fmaxf(m0, __shfl_xor_sync(0xFFFFFFFFu, m0, o));
        m1 = fmaxf(m1, __shfl_xor_sync(0xFFFFFFFFu, m1, o));
        m2 = fmaxf(m2, __shfl_xor_sync(0xFFFFFFFFu, m2, o));
        m3 = fmaxf(m3, __shfl_xor_sync(0xFFFFFFFFu, m3, o));
    }

    // --- pass 2: z = sum exp(lg - m)
    float z0 = (l == 0) ? __expf(slg0 - m0) : 0.f;
    float z1 = (l == 0) ? __expf(slg1 - m1) : 0.f;
    float z2 = (l == 0) ? __expf(slg2 - m2) : 0.f;
    float z3 = (l == 0) ? __expf(slg3 - m3) : 0.f;
    for (int j = rp + l; j < re; j += 32) {
        int s = g_csr[j];
        float4 a = *(const float4*)&g_al[s * 4];
        z0 += __expf(lrelu(a.x + bd.x) - m0);
        z1 += __expf(lrelu(a.y + bd.y) - m1);
        z2 += __expf(lrelu(a.z + bd.z) - m2);
        z3 += __expf(lrelu(a.w + bd.w) - m3);
    }
#pragma unroll
    for (int o = 16; o > 0; o >>= 1) {
        z0 += __shfl_xor_sync(0xFFFFFFFFu, z0, o);
        z1 += __shfl_xor_sync(0xFFFFFFFFu, z1, o);
        z2 += __shfl_xor_sync(0xFFFFFFFFu, z2, o);
        z3 += __shfl_xor_sync(0xFFFFFFFFu, z3, o);
    }

    // --- pass 3: aggregate messages; lanes cooperate over 128 dims
    int h = l >> 3;
    float mh   = (h == 0) ? m0 : (h == 1) ? m1 : (h == 2) ? m2 : m3;
    float zh   = (h == 0) ? z0 : (h == 1) ? z1 : (h == 2) ? z2 : z3;
    float bdh  = (h == 0) ? bd.x : (h == 1) ? bd.y : (h == 2) ? bd.z : bd.w;
    float slgh = (h == 0) ? slg0 : (h == 1) ? slg1 : (h == 2) ? slg2 : slg3;
    float rzh = 1.f / zh;

    float aself = __expf(slgh - mh) * rzh;
    float4 xv = *(const float4*)&g_XW[wid * 128 + 4 * l];
    float4 acc = make_float4(xv.x * aself, xv.y * aself, xv.z * aself, xv.w * aself);

    for (int j0 = rp; j0 < re; j0 += 32) {
        int myS = (j0 + l < re) ? g_csr[j0 + l] : 0;
        int cnt = min(32, re - j0);
        for (int k = 0; k < cnt; k++) {
            int s = __shfl_sync(0xFFFFFFFFu, myS, k);
            float als = g_al[s * 4 + h];
            float alpha = __expf(lrelu(als + bdh) - mh) * rzh;
            float4 x2 = *(const float4*)&g_XW[s * 128 + 4 * l];
            acc.x += x2.x * alpha; acc.y += x2.y * alpha;
            acc.z += x2.z * alpha; acc.w += x2.w * alpha;
        }
    }
    float4 bv = *(const float4*)&bias[4 * l];
    acc.x += bv.x; acc.y += bv.y; acc.z += bv.z; acc.w += bv.w;
    *(float4*)&g_H[wid * 128 + 4 * l] = acc;
}

// ---------------- zero pool accumulators ------------------------------------
__global__ void zero_pool() {
    int i = blockIdx.x * blockDim.x + threadIdx.x;
    if (i < NG * DF) g_pool[i] = 0.f;
    if (i < NG) g_cnt[i] = 0;
}

// ---------------- pooling + write "last" output (relu fused) ----------------
__global__ void pool_copy(const int* __restrict__ batch, float* __restrict__ outLast, int n) {
    int wid = (blockIdx.x * blockDim.x + threadIdx.x) >> 5;
    int l = threadIdx.x & 31;
    if (wid >= n) return;
    float4 v = *(const float4*)&g_H[wid * 128 + 4 * l];
    v.x = fmaxf(v.x, 0.f); v.y = fmaxf(v.y, 0.f);
    v.z = fmaxf(v.z, 0.f); v.w = fmaxf(v.w, 0.f);
    *(float4*)&outLast[wid * 128 + 4 * l] = v;
    int b = batch[wid];
    redAdd4(&g_pool[b * 128 + 4 * l], v);
    if (l == 0) atomicAdd(&g_cnt[b], 1);
}

// ---------------- final MLP + log_softmax (block per graph) -----------------
__global__ void mlp_kernel(const float* __restrict__ lin1w, const float* __restrict__ lin1b,
                           const float* __restrict__ lin2w, const float* __restrict__ lin2b,
                           float* __restrict__ out) {
    __shared__ float pr[128];
    __shared__ float gg[128];
    __shared__ float lo[NCLS];
    int gr = blockIdx.x;
    int c = threadIdx.x;   // 128 threads
    float cnt = (float)max(g_cnt[gr], 1);
    pr[c] = g_pool[gr * 128 + c] / cnt;
    __syncthreads();
    float acc = lin1b[c];
#pragma unroll 8
    for (int k = 0; k < 128; k++) acc += pr[k] * lin1w[k * 128 + c];
    gg[c] = fmaxf(acc, 0.f);
    __syncthreads();
    if (c < NCLS) {
        float a = lin2b[c];
#pragma unroll 8
        for (int k = 0; k < 128; k++) a += gg[k] * lin2w[k * NCLS + c];
        lo[c] = a;
    }
    __syncthreads();
    if (c == 0) {
        float mx = lo[0];
#pragma unroll
        for (int j = 1; j < NCLS; j++) mx = fmaxf(mx, lo[j]);
        float s = 0.f;
#pragma unroll
        for (int j = 0; j < NCLS; j++) s += expf(lo[j] - mx);
        float lse = mx + logf(s);
#pragma unroll
        for (int j = 0; j < NCLS; j++) out[gr * NCLS + j] = lo[j] - lse;
    }
}

// ---------------- host launcher ---------------------------------------------
extern "C" void kernel_launch(void* const* d_in, const int* in_sizes, int n_in,
                              void* d_out, int out_size) {
    const float* x    = (const float*)d_in[0];
    const int*   eidx = (const int*)d_in[1];
    const int*   batch= (const int*)d_in[2];
    const float* W[3]  = { (const float*)d_in[3], (const float*)d_in[7],  (const float*)d_in[11] };
    const float* al[3] = { (const float*)d_in[4], (const float*)d_in[8],  (const float*)d_in[12] };
    const float* ar[3] = { (const float*)d_in[5], (const float*)d_in[9],  (const float*)d_in[13] };
    const float* bb[3] = { (const float*)d_in[6], (const float*)d_in[10], (const float*)d_in[14] };
    const float* lin1w = (const float*)d_in[15];
    const float* lin1b = (const float*)d_in[16];
    const float* lin2w = (const float*)d_in[17];
    const float* lin2b = (const float*)d_in[18];

    int n = in_sizes[0] / DF;          // 100000
    int E = in_sizes[1] / 2;           // 1600000
    const int* src = eidx;
    const int* dst = eidx + E;

    float* out_logits = (float*)d_out;                 // [64,10]
    float* out_last   = (float*)d_out + NG * NCLS;     // [N,128]

    float* xw; cudaGetSymbolAddress((void**)&xw, g_XW);
    float* hh; cudaGetSymbolAddress((void**)&hh, g_H);

    int gB     = (n + 63) / 64;
    int warpNB = (n * 32 + 255) / 256;
    int edgeTB = (E + 255) / 256;
    int nodeTB = (n + 255) / 256;
    int nScanB = (n + SCANB - 1) / SCANB;

    // ---- CSR build (once per launch) ----
    zero_deg<<<nodeTB, 256>>>(n);
    count_deg<<<edgeTB, 256>>>(dst, E);
    scanA<<<nScanB, SCANB>>>(n);
    scanB<<<1, 256>>>(nScanB);
    scanC<<<nodeTB, 256>>>(n, E);
    csr_fill<<<edgeTB, 256>>>(src, dst, E);

    // ---- 3 GAT layers ----
    for (int L = 0; L < 3; L++) {
        const float* A = (L == 0) ? x : hh;
        gemm_nk128<<<gB, 256>>>(A, W[L], xw, n, L > 0 ? 1 : 0);
        alar_kernel<<<warpNB, 256>>>(al[L], ar[L], n);
        gat_node<<<warpNB, 256>>>(bb[L], n);
    }

    // ---- pooling + MLP head ----
    zero_pool<<<(NG * DF + 255) / 256, 256>>>();
    pool_copy<<<warpNB, 256>>>(batch, out_last, n);
    mlp_kernel<<<NG, 128>>>(lin1w, lin1b, lin2w, lin2b, out_logits);
}

// round 4
// speedup vs baseline: 2.0583x; 1.0570x over previous
#include <cuda_runtime.h>
#include <cuda_bf16.h>
#include <cstdint>
#include <math.h>

#define NND 100000
#define NE  1600000
#define DF  128
#define HEADS 4
#define NG  64
#define NCLS 10
#define NEG 0.2f
#define SCANB 512

// ---------------- scratch (device globals; no allocation allowed) -----------
__device__ __align__(16) float g_XW[NND * DF];
__device__ __align__(16) float g_H [NND * DF];
__device__ __align__(16) float g_al[NND * HEADS];
__device__ __align__(16) float g_ar[NND * HEADS];
__device__ int   g_deg[NND];
__device__ int   g_rowptr[NND + 1];
__device__ int   g_pos[NND];
__device__ int   g_bsum[(NND + SCANB - 1) / SCANB];
__device__ int   g_csr[NE];
__device__ float g_pool[NG * DF];
__device__ int   g_cnt[NG];
// pre-swizzled bf16 W^T planes (hi/lo), 3 layers, 128x128 bf16 = 32KB each
__device__ __align__(16) uint4 g_WhT[3][2048];
__device__ __align__(16) uint4 g_WlT[3][2048];

// ---------------- helpers ---------------------------------------------------
__device__ __forceinline__ float lrelu(float x) { return x > 0.f ? x : NEG * x; }
__device__ __forceinline__ void redAdd4(float* p, float4 v) {
    asm volatile("red.global.add.v4.f32 [%0], {%1,%2,%3,%4};"
                 :: "l"(p), "f"(v.x), "f"(v.y), "f"(v.z), "f"(v.w) : "memory");
}
__device__ __forceinline__ uint32_t smem_u32(const void* p) {
    uint32_t a;
    asm("{ .reg .u64 t; cvta.to.shared.u64 t, %1; cvt.u32.u64 %0, t; }" : "=r"(a) : "l"(p));
    return a;
}
__device__ __forceinline__ void ldm4(uint32_t& r0, uint32_t& r1, uint32_t& r2,
                                     uint32_t& r3, uint32_t addr) {
    asm volatile("ldmatrix.sync.aligned.m8n8.x4.shared.b16 {%0,%1,%2,%3}, [%4];"
                 : "=r"(r0), "=r"(r1), "=r"(r2), "=r"(r3) : "r"(addr));
}
__device__ __forceinline__ void mma16816(float* d, uint32_t a0, uint32_t a1,
                                         uint32_t a2, uint32_t a3,
                                         uint32_t b0, uint32_t b1) {
    asm volatile(
        "mma.sync.aligned.m16n8k16.row.col.f32.bf16.bf16.f32 "
        "{%0,%1,%2,%3}, {%4,%5,%6,%7}, {%8,%9}, {%0,%1,%2,%3};"
        : "+f"(d[0]), "+f"(d[1]), "+f"(d[2]), "+f"(d[3])
        : "r"(a0), "r"(a1), "r"(a2), "r"(a3), "r"(b0), "r"(b1));
}

union B16x8 { __nv_bfloat16 b[8]; uint4 u; };

// ---------------- weight prep: W[k][n] fp32 -> swizzled bf16 W^T planes ------
__global__ void prep_w(const float* __restrict__ W, uint4* __restrict__ hi,
                       uint4* __restrict__ lo) {
    int i = blockIdx.x * blockDim.x + threadIdx.x;
    if (i >= 2048) return;
    int nn = i >> 4, c = i & 15;          // row n, 16-byte k-chunk c
    B16x8 H, L;
#pragma unroll
    for (int j = 0; j < 8; j++) {
        float wv = W[(c * 8 + j) * 128 + nn];
        __nv_bfloat16 h = __float2bfloat16(wv);
        H.b[j] = h;
        L.b[j] = __float2bfloat16(wv - __bfloat162float(h));
    }
    int off = nn * 16 + (c ^ (nn & 7));   // uint4 units, XOR swizzle
    hi[off] = H.u;
    lo[off] = L.u;
}

// ---------------- HMMA GEMM + fused al/ar epilogue ---------------------------
// C[row,0:128] = (relu?)A @ W via bf16 split; also g_al/g_ar dots.
#define GS_AH 0
#define GS_AL 16384
#define GS_WH 32768
#define GS_WL 65536
#define GS_TOT 98304

__global__ void __launch_bounds__(128, 2) gemm_mma(
    const float* __restrict__ A, const uint4* __restrict__ WhT,
    const uint4* __restrict__ WlT, float* __restrict__ C,
    const float* __restrict__ attl, const float* __restrict__ attr,
    int n, int reluIn) {
    extern __shared__ char smem[];
    uint32_t sb = smem_u32(smem);
    int tid = threadIdx.x, w = tid >> 5, l = tid & 31;
    int row0 = blockIdx.x * 64;

    // copy pre-swizzled W planes
    {
        uint4* wh = (uint4*)(smem + GS_WH);
        uint4* wl = (uint4*)(smem + GS_WL);
        for (int i = tid; i < 2048; i += 128) { wh[i] = WhT[i]; wl[i] = WlT[i]; }
    }
    // convert A tile (64x128 fp32) to bf16 hi/lo, swizzled
    for (int i = tid; i < 1024; i += 128) {
        int r = i >> 4, c = i & 15;
        int row = row0 + r;
        float4 v0 = make_float4(0.f, 0.f, 0.f, 0.f), v1 = v0;
        if (row < n) {
            v0 = *(const float4*)&A[row * 128 + c * 8];
            v1 = *(const float4*)&A[row * 128 + c * 8 + 4];
        }
        if (reluIn) {
            v0.x = fmaxf(v0.x, 0.f); v0.y = fmaxf(v0.y, 0.f);
            v0.z = fmaxf(v0.z, 0.f); v0.w = fmaxf(v0.w, 0.f);
            v1.x = fmaxf(v1.x, 0.f); v1.y = fmaxf(v1.y, 0.f);
            v1.z = fmaxf(v1.z, 0.f); v1.w = fmaxf(v1.w, 0.f);
        }
        B16x8 H, L;
        float vv[8] = { v0.x, v0.y, v0.z, v0.w, v1.x, v1.y, v1.z, v1.w };
#pragma unroll
        for (int j = 0; j < 8; j++) {
            __nv_bfloat16 h = __float2bfloat16(vv[j]);
            H.b[j] = h;
            L.b[j] = __float2bfloat16(vv[j] - __bfloat162float(h));
        }
        int off = r * 256 + ((c ^ (r & 7)) << 4);
        *(uint4*)(smem + GS_AH + off) = H.u;
        *(uint4*)(smem + GS_AL + off) = L.u;
    }
    __syncthreads();

    // per-lane ldmatrix address components
    int aRow = (w << 4) + ((l >> 3) & 1) * 8 + (l & 7);
    int aChk = (l >> 4) & 1;
    uint32_t aBase = sb + GS_AH + aRow * 256;
    int aXor = aRow & 7;
    int bRowL = ((l >> 4) & 1) * 8 + (l & 7);
    int bChk = (l >> 3) & 1;

    float acc[64];
#pragma unroll
    for (int i = 0; i < 64; i++) acc[i] = 0.f;

#pragma unroll
    for (int ks = 0; ks < 8; ks++) {
        uint32_t ah0, ah1, ah2, ah3, al0, al1, al2, al3;
        uint32_t aOff = (((2 * ks + aChk) ^ aXor) << 4);
        ldm4(ah0, ah1, ah2, ah3, aBase + aOff);
        ldm4(al0, al1, al2, al3, aBase + 16384 + aOff);
#pragma unroll
        for (int p = 0; p < 8; p++) {
            int bRow = p * 16 + bRowL;
            uint32_t bAddr = sb + GS_WH + bRow * 256
                           + (((2 * ks + bChk) ^ (bRow & 7)) << 4);
            uint32_t bh0, bh1, bh2, bh3, bl0, bl1, bl2, bl3;
            ldm4(bh0, bh1, bh2, bh3, bAddr);
            ldm4(bl0, bl1, bl2, bl3, bAddr + 32768);
            float* d0 = &acc[(2 * p) * 4];
            float* d1 = &acc[(2 * p + 1) * 4];
            mma16816(d0, ah0, ah1, ah2, ah3, bh0, bh1);
            mma16816(d0, al0, al1, al2, al3, bh0, bh1);
            mma16816(d0, ah0, ah1, ah2, ah3, bl0, bl1);
            mma16816(d1, ah0, ah1, ah2, ah3, bh2, bh3);
            mma16816(d1, al0, al1, al2, al3, bh2, bh3);
            mma16816(d1, ah0, ah1, ah2, ah3, bl2, bl3);
        }
    }
    __syncthreads();

    // stage acc -> smem (stride 132), load att vectors into freed WL region
    float* Cs = (float*)smem;
    float* att = (float*)(smem + GS_WL);
    att[tid] = attl[tid];
    att[128 + tid] = attr[tid];
    {
        int r1 = w * 16 + (l >> 2);
#pragma unroll
        for (int nt = 0; nt < 16; nt++) {
            int col = nt * 8 + (l & 3) * 2;
            Cs[r1 * 132 + col]           = acc[nt * 4 + 0];
            Cs[r1 * 132 + col + 1]       = acc[nt * 4 + 1];
            Cs[(r1 + 8) * 132 + col]     = acc[nt * 4 + 2];
            Cs[(r1 + 8) * 132 + col + 1] = acc[nt * 4 + 3];
        }
    }
    __syncthreads();

    // write C (coalesced)
    for (int i = tid; i < 64 * 32; i += 128) {
        int r = i >> 5, c4 = i & 31;
        int row = row0 + r;
        if (row < n)
            *(float4*)&C[row * 128 + c4 * 4] = *(float4*)&Cs[r * 132 + c4 * 4];
    }
    // fused al / ar dots
    {
        int half = tid >> 6;          // 0: al, 1: ar
        int r = tid & 63;
        int row = row0 + r;
        if (row < n) {
            const float* av = att + half * 128;
            float d0 = 0.f, d1 = 0.f, d2 = 0.f, d3 = 0.f;
#pragma unroll 8
            for (int c = 0; c < 32; c++) {
                d0 += Cs[r * 132 + c]      * av[c];
                d1 += Cs[r * 132 + 32 + c] * av[32 + c];
                d2 += Cs[r * 132 + 64 + c] * av[64 + c];
                d3 += Cs[r * 132 + 96 + c] * av[96 + c];
            }
            float* dst = half ? g_ar : g_al;
            *(float4*)&dst[row * 4] = make_float4(d0, d1, d2, d3);
        }
    }
}

// ---------------- CSR build --------------------------------------------------
__global__ void zero_deg(int n) {
    int i = blockIdx.x * blockDim.x + threadIdx.x;
    if (i < n) g_deg[i] = 0;
}
__global__ void count_deg(const int* __restrict__ dst, int E) {
    int e = blockIdx.x * blockDim.x + threadIdx.x;
    if (e < E) atomicAdd(&g_deg[dst[e]], 1);
}
__global__ void scanA(int n) {
    __shared__ int sh[SCANB];
    int i = blockIdx.x * SCANB + threadIdx.x;
    int v = (i < n) ? g_deg[i] : 0;
    sh[threadIdx.x] = v;
    __syncthreads();
    for (int off = 1; off < SCANB; off <<= 1) {
        int t = (threadIdx.x >= off) ? sh[threadIdx.x - off] : 0;
        __syncthreads();
        sh[threadIdx.x] += t;
        __syncthreads();
    }
    if (i < n) g_rowptr[i] = sh[threadIdx.x] - v;
    if (threadIdx.x == SCANB - 1) g_bsum[blockIdx.x] = sh[SCANB - 1];
}
__global__ void scanB(int nb) {
    __shared__ int sh[256];
    int v = (threadIdx.x < nb) ? g_bsum[threadIdx.x] : 0;
    sh[threadIdx.x] = v;
    __syncthreads();
    for (int off = 1; off < 256; off <<= 1) {
        int t = (threadIdx.x >= off) ? sh[threadIdx.x - off] : 0;
        __syncthreads();
        sh[threadIdx.x] += t;
        __syncthreads();
    }
    if (threadIdx.x < nb) g_bsum[threadIdx.x] = sh[threadIdx.x] - v;
}
__global__ void scanC(int n, int E) {
    int i = blockIdx.x * blockDim.x + threadIdx.x;
    if (i < n) {
        int r = g_rowptr[i] + g_bsum[i / SCANB];
        g_rowptr[i] = r;
        g_pos[i] = r;
    }
    if (i == 0) g_rowptr[n] = E;
}
__global__ void csr_fill(const int* __restrict__ src, const int* __restrict__ dst, int E) {
    int e = blockIdx.x * blockDim.x + threadIdx.x;
    if (e >= E) return;
    int p = atomicAdd(&g_pos[dst[e]], 1);
    g_csr[p] = src[e];
}

// ---------------- fused per-node GAT (warp per node, 2 edge passes) ----------
__global__ void gat_node(const float* __restrict__ bias, int n) {
    int wid = (blockIdx.x * blockDim.x + threadIdx.x) >> 5;
    int l = threadIdx.x & 31;
    if (wid >= n) return;
    int rp = g_rowptr[wid], re = g_rowptr[wid + 1];

    float4 ad = *(const float4*)&g_al[wid * 4];
    float4 bd = *(const float4*)&g_ar[wid * 4];
    float slg0 = lrelu(ad.x + bd.x), slg1 = lrelu(ad.y + bd.y);
    float slg2 = lrelu(ad.z + bd.z), slg3 = lrelu(ad.w + bd.w);

    // pass 1: per-head max (no exp)
    float m0 = slg0, m1 = slg1, m2 = slg2, m3 = slg3;
    for (int j = rp + l; j < re; j += 32) {
        int s = g_csr[j];
        float4 a = *(const float4*)&g_al[s * 4];
        m0 = fmaxf(m0, lrelu(a.x + bd.x));
        m1 = fmaxf(m1, lrelu(a.y + bd.y));
        m2 = fmaxf(m2, lrelu(a.z + bd.z));
        m3 = fmaxf(m3, lrelu(a.w + bd.w));
    }
#pragma unroll
    for (int o = 16; o > 0; o >>= 1) {
        m0 = fmaxf(m0, __shfl_xor_sync(0xFFFFFFFFu, m0, o));
        m1 = fmaxf(m1, __shfl_xor_sync(0xFFFFFFFFu, m1, o));
        m2 = fmaxf(m2, __shfl_xor_sync(0xFFFFFFFFu, m2, o));
        m3 = fmaxf(m3, __shfl_xor_sync(0xFFFFFFFFu, m3, o));
    }

    int h = l >> 3;
    int eo = l & 7;
    float mh   = (h == 0) ? m0 : (h == 1) ? m1 : (h == 2) ? m2 : m3;
    float arh  = (h == 0) ? bd.x : (h == 1) ? bd.y : (h == 2) ? bd.z : bd.w;
    float slgh = (h == 0) ? slg0 : (h == 1) ? slg1 : (h == 2) ? slg2 : slg3;

    // pass 2: unnormalized aggregation + z, 8 edges x 4 heads per iteration
    float zacc = 0.f;
    float4 acc = make_float4(0.f, 0.f, 0.f, 0.f);
    for (int j0 = rp; j0 < re; j0 += 8) {
        int cnt = re - j0;
        int s_l = wid;
        float e_l = 0.f;
        if (eo < cnt) {
            s_l = g_csr[j0 + eo];
            float als = __ldg(&g_al[s_l * 4 + h]);
            e_l = __expf(lrelu(als + arh) - mh);
            zacc += e_l;
        }
        if (cnt >= 8) {
#pragma unroll
            for (int k = 0; k < 8; k++) {
                int s = __shfl_sync(0xFFFFFFFFu, s_l, k);
                float ek = __shfl_sync(0xFFFFFFFFu, e_l, (l & 24) | k);
                float4 x = *(const float4*)&g_XW[s * 128 + 4 * l];
                acc.x += ek * x.x; acc.y += ek * x.y;
                acc.z += ek * x.z; acc.w += ek * x.w;
            }
        } else {
            for (int k = 0; k < cnt; k++) {
                int s = __shfl_sync(0xFFFFFFFFu, s_l, k);
                float ek = __shfl_sync(0xFFFFFFFFu, e_l, (l & 24) | k);
                float4 x = *(const float4*)&g_XW[s * 128 + 4 * l];
                acc.x += ek * x.x; acc.y += ek * x.y;
                acc.z += ek * x.z; acc.w += ek * x.w;
            }
        }
    }
    // reduce z within same-head lane groups
#pragma unroll
    for (int o = 1; o < 8; o <<= 1) zacc += __shfl_xor_sync(0xFFFFFFFFu, zacc, o);

    float eself = __expf(slgh - mh);
    float rz = 1.f / (zacc + eself);
    float4 xs = *(const float4*)&g_XW[wid * 128 + 4 * l];
    acc.x = (acc.x + eself * xs.x) * rz;
    acc.y = (acc.y + eself * xs.y) * rz;
    acc.z = (acc.z + eself * xs.z) * rz;
    acc.w = (acc.w + eself * xs.w) * rz;
    float4 bv = *(const float4*)&bias[4 * l];
    acc.x += bv.x; acc.y += bv.y; acc.z += bv.z; acc.w += bv.w;
    *(float4*)&g_H[wid * 128 + 4 * l] = acc;
}

// ---------------- zero pool accumulators ------------------------------------
__global__ void zero_pool() {
    int i = blockIdx.x * blockDim.x + threadIdx.x;
    if (i < NG * DF) g_pool[i] = 0.f;
    if (i < NG) g_cnt[i] = 0;
}

// ---------------- pooling + write "last" output (relu fused) ----------------
__global__ void pool_copy(const int* __restrict__ batch, float* __restrict__ outLast, int n) {
    int wid = (blockIdx.x * blockDim.x + threadIdx.x) >> 5;
    int l = threadIdx.x & 31;
    if (wid >= n) return;
    float4 v = *(const float4*)&g_H[wid * 128 + 4 * l];
    v.x = fmaxf(v.x, 0.f); v.y = fmaxf(v.y, 0.f);
    v.z = fmaxf(v.z, 0.f); v.w = fmaxf(v.w, 0.f);
    *(float4*)&outLast[wid * 128 + 4 * l] = v;
    int b = batch[wid];
    redAdd4(&g_pool[b * 128 + 4 * l], v);
    if (l == 0) atomicAdd(&g_cnt[b], 1);
}

// ---------------- final MLP + log_softmax (block per graph) -----------------
__global__ void mlp_kernel(const float* __restrict__ lin1w, const float* __restrict__ lin1b,
                           const float* __restrict__ lin2w, const float* __restrict__ lin2b,
                           float* __restrict__ out) {
    __shared__ float pr[128];
    __shared__ float gg[128];
    __shared__ float lo[NCLS];
    int gr = blockIdx.x;
    int c = threadIdx.x;
    float cnt = (float)max(g_cnt[gr], 1);
    pr[c] = g_pool[gr * 128 + c] / cnt;
    __syncthreads();
    float acc = lin1b[c];
#pragma unroll 8
    for (int k = 0; k < 128; k++) acc += pr[k] * lin1w[k * 128 + c];
    gg[c] = fmaxf(acc, 0.f);
    __syncthreads();
    if (c < NCLS) {
        float a = lin2b[c];
#pragma unroll 8
        for (int k = 0; k < 128; k++) a += gg[k] * lin2w[k * NCLS + c];
        lo[c] = a;
    }
    __syncthreads();
    if (c == 0) {
        float mx = lo[0];
#pragma unroll
        for (int j = 1; j < NCLS; j++) mx = fmaxf(mx, lo[j]);
        float s = 0.f;
#pragma unroll
        for (int j = 0; j < NCLS; j++) s += expf(lo[j] - mx);
        float lse = mx + logf(s);
#pragma unroll
        for (int j = 0; j < NCLS; j++) out[gr * NCLS + j] = lo[j] - lse;
    }
}

// ---------------- host launcher ---------------------------------------------
extern "C" void kernel_launch(void* const* d_in, const int* in_sizes, int n_in,
                              void* d_out, int out_size) {
    const float* x    = (const float*)d_in[0];
    const int*   eidx = (const int*)d_in[1];
    const int*   batch= (const int*)d_in[2];
    const float* W[3]  = { (const float*)d_in[3], (const float*)d_in[7],  (const float*)d_in[11] };
    const float* al[3] = { (const float*)d_in[4], (const float*)d_in[8],  (const float*)d_in[12] };
    const float* ar[3] = { (const float*)d_in[5], (const float*)d_in[9],  (const float*)d_in[13] };
    const float* bb[3] = { (const float*)d_in[6], (const float*)d_in[10], (const float*)d_in[14] };
    const float* lin1w = (const float*)d_in[15];
    const float* lin1b = (const float*)d_in[16];
    const float* lin2w = (const float*)d_in[17];
    const float* lin2b = (const float*)d_in[18];

    int n = in_sizes[0] / DF;
    int E = in_sizes[1] / 2;
    const int* src = eidx;
    const int* dst = eidx + E;

    float* out_logits = (float*)d_out;
    float* out_last   = (float*)d_out + NG * NCLS;

    float* xw; cudaGetSymbolAddress((void**)&xw, g_XW);
    float* hh; cudaGetSymbolAddress((void**)&hh, g_H);
    uint4* wh; cudaGetSymbolAddress((void**)&wh, g_WhT);
    uint4* wl; cudaGetSymbolAddress((void**)&wl, g_WlT);

    static int smemSet = 0;
    if (!smemSet) {
        cudaFuncSetAttribute(gemm_mma, cudaFuncAttributeMaxDynamicSharedMemorySize, GS_TOT);
        smemSet = 1;
    }

    int warpNB = (n * 32 + 255) / 256;
    int edgeTB = (E + 255) / 256;
    int nodeTB = (n + 255) / 256;
    int nScanB = (n + SCANB - 1) / SCANB;
    int gemmB  = (n + 63) / 64;

    // ---- weight prep ----
    for (int L = 0; L < 3; L++)
        prep_w<<<8, 256>>>(W[L], wh + L * 2048, wl + L * 2048);

    // ---- CSR build ----
    zero_deg<<<nodeTB, 256>>>(n);
    count_deg<<<edgeTB, 256>>>(dst, E);
    scanA<<<nScanB, SCANB>>>(n);
    scanB<<<1, 256>>>(nScanB);
    scanC<<<nodeTB, 256>>>(n, E);
    csr_fill<<<edgeTB, 256>>>(src, dst, E);

    // ---- 3 GAT layers ----
    for (int L = 0; L < 3; L++) {
        const float* A = (L == 0) ? x : hh;
        gemm_mma<<<gemmB, 128, GS_TOT>>>(A, wh + L * 2048, wl + L * 2048,
                                         xw, al[L], ar[L], n, L > 0 ? 1 : 0);
        gat_node<<<warpNB, 256>>>(bb[L], n);
    }

    // ---- pooling + MLP head ----
    zero_pool<<<(NG * DF + 255) / 256, 256>>>();
    pool_copy<<<warpNB, 256>>>(batch, out_last, n);
    mlp_kernel<<<NG, 128>>>(lin1w, lin1b, lin2w, lin2b, out_logits);
}

// round 5
// speedup vs baseline: 2.1646x; 1.0516x over previous
#include <cuda_runtime.h>
#include <cuda_bf16.h>
#include <cuda_fp16.h>
#include <cstdint>
#include <math.h>

#define NND 100000
#define NE  1600000
#define DF  128
#define HEADS 4
#define NG  64
#define NCLS 10
#define NEG 0.2f
#define SCANB 512

// ---------------- scratch (device globals; no allocation allowed) -----------
__device__ __align__(16) float  g_XW [NND * DF];
__device__ __align__(16) __half g_XWh[NND * DF];   // fp16 copy for messages
__device__ __align__(16) float  g_H  [NND * DF];
__device__ __align__(16) float  g_al[NND * HEADS];
__device__ __align__(16) float  g_ar[NND * HEADS];
__device__ int   g_deg[NND];
__device__ int   g_rowptr[NND + 1];
__device__ int   g_pos[NND];
__device__ int   g_bsum[(NND + SCANB - 1) / SCANB];
__device__ int   g_csr[NE];
__device__ float g_pool[NG * DF];
__device__ int   g_cnt[NG];
__device__ __align__(16) uint4 g_WhT[3][2048];
__device__ __align__(16) uint4 g_WlT[3][2048];

// ---------------- helpers ---------------------------------------------------
__device__ __forceinline__ float lrelu(float x) { return x > 0.f ? x : NEG * x; }
__device__ __forceinline__ void redAdd4(float* p, float4 v) {
    asm volatile("red.global.add.v4.f32 [%0], {%1,%2,%3,%4};"
                 :: "l"(p), "f"(v.x), "f"(v.y), "f"(v.z), "f"(v.w) : "memory");
}
__device__ __forceinline__ uint32_t smem_u32(const void* p) {
    uint32_t a;
    asm("{ .reg .u64 t; cvta.to.shared.u64 t, %1; cvt.u32.u64 %0, t; }" : "=r"(a) : "l"(p));
    return a;
}
__device__ __forceinline__ void ldm4(uint32_t& r0, uint32_t& r1, uint32_t& r2,
                                     uint32_t& r3, uint32_t addr) {
    asm volatile("ldmatrix.sync.aligned.m8n8.x4.shared.b16 {%0,%1,%2,%3}, [%4];"
                 : "=r"(r0), "=r"(r1), "=r"(r2), "=r"(r3) : "r"(addr));
}
__device__ __forceinline__ void mma16816(float* d, uint32_t a0, uint32_t a1,
                                         uint32_t a2, uint32_t a3,
                                         uint32_t b0, uint32_t b1) {
    asm volatile(
        "mma.sync.aligned.m16n8k16.row.col.f32.bf16.bf16.f32 "
        "{%0,%1,%2,%3}, {%4,%5,%6,%7}, {%8,%9}, {%0,%1,%2,%3};"
        : "+f"(d[0]), "+f"(d[1]), "+f"(d[2]), "+f"(d[3])
        : "r"(a0), "r"(a1), "r"(a2), "r"(a3), "r"(b0), "r"(b1));
}

union B16x8 { __nv_bfloat16 b[8]; uint4 u; };

// ---------------- weight prep: all 3 layers in one launch --------------------
__global__ void prep_all(const float* __restrict__ W0, const float* __restrict__ W1,
                         const float* __restrict__ W2) {
    int L = blockIdx.x >> 3;
    int i = (blockIdx.x & 7) * 256 + threadIdx.x;   // 0..2047
    const float* W = (L == 0) ? W0 : (L == 1) ? W1 : W2;
    int nn = i >> 4, c = i & 15;
    B16x8 H, Lo;
#pragma unroll
    for (int j = 0; j < 8; j++) {
        float wv = W[(c * 8 + j) * 128 + nn];
        __nv_bfloat16 h = __float2bfloat16(wv);
        H.b[j] = h;
        Lo.b[j] = __float2bfloat16(wv - __bfloat162float(h));
    }
    int off = nn * 16 + (c ^ (nn & 7));
    g_WhT[L][off] = H.u;
    g_WlT[L][off] = Lo.u;
}

// ---------------- HMMA GEMM + fused al/ar epilogue + fp16 copy ---------------
#define GS_AH 0
#define GS_AL 16384
#define GS_WH 32768
#define GS_WL 65536
#define GS_TOT 98304

__global__ void __launch_bounds__(128, 2) gemm_mma(
    const float* __restrict__ A, const uint4* __restrict__ WhT,
    const uint4* __restrict__ WlT, float* __restrict__ C,
    const float* __restrict__ attl, const float* __restrict__ attr,
    int n, int reluIn) {
    extern __shared__ char smem[];
    uint32_t sb = smem_u32(smem);
    int tid = threadIdx.x, w = tid >> 5, l = tid & 31;
    int row0 = blockIdx.x * 64;

    {
        uint4* wh = (uint4*)(smem + GS_WH);
        uint4* wl = (uint4*)(smem + GS_WL);
        for (int i = tid; i < 2048; i += 128) { wh[i] = WhT[i]; wl[i] = WlT[i]; }
    }
    for (int i = tid; i < 1024; i += 128) {
        int r = i >> 4, c = i & 15;
        int row = row0 + r;
        float4 v0 = make_float4(0.f, 0.f, 0.f, 0.f), v1 = v0;
        if (row < n) {
            v0 = *(const float4*)&A[row * 128 + c * 8];
            v1 = *(const float4*)&A[row * 128 + c * 8 + 4];
        }
        if (reluIn) {
            v0.x = fmaxf(v0.x, 0.f); v0.y = fmaxf(v0.y, 0.f);
            v0.z = fmaxf(v0.z, 0.f); v0.w = fmaxf(v0.w, 0.f);
            v1.x = fmaxf(v1.x, 0.f); v1.y = fmaxf(v1.y, 0.f);
            v1.z = fmaxf(v1.z, 0.f); v1.w = fmaxf(v1.w, 0.f);
        }
        B16x8 H, L;
        float vv[8] = { v0.x, v0.y, v0.z, v0.w, v1.x, v1.y, v1.z, v1.w };
#pragma unroll
        for (int j = 0; j < 8; j++) {
            __nv_bfloat16 h = __float2bfloat16(vv[j]);
            H.b[j] = h;
            L.b[j] = __float2bfloat16(vv[j] - __bfloat162float(h));
        }
        int off = r * 256 + ((c ^ (r & 7)) << 4);
        *(uint4*)(smem + GS_AH + off) = H.u;
        *(uint4*)(smem + GS_AL + off) = L.u;
    }
    __syncthreads();

    int aRow = (w << 4) + ((l >> 3) & 1) * 8 + (l & 7);
    int aChk = (l >> 4) & 1;
    uint32_t aBase = sb + GS_AH + aRow * 256;
    int aXor = aRow & 7;
    int bRowL = ((l >> 4) & 1) * 8 + (l & 7);
    int bChk = (l >> 3) & 1;

    float acc[64];
#pragma unroll
    for (int i = 0; i < 64; i++) acc[i] = 0.f;

#pragma unroll
    for (int ks = 0; ks < 8; ks++) {
        uint32_t ah0, ah1, ah2, ah3, al0, al1, al2, al3;
        uint32_t aOff = (((2 * ks + aChk) ^ aXor) << 4);
        ldm4(ah0, ah1, ah2, ah3, aBase + aOff);
        ldm4(al0, al1, al2, al3, aBase + 16384 + aOff);
#pragma unroll
        for (int p = 0; p < 8; p++) {
            int bRow = p * 16 + bRowL;
            uint32_t bAddr = sb + GS_WH + bRow * 256
                           + (((2 * ks + bChk) ^ (bRow & 7)) << 4);
            uint32_t bh0, bh1, bh2, bh3, bl0, bl1, bl2, bl3;
            ldm4(bh0, bh1, bh2, bh3, bAddr);
            ldm4(bl0, bl1, bl2, bl3, bAddr + 32768);
            float* d0 = &acc[(2 * p) * 4];
            float* d1 = &acc[(2 * p + 1) * 4];
            mma16816(d0, ah0, ah1, ah2, ah3, bh0, bh1);
            mma16816(d0, al0, al1, al2, al3, bh0, bh1);
            mma16816(d0, ah0, ah1, ah2, ah3, bl0, bl1);
            mma16816(d1, ah0, ah1, ah2, ah3, bh2, bh3);
            mma16816(d1, al0, al1, al2, al3, bh2, bh3);
            mma16816(d1, ah0, ah1, ah2, ah3, bl2, bl3);
        }
    }
    __syncthreads();

    float* Cs = (float*)smem;
    float* att = (float*)(smem + GS_WL);
    att[tid] = attl[tid];
    att[128 + tid] = attr[tid];
    {
        int r1 = w * 16 + (l >> 2);
#pragma unroll
        for (int nt = 0; nt < 16; nt++) {
            int col = nt * 8 + (l & 3) * 2;
            Cs[r1 * 132 + col]           = acc[nt * 4 + 0];
            Cs[r1 * 132 + col + 1]       = acc[nt * 4 + 1];
            Cs[(r1 + 8) * 132 + col]     = acc[nt * 4 + 2];
            Cs[(r1 + 8) * 132 + col + 1] = acc[nt * 4 + 3];
        }
    }
    __syncthreads();

    // write C fp32 + fp16 copy (coalesced)
    for (int i = tid; i < 64 * 32; i += 128) {
        int r = i >> 5, c4 = i & 31;
        int row = row0 + r;
        if (row < n) {
            float4 v = *(float4*)&Cs[r * 132 + c4 * 4];
            *(float4*)&C[row * 128 + c4 * 4] = v;
            __half2 h0 = __floats2half2_rn(v.x, v.y);
            __half2 h1 = __floats2half2_rn(v.z, v.w);
            uint2 u;
            u.x = *(uint32_t*)&h0; u.y = *(uint32_t*)&h1;
            *(uint2*)&g_XWh[row * 128 + c4 * 4] = u;
        }
    }
    // fused al / ar dots
    {
        int half_ = tid >> 6;
        int r = tid & 63;
        int row = row0 + r;
        if (row < n) {
            const float* av = att + half_ * 128;
            float d0 = 0.f, d1 = 0.f, d2 = 0.f, d3 = 0.f;
#pragma unroll 8
            for (int c = 0; c < 32; c++) {
                d0 += Cs[r * 132 + c]      * av[c];
                d1 += Cs[r * 132 + 32 + c] * av[32 + c];
                d2 += Cs[r * 132 + 64 + c] * av[64 + c];
                d3 += Cs[r * 132 + 96 + c] * av[96 + c];
            }
            float* dst = half_ ? g_ar : g_al;
            *(float4*)&dst[row * 4] = make_float4(d0, d1, d2, d3);
        }
    }
}

// ---------------- CSR build --------------------------------------------------
__global__ void zero_deg(int n) {
    int i = blockIdx.x * blockDim.x + threadIdx.x;
    if (i < n) g_deg[i] = 0;
}
__global__ void count_deg(const int* __restrict__ dst, int E) {
    int e = blockIdx.x * blockDim.x + threadIdx.x;
    if (e < E) atomicAdd(&g_deg[dst[e]], 1);
}
__global__ void scanA(int n) {
    __shared__ int sh[SCANB];
    int i = blockIdx.x * SCANB + threadIdx.x;
    int v = (i < n) ? g_deg[i] : 0;
    sh[threadIdx.x] = v;
    __syncthreads();
    for (int off = 1; off < SCANB; off <<= 1) {
        int t = (threadIdx.x >= off) ? sh[threadIdx.x - off] : 0;
        __syncthreads();
        sh[threadIdx.x] += t;
        __syncthreads();
    }
    if (i < n) g_rowptr[i] = sh[threadIdx.x] - v;
    if (threadIdx.x == SCANB - 1) g_bsum[blockIdx.x] = sh[SCANB - 1];
}
__global__ void scanB(int nb) {
    __shared__ int sh[256];
    int v = (threadIdx.x < nb) ? g_bsum[threadIdx.x] : 0;
    sh[threadIdx.x] = v;
    __syncthreads();
    for (int off = 1; off < 256; off <<= 1) {
        int t = (threadIdx.x >= off) ? sh[threadIdx.x - off] : 0;
        __syncthreads();
        sh[threadIdx.x] += t;
        __syncthreads();
    }
    if (threadIdx.x < nb) g_bsum[threadIdx.x] = sh[threadIdx.x] - v;
}
__global__ void scanC(int n, int E) {
    int i = blockIdx.x * blockDim.x + threadIdx.x;
    if (i < n) {
        int r = g_rowptr[i] + g_bsum[i / SCANB];
        g_rowptr[i] = r;
        g_pos[i] = r;
    }
    if (i == 0) g_rowptr[n] = E;
}
__global__ void csr_fill(const int* __restrict__ src, const int* __restrict__ dst, int E) {
    int e = blockIdx.x * blockDim.x + threadIdx.x;
    if (e >= E) return;
    int p = atomicAdd(&g_pos[dst[e]], 1);
    g_csr[p] = src[e];
}

// ---------------- fused per-node GAT (warp per node) -------------------------
__global__ void gat_node(const float* __restrict__ bias, int n) {
    int wid = (blockIdx.x * blockDim.x + threadIdx.x) >> 5;
    int l = threadIdx.x & 31;
    if (wid >= n) return;
    int rp = g_rowptr[wid], re = g_rowptr[wid + 1];

    float4 ad = *(const float4*)&g_al[wid * 4];
    float4 bd = *(const float4*)&g_ar[wid * 4];
    float slg0 = lrelu(ad.x + bd.x), slg1 = lrelu(ad.y + bd.y);
    float slg2 = lrelu(ad.z + bd.z), slg3 = lrelu(ad.w + bd.w);

    float m0 = slg0, m1 = slg1, m2 = slg2, m3 = slg3;
    for (int j = rp + l; j < re; j += 32) {
        int s = g_csr[j];
        float4 a = *(const float4*)&g_al[s * 4];
        m0 = fmaxf(m0, lrelu(a.x + bd.x));
        m1 = fmaxf(m1, lrelu(a.y + bd.y));
        m2 = fmaxf(m2, lrelu(a.z + bd.z));
        m3 = fmaxf(m3, lrelu(a.w + bd.w));
    }
#pragma unroll
    for (int o = 16; o > 0; o >>= 1) {
        m0 = fmaxf(m0, __shfl_xor_sync(0xFFFFFFFFu, m0, o));
        m1 = fmaxf(m1, __shfl_xor_sync(0xFFFFFFFFu, m1, o));
        m2 = fmaxf(m2, __shfl_xor_sync(0xFFFFFFFFu, m2, o));
        m3 = fmaxf(m3, __shfl_xor_sync(0xFFFFFFFFu, m3, o));
    }

    int h = l >> 3;
    int eo = l & 7;
    float mh   = (h == 0) ? m0 : (h == 1) ? m1 : (h == 2) ? m2 : m3;
    float arh  = (h == 0) ? bd.x : (h == 1) ? bd.y : (h == 2) ? bd.z : bd.w;
    float slgh = (h == 0) ? slg0 : (h == 1) ? slg1 : (h == 2) ? slg2 : slg3;

    float zacc = 0.f;
    float4 acc = make_float4(0.f, 0.f, 0.f, 0.f);
    for (int j0 = rp; j0 < re; j0 += 8) {
        int cnt = re - j0;
        int s_l = wid;
        float e_l = 0.f;
        if (eo < cnt) {
            s_l = g_csr[j0 + eo];
            float als = __ldg(&g_al[s_l * 4 + h]);
            e_l = __expf(lrelu(als + arh) - mh);
            zacc += e_l;
        }
        int kmax = (cnt >= 8) ? 8 : cnt;
#pragma unroll 8
        for (int k = 0; k < kmax; k++) {
            int s = __shfl_sync(0xFFFFFFFFu, s_l, k);
            float ek = __shfl_sync(0xFFFFFFFFu, e_l, (l & 24) | k);
            uint2 u = *(const uint2*)&g_XWh[s * 128 + 4 * l];
            __half2 p0 = *(__half2*)&u.x, p1 = *(__half2*)&u.y;
            float2 f0 = __half22float2(p0), f1 = __half22float2(p1);
            acc.x += ek * f0.x; acc.y += ek * f0.y;
            acc.z += ek * f1.x; acc.w += ek * f1.y;
        }
    }
#pragma unroll
    for (int o = 1; o < 8; o <<= 1) zacc += __shfl_xor_sync(0xFFFFFFFFu, zacc, o);

    float eself = __expf(slgh - mh);
    float rz = 1.f / (zacc + eself);
    float4 xs = *(const float4*)&g_XW[wid * 128 + 4 * l];
    acc.x = (acc.x + eself * xs.x) * rz;
    acc.y = (acc.y + eself * xs.y) * rz;
    acc.z = (acc.z + eself * xs.z) * rz;
    acc.w = (acc.w + eself * xs.w) * rz;
    float4 bv = *(const float4*)&bias[4 * l];
    acc.x += bv.x; acc.y += bv.y; acc.z += bv.z; acc.w += bv.w;
    *(float4*)&g_H[wid * 128 + 4 * l] = acc;
}

// ---------------- zero pool accumulators ------------------------------------
__global__ void zero_pool() {
    int i = blockIdx.x * blockDim.x + threadIdx.x;
    if (i < NG * DF) g_pool[i] = 0.f;
    if (i < NG) g_cnt[i] = 0;
}

// ---------------- pooling + write "last" output (relu fused) ----------------
__global__ void pool_copy(const int* __restrict__ batch, float* __restrict__ outLast, int n) {
    int wid = (blockIdx.x * blockDim.x + threadIdx.x) >> 5;
    int l = threadIdx.x & 31;
    if (wid >= n) return;
    float4 v = *(const float4*)&g_H[wid * 128 + 4 * l];
    v.x = fmaxf(v.x, 0.f); v.y = fmaxf(v.y, 0.f);
    v.z = fmaxf(v.z, 0.f); v.w = fmaxf(v.w, 0.f);
    *(float4*)&outLast[wid * 128 + 4 * l] = v;
    int b = batch[wid];
    redAdd4(&g_pool[b * 128 + 4 * l], v);
    if (l == 0) atomicAdd(&g_cnt[b], 1);
}

// ---------------- final MLP + log_softmax (block per graph) -----------------
__global__ void mlp_kernel(const float* __restrict__ lin1w, const float* __restrict__ lin1b,
                           const float* __restrict__ lin2w, const float* __restrict__ lin2b,
                           float* __restrict__ out) {
    __shared__ float pr[128];
    __shared__ float gg[128];
    __shared__ float lo[NCLS];
    int gr = blockIdx.x;
    int c = threadIdx.x;
    float cnt = (float)max(g_cnt[gr], 1);
    pr[c] = g_pool[gr * 128 + c] / cnt;
    __syncthreads();
    float acc = lin1b[c];
#pragma unroll 8
    for (int k = 0; k < 128; k++) acc += pr[k] * lin1w[k * 128 + c];
    gg[c] = fmaxf(acc, 0.f);
    __syncthreads();
    if (c < NCLS) {
        float a = lin2b[c];
#pragma unroll 8
        for (int k = 0; k < 128; k++) a += gg[k] * lin2w[k * NCLS + c];
        lo[c] = a;
    }
    __syncthreads();
    if (c == 0) {
        float mx = lo[0];
#pragma unroll
        for (int j = 1; j < NCLS; j++) mx = fmaxf(mx, lo[j]);
        float s = 0.f;
#pragma unroll
        for (int j = 0; j < NCLS; j++) s += expf(lo[j] - mx);
        float lse = mx + logf(s);
#pragma unroll
        for (int j = 0; j < NCLS; j++) out[gr * NCLS + j] = lo[j] - lse;
    }
}

// ---------------- host launcher ---------------------------------------------
extern "C" void kernel_launch(void* const* d_in, const int* in_sizes, int n_in,
                              void* d_out, int out_size) {
    const float* x    = (const float*)d_in[0];
    const int*   eidx = (const int*)d_in[1];
    const int*   batch= (const int*)d_in[2];
    const float* W[3]  = { (const float*)d_in[3], (const float*)d_in[7],  (const float*)d_in[11] };
    const float* al[3] = { (const float*)d_in[4], (const float*)d_in[8],  (const float*)d_in[12] };
    const float* ar[3] = { (const float*)d_in[5], (const float*)d_in[9],  (const float*)d_in[13] };
    const float* bb[3] = { (const float*)d_in[6], (const float*)d_in[10], (const float*)d_in[14] };
    const float* lin1w = (const float*)d_in[15];
    const float* lin1b = (const float*)d_in[16];
    const float* lin2w = (const float*)d_in[17];
    const float* lin2b = (const float*)d_in[18];

    int n = in_sizes[0] / DF;
    int E = in_sizes[1] / 2;
    const int* src = eidx;
    const int* dst = eidx + E;

    float* out_logits = (float*)d_out;
    float* out_last   = (float*)d_out + NG * NCLS;

    float* xw; cudaGetSymbolAddress((void**)&xw, g_XW);
    float* hh; cudaGetSymbolAddress((void**)&hh, g_H);
    uint4* wh; cudaGetSymbolAddress((void**)&wh, g_WhT);
    uint4* wl; cudaGetSymbolAddress((void**)&wl, g_WlT);

    static int smemSet = 0;
    if (!smemSet) {
        cudaFuncSetAttribute(gemm_mma, cudaFuncAttributeMaxDynamicSharedMemorySize, GS_TOT);
        smemSet = 1;
    }

    int warpNB = (n * 32 + 255) / 256;
    int edgeTB = (E + 255) / 256;
    int nodeTB = (n + 255) / 256;
    int nScanB = (n + SCANB - 1) / SCANB;
    int gemmB  = (n + 63) / 64;

    // launch order arranged so gemm_mma L0 sits at profiled launch index 3
    prep_all<<<24, 256>>>(W[0], W[1], W[2]);                         // 0
    zero_deg<<<nodeTB, 256>>>(n);                                    // 1
    count_deg<<<edgeTB, 256>>>(dst, E);                              // 2
    gemm_mma<<<gemmB, 128, GS_TOT>>>(x, wh, wl, xw, al[0], ar[0], n, 0);  // 3 <- profiled
    scanA<<<nScanB, SCANB>>>(n);                                     // 4
    scanB<<<1, 256>>>(nScanB);                                       // 5
    scanC<<<nodeTB, 256>>>(n, E);                                    // 6
    csr_fill<<<edgeTB, 256>>>(src, dst, E);                          // 7
    gat_node<<<warpNB, 256>>>(bb[0], n);                             // 8

    for (int L = 1; L < 3; L++) {
        gemm_mma<<<gemmB, 128, GS_TOT>>>(hh, wh + L * 2048, wl + L * 2048,
                                         xw, al[L], ar[L], n, 1);
        gat_node<<<warpNB, 256>>>(bb[L], n);
    }

    zero_pool<<<(NG * DF + 255) / 256, 256>>>();
    pool_copy<<<warpNB, 256>>>(batch, out_last, n);
    mlp_kernel<<<NG, 128>>>(lin1w, lin1b, lin2w, lin2b, out_logits);
}

// round 6
// speedup vs baseline: 2.3846x; 1.1016x over previous
#include <cuda_runtime.h>
#include <cuda_bf16.h>
#include <cuda_fp16.h>
#include <cstdint>
#include <math.h>

#define NND 100000
#define NE  1600000
#define DF  128
#define HEADS 4
#define NG  64
#define NCLS 10
#define NEG 0.2f
#define SCANB 512

// ---------------- scratch ----------------------------------------------------
__device__ __align__(16) float  g_XW [NND * DF];
__device__ __align__(16) __half g_XWh[NND * DF];
__device__ __align__(16) float  g_H  [NND * DF];
__device__ __align__(16) float  g_al[NND * HEADS];
__device__ __align__(16) float  g_ar[NND * HEADS];
__device__ unsigned g_gmaxenc[3][HEADS];
__device__ int   g_deg[NND];
__device__ int   g_rowptr[NND + 1];
__device__ int   g_pos[NND];
__device__ int   g_bsum[(NND + SCANB - 1) / SCANB];
__device__ int   g_csr[NE];
__device__ float g_pool[NG * DF];
__device__ int   g_cnt[NG];
__device__ __align__(16) uint4 g_WhT[3][2048];
__device__ __align__(16) uint4 g_WlT[3][2048];

// ---------------- helpers ----------------------------------------------------
__device__ __forceinline__ float lrelu(float x) { return x > 0.f ? x : NEG * x; }
__device__ __forceinline__ unsigned fenc(float f) {
    unsigned u = __float_as_uint(f);
    return (u & 0x80000000u) ? ~u : (u | 0x80000000u);
}
__device__ __forceinline__ float fdec(unsigned u) {
    return (u & 0x80000000u) ? __uint_as_float(u & 0x7FFFFFFFu)
                             : __uint_as_float(~u);
}
__device__ __forceinline__ float sel4(float4 v, int h) {
    return h == 0 ? v.x : h == 1 ? v.y : h == 2 ? v.z : v.w;
}
__device__ __forceinline__ void redAdd4(float* p, float4 v) {
    asm volatile("red.global.add.v4.f32 [%0], {%1,%2,%3,%4};"
                 :: "l"(p), "f"(v.x), "f"(v.y), "f"(v.z), "f"(v.w) : "memory");
}
__device__ __forceinline__ uint32_t smem_u32(const void* p) {
    uint32_t a;
    asm("{ .reg .u64 t; cvta.to.shared.u64 t, %1; cvt.u32.u64 %0, t; }" : "=r"(a) : "l"(p));
    return a;
}
__device__ __forceinline__ void ldm4(uint32_t& r0, uint32_t& r1, uint32_t& r2,
                                     uint32_t& r3, uint32_t addr) {
    asm volatile("ldmatrix.sync.aligned.m8n8.x4.shared.b16 {%0,%1,%2,%3}, [%4];"
                 : "=r"(r0), "=r"(r1), "=r"(r2), "=r"(r3) : "r"(addr));
}
__device__ __forceinline__ void mma16816(float* d, uint32_t a0, uint32_t a1,
                                         uint32_t a2, uint32_t a3,
                                         uint32_t b0, uint32_t b1) {
    asm volatile(
        "mma.sync.aligned.m16n8k16.row.col.f32.bf16.bf16.f32 "
        "{%0,%1,%2,%3}, {%4,%5,%6,%7}, {%8,%9}, {%0,%1,%2,%3};"
        : "+f"(d[0]), "+f"(d[1]), "+f"(d[2]), "+f"(d[3])
        : "r"(a0), "r"(a1), "r"(a2), "r"(a3), "r"(b0), "r"(b1));
}

union B16x8 { __nv_bfloat16 b[8]; uint4 u; };

// ---------------- weight prep (all layers, one launch) ------------------------
__global__ void prep_all(const float* __restrict__ W0, const float* __restrict__ W1,
                         const float* __restrict__ W2) {
    int L = blockIdx.x >> 3;
    int i = (blockIdx.x & 7) * 256 + threadIdx.x;
    const float* W = (L == 0) ? W0 : (L == 1) ? W1 : W2;
    int nn = i >> 4, c = i & 15;
    B16x8 H, Lo;
#pragma unroll
    for (int j = 0; j < 8; j++) {
        float wv = W[(c * 8 + j) * 128 + nn];
        __nv_bfloat16 h = __float2bfloat16(wv);
        H.b[j] = h;
        Lo.b[j] = __float2bfloat16(wv - __bfloat162float(h));
    }
    int off = nn * 16 + (c ^ (nn & 7));
    g_WhT[L][off] = H.u;
    g_WlT[L][off] = Lo.u;
}

// ---------------- HMMA GEMM (256 thr, 64 rows x 128 cols) --------------------
#define GS_AH 0
#define GS_AL 16384
#define GS_WH 32768
#define GS_WL 65536
#define GS_TOT 98304

__global__ void __launch_bounds__(256, 2) gemm_mma(
    const float* __restrict__ A, const uint4* __restrict__ WhT,
    const uint4* __restrict__ WlT, float* __restrict__ C,
    const float* __restrict__ attl, const float* __restrict__ attr,
    int n, int reluIn) {
    extern __shared__ char smem[];
    uint32_t sb = smem_u32(smem);
    int tid = threadIdx.x, w = tid >> 5, l = tid & 31;
    int rg = w & 3, ch = w >> 2;           // row-group 0..3, col-half 0..1
    int row0 = blockIdx.x * 64;

    {
        uint4* wh = (uint4*)(smem + GS_WH);
        uint4* wl = (uint4*)(smem + GS_WL);
        for (int i = tid; i < 2048; i += 256) { wh[i] = WhT[i]; wl[i] = WlT[i]; }
    }
    for (int i = tid; i < 1024; i += 256) {
        int r = i >> 4, c = i & 15;
        int row = row0 + r;
        float4 v0 = make_float4(0.f, 0.f, 0.f, 0.f), v1 = v0;
        if (row < n) {
            v0 = *(const float4*)&A[row * 128 + c * 8];
            v1 = *(const float4*)&A[row * 128 + c * 8 + 4];
        }
        if (reluIn) {
            v0.x = fmaxf(v0.x, 0.f); v0.y = fmaxf(v0.y, 0.f);
            v0.z = fmaxf(v0.z, 0.f); v0.w = fmaxf(v0.w, 0.f);
            v1.x = fmaxf(v1.x, 0.f); v1.y = fmaxf(v1.y, 0.f);
            v1.z = fmaxf(v1.z, 0.f); v1.w = fmaxf(v1.w, 0.f);
        }
        B16x8 H, L;
        float vv[8] = { v0.x, v0.y, v0.z, v0.w, v1.x, v1.y, v1.z, v1.w };
#pragma unroll
        for (int j = 0; j < 8; j++) {
            __nv_bfloat16 h = __float2bfloat16(vv[j]);
            H.b[j] = h;
            L.b[j] = __float2bfloat16(vv[j] - __bfloat162float(h));
        }
        int off = r * 256 + ((c ^ (r & 7)) << 4);
        *(uint4*)(smem + GS_AH + off) = H.u;
        *(uint4*)(smem + GS_AL + off) = L.u;
    }
    __syncthreads();

    int aRow = rg * 16 + ((l >> 3) & 1) * 8 + (l & 7);
    int aChk = (l >> 4) & 1;
    uint32_t aBase = sb + GS_AH + aRow * 256;
    int aXor = aRow & 7;
    int bRowL = ((l >> 4) & 1) * 8 + (l & 7);
    int bChk = (l >> 3) & 1;

    float acc[32];
#pragma unroll
    for (int i = 0; i < 32; i++) acc[i] = 0.f;

#pragma unroll
    for (int ks = 0; ks < 8; ks++) {
        uint32_t ah0, ah1, ah2, ah3, al0, al1, al2, al3;
        uint32_t aOff = (((2 * ks + aChk) ^ aXor) << 4);
        ldm4(ah0, ah1, ah2, ah3, aBase + aOff);
        ldm4(al0, al1, al2, al3, aBase + 16384 + aOff);
#pragma unroll
        for (int p = 0; p < 4; p++) {
            int bRow = ch * 64 + p * 16 + bRowL;
            uint32_t bAddr = sb + GS_WH + bRow * 256
                           + (((2 * ks + bChk) ^ (bRow & 7)) << 4);
            uint32_t bh0, bh1, bh2, bh3, bl0, bl1, bl2, bl3;
            ldm4(bh0, bh1, bh2, bh3, bAddr);
            ldm4(bl0, bl1, bl2, bl3, bAddr + 32768);
            float* d0 = &acc[(2 * p) * 4];
            float* d1 = &acc[(2 * p + 1) * 4];
            mma16816(d0, ah0, ah1, ah2, ah3, bh0, bh1);
            mma16816(d0, al0, al1, al2, al3, bh0, bh1);
            mma16816(d0, ah0, ah1, ah2, ah3, bl0, bl1);
            mma16816(d1, ah0, ah1, ah2, ah3, bh2, bh3);
            mma16816(d1, al0, al1, al2, al3, bh2, bh3);
            mma16816(d1, ah0, ah1, ah2, ah3, bl2, bl3);
        }
    }
    __syncthreads();

    float* Cs = (float*)smem;              // 64 x 132 floats (A/W regions dead)
    float* att = (float*)(smem + GS_WL);
    att[tid] = (tid < 128) ? attl[tid] : attr[tid - 128];
    {
        int r1 = rg * 16 + (l >> 2);
#pragma unroll
        for (int nt = 0; nt < 8; nt++) {
            int p = nt >> 1, t = nt & 1;
            int col = ch * 64 + p * 16 + t * 8 + (l & 3) * 2;
            float* d = &acc[nt * 4];
            Cs[r1 * 132 + col]           = d[0];
            Cs[r1 * 132 + col + 1]       = d[1];
            Cs[(r1 + 8) * 132 + col]     = d[2];
            Cs[(r1 + 8) * 132 + col + 1] = d[3];
        }
    }
    __syncthreads();

    for (int i = tid; i < 2048; i += 256) {
        int r = i >> 5, c4 = i & 31;
        int row = row0 + r;
        if (row < n) {
            float4 v = *(float4*)&Cs[r * 132 + c4 * 4];
            *(float4*)&C[row * 128 + c4 * 4] = v;
            __half2 h0 = __floats2half2_rn(v.x, v.y);
            __half2 h1 = __floats2half2_rn(v.z, v.w);
            uint2 u;
            u.x = *(uint32_t*)&h0; u.y = *(uint32_t*)&h1;
            *(uint2*)&g_XWh[row * 128 + c4 * 4] = u;
        }
    }
    if (tid < 128) {
        int half_ = tid >> 6;
        int r = tid & 63;
        int row = row0 + r;
        if (row < n) {
            const float* av = att + half_ * 128;
            float d0 = 0.f, d1 = 0.f, d2 = 0.f, d3 = 0.f;
#pragma unroll 8
            for (int c = 0; c < 32; c++) {
                d0 += Cs[r * 132 + c]      * av[c];
                d1 += Cs[r * 132 + 32 + c] * av[32 + c];
                d2 += Cs[r * 132 + 64 + c] * av[64 + c];
                d3 += Cs[r * 132 + 96 + c] * av[96 + c];
            }
            float* dst = half_ ? g_ar : g_al;
            *(float4*)&dst[row * 4] = make_float4(d0, d1, d2, d3);
        }
    }
}

// ---------------- global per-head max of al ----------------------------------
__global__ void almax(int n, int L) {
    __shared__ float sm[8][4];
    int tid = threadIdx.x, wr = tid >> 5, l = tid & 31;
    float m0 = -1e30f, m1 = -1e30f, m2 = -1e30f, m3 = -1e30f;
    for (int i = blockIdx.x * blockDim.x + tid; i < n; i += gridDim.x * blockDim.x) {
        float4 a = *(const float4*)&g_al[i * 4];
        m0 = fmaxf(m0, a.x); m1 = fmaxf(m1, a.y);
        m2 = fmaxf(m2, a.z); m3 = fmaxf(m3, a.w);
    }
#pragma unroll
    for (int o = 16; o > 0; o >>= 1) {
        m0 = fmaxf(m0, __shfl_xor_sync(0xFFFFFFFFu, m0, o));
        m1 = fmaxf(m1, __shfl_xor_sync(0xFFFFFFFFu, m1, o));
        m2 = fmaxf(m2, __shfl_xor_sync(0xFFFFFFFFu, m2, o));
        m3 = fmaxf(m3, __shfl_xor_sync(0xFFFFFFFFu, m3, o));
    }
    if (l == 0) { sm[wr][0] = m0; sm[wr][1] = m1; sm[wr][2] = m2; sm[wr][3] = m3; }
    __syncthreads();
    if (tid < 4) {
        float m = sm[0][tid];
#pragma unroll
        for (int j = 1; j < 8; j++) m = fmaxf(m, sm[j][tid]);
        atomicMax(&g_gmaxenc[L][tid], fenc(m));
    }
}

// ---------------- CSR build --------------------------------------------------
__global__ void zero_deg(int n) {
    int i = blockIdx.x * blockDim.x + threadIdx.x;
    if (i < n) g_deg[i] = 0;
    if (i < 12) ((unsigned*)g_gmaxenc)[i] = 0u;
}
__global__ void count_deg(const int* __restrict__ dst, int E) {
    int e = blockIdx.x * blockDim.x + threadIdx.x;
    if (e < E) atomicAdd(&g_deg[dst[e]], 1);
}
__global__ void scanA(int n) {
    __shared__ int sh[SCANB];
    int i = blockIdx.x * SCANB + threadIdx.x;
    int v = (i < n) ? g_deg[i] : 0;
    sh[threadIdx.x] = v;
    __syncthreads();
    for (int off = 1; off < SCANB; off <<= 1) {
        int t = (threadIdx.x >= off) ? sh[threadIdx.x - off] : 0;
        __syncthreads();
        sh[threadIdx.x] += t;
        __syncthreads();
    }
    if (i < n) g_rowptr[i] = sh[threadIdx.x] - v;
    if (threadIdx.x == SCANB - 1) g_bsum[blockIdx.x] = sh[SCANB - 1];
}
__global__ void scanB(int nb) {
    __shared__ int sh[256];
    int v = (threadIdx.x < nb) ? g_bsum[threadIdx.x] : 0;
    sh[threadIdx.x] = v;
    __syncthreads();
    for (int off = 1; off < 256; off <<= 1) {
        int t = (threadIdx.x >= off) ? sh[threadIdx.x - off] : 0;
        __syncthreads();
        sh[threadIdx.x] += t;
        __syncthreads();
    }
    if (threadIdx.x < nb) g_bsum[threadIdx.x] = sh[threadIdx.x] - v;
}
__global__ void scanC(int n, int E) {
    int i = blockIdx.x * blockDim.x + threadIdx.x;
    if (i < n) {
        int r = g_rowptr[i] + g_bsum[i / SCANB];
        g_rowptr[i] = r;
        g_pos[i] = r;
    }
    if (i == 0) g_rowptr[n] = E;
}
__global__ void csr_fill(const int* __restrict__ src, const int* __restrict__ dst, int E) {
    int e = blockIdx.x * blockDim.x + threadIdx.x;
    if (e >= E) return;
    int p = atomicAdd(&g_pos[dst[e]], 1);
    g_csr[p] = src[e];
}

// ---------------- fused per-node GAT: SINGLE edge sweep ----------------------
__global__ void gat_node(const float* __restrict__ bias, int n, int L) {
    int wid = (blockIdx.x * blockDim.x + threadIdx.x) >> 5;
    int l = threadIdx.x & 31;
    if (wid >= n) return;
    int rp = g_rowptr[wid], re = g_rowptr[wid + 1];

    float4 ad = *(const float4*)&g_al[wid * 4];
    float4 bd = *(const float4*)&g_ar[wid * 4];

    int h = l >> 3;
    int eo = l & 7;
    float arh  = sel4(bd, h);
    float gm   = fdec(g_gmaxenc[L][h]);
    float mh   = lrelu(gm + arh);                 // upper bound of all logits into d
    float slgh = lrelu(sel4(ad, h) + arh);

    float zacc = 0.f;
    float4 acc = make_float4(0.f, 0.f, 0.f, 0.f);
    for (int j0 = rp; j0 < re; j0 += 8) {
        int cnt = re - j0;
        int s_l = wid;
        float e_l = 0.f;
        if (eo < cnt) {
            s_l = g_csr[j0 + eo];
            float als = __ldg(&g_al[s_l * 4 + h]);
            e_l = __expf(lrelu(als + arh) - mh);
            zacc += e_l;
        }
        int kmax = (cnt >= 8) ? 8 : cnt;
#pragma unroll 8
        for (int k = 0; k < kmax; k++) {
            int s = __shfl_sync(0xFFFFFFFFu, s_l, k);
            float ek = __shfl_sync(0xFFFFFFFFu, e_l, (l & 24) | k);
            uint2 u = *(const uint2*)&g_XWh[s * 128 + 4 * l];
            __half2 p0 = *(__half2*)&u.x, p1 = *(__half2*)&u.y;
            float2 f0 = __half22float2(p0), f1 = __half22float2(p1);
            acc.x += ek * f0.x; acc.y += ek * f0.y;
            acc.z += ek * f1.x; acc.w += ek * f1.y;
        }
    }
#pragma unroll
    for (int o = 1; o < 8; o <<= 1) zacc += __shfl_xor_sync(0xFFFFFFFFu, zacc, o);

    float eself = __expf(slgh - mh);
    float rz = 1.f / (zacc + eself);
    float4 xs = *(const float4*)&g_XW[wid * 128 + 4 * l];
    acc.x = (acc.x + eself * xs.x) * rz;
    acc.y = (acc.y + eself * xs.y) * rz;
    acc.z = (acc.z + eself * xs.z) * rz;
    acc.w = (acc.w + eself * xs.w) * rz;
    float4 bv = *(const float4*)&bias[4 * l];
    acc.x += bv.x; acc.y += bv.y; acc.z += bv.z; acc.w += bv.w;
    *(float4*)&g_H[wid * 128 + 4 * l] = acc;
}

// ---------------- pooling / MLP ----------------------------------------------
__global__ void zero_pool() {
    int i = blockIdx.x * blockDim.x + threadIdx.x;
    if (i < NG * DF) g_pool[i] = 0.f;
    if (i < NG) g_cnt[i] = 0;
}
__global__ void pool_copy(const int* __restrict__ batch, float* __restrict__ outLast, int n) {
    int wid = (blockIdx.x * blockDim.x + threadIdx.x) >> 5;
    int l = threadIdx.x & 31;
    if (wid >= n) return;
    float4 v = *(const float4*)&g_H[wid * 128 + 4 * l];
    v.x = fmaxf(v.x, 0.f); v.y = fmaxf(v.y, 0.f);
    v.z = fmaxf(v.z, 0.f); v.w = fmaxf(v.w, 0.f);
    *(float4*)&outLast[wid * 128 + 4 * l] = v;
    int b = batch[wid];
    redAdd4(&g_pool[b * 128 + 4 * l], v);
    if (l == 0) atomicAdd(&g_cnt[b], 1);
}
__global__ void mlp_kernel(const float* __restrict__ lin1w, const float* __restrict__ lin1b,
                           const float* __restrict__ lin2w, const float* __restrict__ lin2b,
                           float* __restrict__ out) {
    __shared__ float pr[128];
    __shared__ float gg[128];
    __shared__ float lo[NCLS];
    int gr = blockIdx.x;
    int c = threadIdx.x;
    float cnt = (float)max(g_cnt[gr], 1);
    pr[c] = g_pool[gr * 128 + c] / cnt;
    __syncthreads();
    float acc = lin1b[c];
#pragma unroll 8
    for (int k = 0; k < 128; k++) acc += pr[k] * lin1w[k * 128 + c];
    gg[c] = fmaxf(acc, 0.f);
    __syncthreads();
    if (c < NCLS) {
        float a = lin2b[c];
#pragma unroll 8
        for (int k = 0; k < 128; k++) a += gg[k] * lin2w[k * NCLS + c];
        lo[c] = a;
    }
    __syncthreads();
    if (c == 0) {
        float mx = lo[0];
#pragma unroll
        for (int j = 1; j < NCLS; j++) mx = fmaxf(mx, lo[j]);
        float s = 0.f;
#pragma unroll
        for (int j = 0; j < NCLS; j++) s += expf(lo[j] - mx);
        float lse = mx + logf(s);
#pragma unroll
        for (int j = 0; j < NCLS; j++) out[gr * NCLS + j] = lo[j] - lse;
    }
}

// ---------------- host launcher ---------------------------------------------
extern "C" void kernel_launch(void* const* d_in, const int* in_sizes, int n_in,
                              void* d_out, int out_size) {
    const float* x    = (const float*)d_in[0];
    const int*   eidx = (const int*)d_in[1];
    const int*   batch= (const int*)d_in[2];
    const float* W[3]  = { (const float*)d_in[3], (const float*)d_in[7],  (const float*)d_in[11] };
    const float* al[3] = { (const float*)d_in[4], (const float*)d_in[8],  (const float*)d_in[12] };
    const float* ar[3] = { (const float*)d_in[5], (const float*)d_in[9],  (const float*)d_in[13] };
    const float* bb[3] = { (const float*)d_in[6], (const float*)d_in[10], (const float*)d_in[14] };
    const float* lin1w = (const float*)d_in[15];
    const float* lin1b = (const float*)d_in[16];
    const float* lin2w = (const float*)d_in[17];
    const float* lin2b = (const float*)d_in[18];

    int n = in_sizes[0] / DF;
    int E = in_sizes[1] / 2;
    const int* src = eidx;
    const int* dst = eidx + E;

    float* out_logits = (float*)d_out;
    float* out_last   = (float*)d_out + NG * NCLS;

    float* xw; cudaGetSymbolAddress((void**)&xw, g_XW);
    float* hh; cudaGetSymbolAddress((void**)&hh, g_H);
    uint4* wh; cudaGetSymbolAddress((void**)&wh, g_WhT);
    uint4* wl; cudaGetSymbolAddress((void**)&wl, g_WlT);

    static int smemSet = 0;
    if (!smemSet) {
        cudaFuncSetAttribute(gemm_mma, cudaFuncAttributeMaxDynamicSharedMemorySize, GS_TOT);
        smemSet = 1;
    }

    int warpNB = (n * 32 + 255) / 256;
    int edgeTB = (E + 255) / 256;
    int nodeTB = (n + 255) / 256;
    int nScanB = (n + SCANB - 1) / SCANB;
    int gemmB  = (n + 63) / 64;

    prep_all<<<24, 256>>>(W[0], W[1], W[2]);                              // 0
    zero_deg<<<nodeTB, 256>>>(n);                                         // 1
    count_deg<<<edgeTB, 256>>>(dst, E);                                   // 2
    gemm_mma<<<gemmB, 256, GS_TOT>>>(x, wh, wl, xw, al[0], ar[0], n, 0);  // 3 <- profiled
    almax<<<148, 256>>>(n, 0);                                            // 4
    scanA<<<nScanB, SCANB>>>(n);                                          // 5
    scanB<<<1, 256>>>(nScanB);                                            // 6
    scanC<<<nodeTB, 256>>>(n, E);                                         // 7
    csr_fill<<<edgeTB, 256>>>(src, dst, E);                               // 8
    gat_node<<<warpNB, 256>>>(bb[0], n, 0);                               // 9

    for (int L = 1; L < 3; L++) {
        gemm_mma<<<gemmB, 256, GS_TOT>>>(hh, wh + L * 2048, wl + L * 2048,
                                         xw, al[L], ar[L], n, 1);
        almax<<<148, 256>>>(n, L);
        gat_node<<<warpNB, 256>>>(bb[L], n, L);
    }

    zero_pool<<<(NG * DF + 255) / 256, 256>>>();
    pool_copy<<<warpNB, 256>>>(batch, out_last, n);
    mlp_kernel<<<NG, 128>>>(lin1w, lin1b, lin2w, lin2b, out_logits);
}

// round 7
// speedup vs baseline: 2.7971x; 1.1730x over previous
#include <cuda_runtime.h>
#include <cuda_bf16.h>
#include <cuda_fp16.h>
#include <cstdint>
#include <math.h>

#define NND 100000
#define NE  1600000
#define DF  128
#define HEADS 4
#define NG  64
#define NCLS 10
#define NEG 0.2f
#define SCANB 512

// ---------------- scratch ----------------------------------------------------
__device__ __align__(16) __half g_XWh[NND * DF];   // fp16 x@W (messages+self)
__device__ __align__(16) float  g_H  [NND * DF];   // layer output fp32
__device__ __align__(16) float  g_al[NND * HEADS];
__device__ __align__(16) float  g_ar[NND * HEADS];
__device__ unsigned g_gmaxenc[3][HEADS];
__device__ int   g_deg[NND];
__device__ int   g_rowptr[NND + 1];
__device__ int   g_pos[NND];
__device__ int   g_bsum[(NND + SCANB - 1) / SCANB];
__device__ int   g_csr[NE];
__device__ float g_pool[NG * DF];
__device__ int   g_cnt[NG];
__device__ __align__(16) uint4 g_WhT[3][2048];
__device__ __align__(16) uint4 g_WlT[3][2048];

// ---------------- helpers ----------------------------------------------------
__device__ __forceinline__ float lrelu(float x) { return x > 0.f ? x : NEG * x; }
__device__ __forceinline__ unsigned fenc(float f) {
    unsigned u = __float_as_uint(f);
    return (u & 0x80000000u) ? ~u : (u | 0x80000000u);
}
__device__ __forceinline__ float fdec(unsigned u) {
    return (u & 0x80000000u) ? __uint_as_float(u & 0x7FFFFFFFu)
                             : __uint_as_float(~u);
}
__device__ __forceinline__ float sel4(float4 v, int h) {
    return h == 0 ? v.x : h == 1 ? v.y : h == 2 ? v.z : v.w;
}
__device__ __forceinline__ void redAdd4(float* p, float4 v) {
    asm volatile("red.global.add.v4.f32 [%0], {%1,%2,%3,%4};"
                 :: "l"(p), "f"(v.x), "f"(v.y), "f"(v.z), "f"(v.w) : "memory");
}
__device__ __forceinline__ void stcs4(float* p, float4 v) {
    asm volatile("st.global.cs.v4.f32 [%0], {%1,%2,%3,%4};"
                 :: "l"(p), "f"(v.x), "f"(v.y), "f"(v.z), "f"(v.w) : "memory");
}
__device__ __forceinline__ uint32_t smem_u32(const void* p) {
    uint32_t a;
    asm("{ .reg .u64 t; cvta.to.shared.u64 t, %1; cvt.u32.u64 %0, t; }" : "=r"(a) : "l"(p));
    return a;
}
__device__ __forceinline__ void ldm4(uint32_t& r0, uint32_t& r1, uint32_t& r2,
                                     uint32_t& r3, uint32_t addr) {
    asm volatile("ldmatrix.sync.aligned.m8n8.x4.shared.b16 {%0,%1,%2,%3}, [%4];"
                 : "=r"(r0), "=r"(r1), "=r"(r2), "=r"(r3) : "r"(addr));
}
__device__ __forceinline__ void mma16816(float* d, uint32_t a0, uint32_t a1,
                                         uint32_t a2, uint32_t a3,
                                         uint32_t b0, uint32_t b1) {
    asm volatile(
        "mma.sync.aligned.m16n8k16.row.col.f32.bf16.bf16.f32 "
        "{%0,%1,%2,%3}, {%4,%5,%6,%7}, {%8,%9}, {%0,%1,%2,%3};"
        : "+f"(d[0]), "+f"(d[1]), "+f"(d[2]), "+f"(d[3])
        : "r"(a0), "r"(a1), "r"(a2), "r"(a3), "r"(b0), "r"(b1));
}

union B16x8 { __nv_bfloat16 b[8]; uint4 u; };

// ---------------- weight prep (all layers, one launch) ------------------------
__global__ void prep_all(const float* __restrict__ W0, const float* __restrict__ W1,
                         const float* __restrict__ W2) {
    int L = blockIdx.x >> 3;
    int i = (blockIdx.x & 7) * 256 + threadIdx.x;
    const float* W = (L == 0) ? W0 : (L == 1) ? W1 : W2;
    int nn = i >> 4, c = i & 15;
    B16x8 H, Lo;
#pragma unroll
    for (int j = 0; j < 8; j++) {
        float wv = W[(c * 8 + j) * 128 + nn];
        __nv_bfloat16 h = __float2bfloat16(wv);
        H.b[j] = h;
        Lo.b[j] = __float2bfloat16(wv - __bfloat162float(h));
    }
    int off = nn * 16 + (c ^ (nn & 7));
    g_WhT[L][off] = H.u;
    g_WlT[L][off] = Lo.u;
}

// ---------------- HMMA GEMM (256 thr, 64 rows x 128 cols) --------------------
#define GS_AH 0
#define GS_AL 16384
#define GS_WH 32768
#define GS_WL 65536
#define GS_TOT 98304

__global__ void __launch_bounds__(256, 2) gemm_mma(
    const float* __restrict__ A, const uint4* __restrict__ WhT,
    const uint4* __restrict__ WlT,
    const float* __restrict__ attl, const float* __restrict__ attr,
    int n, int reluIn) {
    extern __shared__ char smem[];
    uint32_t sb = smem_u32(smem);
    int tid = threadIdx.x, w = tid >> 5, l = tid & 31;
    int rg = w & 3, ch = w >> 2;
    int row0 = blockIdx.x * 64;

    {
        uint4* wh = (uint4*)(smem + GS_WH);
        uint4* wl = (uint4*)(smem + GS_WL);
        for (int i = tid; i < 2048; i += 256) { wh[i] = WhT[i]; wl[i] = WlT[i]; }
    }
    for (int i = tid; i < 1024; i += 256) {
        int r = i >> 4, c = i & 15;
        int row = row0 + r;
        float4 v0 = make_float4(0.f, 0.f, 0.f, 0.f), v1 = v0;
        if (row < n) {
            v0 = __ldcs((const float4*)&A[row * 128 + c * 8]);
            v1 = __ldcs((const float4*)&A[row * 128 + c * 8 + 4]);
        }
        if (reluIn) {
            v0.x = fmaxf(v0.x, 0.f); v0.y = fmaxf(v0.y, 0.f);
            v0.z = fmaxf(v0.z, 0.f); v0.w = fmaxf(v0.w, 0.f);
            v1.x = fmaxf(v1.x, 0.f); v1.y = fmaxf(v1.y, 0.f);
            v1.z = fmaxf(v1.z, 0.f); v1.w = fmaxf(v1.w, 0.f);
        }
        B16x8 H, L;
        float vv[8] = { v0.x, v0.y, v0.z, v0.w, v1.x, v1.y, v1.z, v1.w };
#pragma unroll
        for (int j = 0; j < 8; j++) {
            __nv_bfloat16 h = __float2bfloat16(vv[j]);
            H.b[j] = h;
            L.b[j] = __float2bfloat16(vv[j] - __bfloat162float(h));
        }
        int off = r * 256 + ((c ^ (r & 7)) << 4);
        *(uint4*)(smem + GS_AH + off) = H.u;
        *(uint4*)(smem + GS_AL + off) = L.u;
    }
    __syncthreads();

    int aRow = rg * 16 + ((l >> 3) & 1) * 8 + (l & 7);
    int aChk = (l >> 4) & 1;
    uint32_t aBase = sb + GS_AH + aRow * 256;
    int aXor = aRow & 7;
    int bRowL = ((l >> 4) & 1) * 8 + (l & 7);
    int bChk = (l >> 3) & 1;

    float acc[32];
#pragma unroll
    for (int i = 0; i < 32; i++) acc[i] = 0.f;

#pragma unroll
    for (int ks = 0; ks < 8; ks++) {
        uint32_t ah0, ah1, ah2, ah3, al0, al1, al2, al3;
        uint32_t aOff = (((2 * ks + aChk) ^ aXor) << 4);
        ldm4(ah0, ah1, ah2, ah3, aBase + aOff);
        ldm4(al0, al1, al2, al3, aBase + 16384 + aOff);
#pragma unroll
        for (int p = 0; p < 4; p++) {
            int bRow = ch * 64 + p * 16 + bRowL;
            uint32_t bAddr = sb + GS_WH + bRow * 256
                           + (((2 * ks + bChk) ^ (bRow & 7)) << 4);
            uint32_t bh0, bh1, bh2, bh3, bl0, bl1, bl2, bl3;
            ldm4(bh0, bh1, bh2, bh3, bAddr);
            ldm4(bl0, bl1, bl2, bl3, bAddr + 32768);
            float* d0 = &acc[(2 * p) * 4];
            float* d1 = &acc[(2 * p + 1) * 4];
            mma16816(d0, ah0, ah1, ah2, ah3, bh0, bh1);
            mma16816(d0, al0, al1, al2, al3, bh0, bh1);
            mma16816(d0, ah0, ah1, ah2, ah3, bl0, bl1);
            mma16816(d1, ah0, ah1, ah2, ah3, bh2, bh3);
            mma16816(d1, al0, al1, al2, al3, bh2, bh3);
            mma16816(d1, ah0, ah1, ah2, ah3, bl2, bl3);
        }
    }
    __syncthreads();

    float* Cs = (float*)smem;              // 64 x 132 floats
    float* att = (float*)(smem + GS_WL);
    att[tid] = (tid < 128) ? attl[tid] : attr[tid - 128];
    {
        int r1 = rg * 16 + (l >> 2);
#pragma unroll
        for (int nt = 0; nt < 8; nt++) {
            int p = nt >> 1, t = nt & 1;
            int col = ch * 64 + p * 16 + t * 8 + (l & 3) * 2;
            float* d = &acc[nt * 4];
            Cs[r1 * 132 + col]           = d[0];
            Cs[r1 * 132 + col + 1]       = d[1];
            Cs[(r1 + 8) * 132 + col]     = d[2];
            Cs[(r1 + 8) * 132 + col + 1] = d[3];
        }
    }
    __syncthreads();

    // write fp16 XWh only (no fp32 C)
    for (int i = tid; i < 2048; i += 256) {
        int r = i >> 5, c4 = i & 31;
        int row = row0 + r;
        if (row < n) {
            float4 v = *(float4*)&Cs[r * 132 + c4 * 4];
            __half2 h0 = __floats2half2_rn(v.x, v.y);
            __half2 h1 = __floats2half2_rn(v.z, v.w);
            uint2 u;
            u.x = *(uint32_t*)&h0; u.y = *(uint32_t*)&h1;
            *(uint2*)&g_XWh[row * 128 + c4 * 4] = u;
        }
    }
    if (tid < 128) {
        int half_ = tid >> 6;
        int r = tid & 63;
        int row = row0 + r;
        if (row < n) {
            const float* av = att + half_ * 128;
            float d0 = 0.f, d1 = 0.f, d2 = 0.f, d3 = 0.f;
#pragma unroll 8
            for (int c = 0; c < 32; c++) {
                d0 += Cs[r * 132 + c]      * av[c];
                d1 += Cs[r * 132 + 32 + c] * av[32 + c];
                d2 += Cs[r * 132 + 64 + c] * av[64 + c];
                d3 += Cs[r * 132 + 96 + c] * av[96 + c];
            }
            float* dst = half_ ? g_ar : g_al;
            *(float4*)&dst[row * 4] = make_float4(d0, d1, d2, d3);
        }
    }
}

// ---------------- global per-head max of al ----------------------------------
__global__ void almax(int n, int L) {
    __shared__ float sm[8][4];
    int tid = threadIdx.x, wr = tid >> 5, l = tid & 31;
    float m0 = -1e30f, m1 = -1e30f, m2 = -1e30f, m3 = -1e30f;
    for (int i = blockIdx.x * blockDim.x + tid; i < n; i += gridDim.x * blockDim.x) {
        float4 a = *(const float4*)&g_al[i * 4];
        m0 = fmaxf(m0, a.x); m1 = fmaxf(m1, a.y);
        m2 = fmaxf(m2, a.z); m3 = fmaxf(m3, a.w);
    }
#pragma unroll
    for (int o = 16; o > 0; o >>= 1) {
        m0 = fmaxf(m0, __shfl_xor_sync(0xFFFFFFFFu, m0, o));
        m1 = fmaxf(m1, __shfl_xor_sync(0xFFFFFFFFu, m1, o));
        m2 = fmaxf(m2, __shfl_xor_sync(0xFFFFFFFFu, m2, o));
        m3 = fmaxf(m3, __shfl_xor_sync(0xFFFFFFFFu, m3, o));
    }
    if (l == 0) { sm[wr][0] = m0; sm[wr][1] = m1; sm[wr][2] = m2; sm[wr][3] = m3; }
    __syncthreads();
    if (tid < 4) {
        float m = sm[0][tid];
#pragma unroll
        for (int j = 1; j < 8; j++) m = fmaxf(m, sm[j][tid]);
        atomicMax(&g_gmaxenc[L][tid], fenc(m));
    }
}

// ---------------- CSR build --------------------------------------------------
__global__ void zero_deg(int n) {
    int i = blockIdx.x * blockDim.x + threadIdx.x;
    if (i < n) g_deg[i] = 0;
    if (i < 12) ((unsigned*)g_gmaxenc)[i] = 0u;
}
__global__ void count_deg(const int* __restrict__ dst, int E) {
    int e = blockIdx.x * blockDim.x + threadIdx.x;
    if (e < E) atomicAdd(&g_deg[dst[e]], 1);
}
__global__ void scanA(int n) {
    __shared__ int sh[SCANB];
    int i = blockIdx.x * SCANB + threadIdx.x;
    int v = (i < n) ? g_deg[i] : 0;
    sh[threadIdx.x] = v;
    __syncthreads();
    for (int off = 1; off < SCANB; off <<= 1) {
        int t = (threadIdx.x >= off) ? sh[threadIdx.x - off] : 0;
        __syncthreads();
        sh[threadIdx.x] += t;
        __syncthreads();
    }
    if (i < n) g_rowptr[i] = sh[threadIdx.x] - v;
    if (threadIdx.x == SCANB - 1) g_bsum[blockIdx.x] = sh[SCANB - 1];
}
__global__ void scanB(int nb) {
    __shared__ int sh[256];
    int v = (threadIdx.x < nb) ? g_bsum[threadIdx.x] : 0;
    sh[threadIdx.x] = v;
    __syncthreads();
    for (int off = 1; off < 256; off <<= 1) {
        int t = (threadIdx.x >= off) ? sh[threadIdx.x - off] : 0;
        __syncthreads();
        sh[threadIdx.x] += t;
        __syncthreads();
    }
    if (threadIdx.x < nb) g_bsum[threadIdx.x] = sh[threadIdx.x] - v;
}
__global__ void scanC(int n, int E) {
    int i = blockIdx.x * blockDim.x + threadIdx.x;
    if (i < n) {
        int r = g_rowptr[i] + g_bsum[i / SCANB];
        g_rowptr[i] = r;
        g_pos[i] = r;
    }
    if (i == 0) g_rowptr[n] = E;
}
__global__ void csr_fill(const int* __restrict__ src, const int* __restrict__ dst, int E) {
    int e = blockIdx.x * blockDim.x + threadIdx.x;
    if (e >= E) return;
    int p = atomicAdd(&g_pos[dst[e]], 1);
    g_csr[p] = src[e];
}

// ---------------- fused per-node GAT: single edge sweep ----------------------
__global__ void gat_node(const float* __restrict__ bias, int n, int L) {
    int wid = (blockIdx.x * blockDim.x + threadIdx.x) >> 5;
    int l = threadIdx.x & 31;
    if (wid >= n) return;
    int rp = g_rowptr[wid], re = g_rowptr[wid + 1];

    float4 ad = *(const float4*)&g_al[wid * 4];
    float4 bd = *(const float4*)&g_ar[wid * 4];

    int h = l >> 3;
    int eo = l & 7;
    float arh  = sel4(bd, h);
    float gm   = fdec(g_gmaxenc[L][h]);
    float mh   = lrelu(gm + arh);
    float slgh = lrelu(sel4(ad, h) + arh);

    float zacc = 0.f;
    float4 acc = make_float4(0.f, 0.f, 0.f, 0.f);
    for (int j0 = rp; j0 < re; j0 += 8) {
        int cnt = re - j0;
        int s_l = wid;
        float e_l = 0.f;
        if (eo < cnt) {
            s_l = g_csr[j0 + eo];
            float als = __ldg(&g_al[s_l * 4 + h]);
            e_l = __expf(lrelu(als + arh) - mh);
            zacc += e_l;
        }
        int kmax = (cnt >= 8) ? 8 : cnt;
#pragma unroll 8
        for (int k = 0; k < kmax; k++) {
            int s = __shfl_sync(0xFFFFFFFFu, s_l, k);
            float ek = __shfl_sync(0xFFFFFFFFu, e_l, (l & 24) | k);
            uint2 u = *(const uint2*)&g_XWh[s * 128 + 4 * l];
            __half2 p0 = *(__half2*)&u.x, p1 = *(__half2*)&u.y;
            float2 f0 = __half22float2(p0), f1 = __half22float2(p1);
            acc.x += ek * f0.x; acc.y += ek * f0.y;
            acc.z += ek * f1.x; acc.w += ek * f1.y;
        }
    }
#pragma unroll
    for (int o = 1; o < 8; o <<= 1) zacc += __shfl_xor_sync(0xFFFFFFFFu, zacc, o);

    float eself = __expf(slgh - mh);
    float rz = 1.f / (zacc + eself);
    // self message from fp16 copy (g_XW removed)
    uint2 us = *(const uint2*)&g_XWh[wid * 128 + 4 * l];
    __half2 s0 = *(__half2*)&us.x, s1 = *(__half2*)&us.y;
    float2 fs0 = __half22float2(s0), fs1 = __half22float2(s1);
    acc.x = (acc.x + eself * fs0.x) * rz;
    acc.y = (acc.y + eself * fs0.y) * rz;
    acc.z = (acc.z + eself * fs1.x) * rz;
    acc.w = (acc.w + eself * fs1.y) * rz;
    float4 bv = *(const float4*)&bias[4 * l];
    acc.x += bv.x; acc.y += bv.y; acc.z += bv.z; acc.w += bv.w;
    stcs4(&g_H[wid * 128 + 4 * l], acc);   // streaming store: keep XWh hot
}

// ---------------- pooling / MLP ----------------------------------------------
__global__ void zero_pool() {
    int i = blockIdx.x * blockDim.x + threadIdx.x;
    if (i < NG * DF) g_pool[i] = 0.f;
    if (i < NG) g_cnt[i] = 0;
}
__global__ void pool_copy(const int* __restrict__ batch, float* __restrict__ outLast, int n) {
    int wid = (blockIdx.x * blockDim.x + threadIdx.x) >> 5;
    int l = threadIdx.x & 31;
    if (wid >= n) return;
    float4 v = __ldcs((const float4*)&g_H[wid * 128 + 4 * l]);
    v.x = fmaxf(v.x, 0.f); v.y = fmaxf(v.y, 0.f);
    v.z = fmaxf(v.z, 0.f); v.w = fmaxf(v.w, 0.f);
    stcs4(&outLast[wid * 128 + 4 * l], v);
    int b = batch[wid];
    redAdd4(&g_pool[b * 128 + 4 * l], v);
    if (l == 0) atomicAdd(&g_cnt[b], 1);
}
__global__ void mlp_kernel(const float* __restrict__ lin1w, const float* __restrict__ lin1b,
                           const float* __restrict__ lin2w, const float* __restrict__ lin2b,
                           float* __restrict__ out) {
    __shared__ float pr[128];
    __shared__ float gg[128];
    __shared__ float lo[NCLS];
    int gr = blockIdx.x;
    int c = threadIdx.x;
    float cnt = (float)max(g_cnt[gr], 1);
    pr[c] = g_pool[gr * 128 + c] / cnt;
    __syncthreads();
    float acc = lin1b[c];
#pragma unroll 8
    for (int k = 0; k < 128; k++) acc += pr[k] * lin1w[k * 128 + c];
    gg[c] = fmaxf(acc, 0.f);
    __syncthreads();
    if (c < NCLS) {
        float a = lin2b[c];
#pragma unroll 8
        for (int k = 0; k < 128; k++) a += gg[k] * lin2w[k * NCLS + c];
        lo[c] = a;
    }
    __syncthreads();
    if (c == 0) {
        float mx = lo[0];
#pragma unroll
        for (int j = 1; j < NCLS; j++) mx = fmaxf(mx, lo[j]);
        float s = 0.f;
#pragma unroll
        for (int j = 0; j < NCLS; j++) s += expf(lo[j] - mx);
        float lse = mx + logf(s);
#pragma unroll
        for (int j = 0; j < NCLS; j++) out[gr * NCLS + j] = lo[j] - lse;
    }
}

// ---------------- host launcher ---------------------------------------------
extern "C" void kernel_launch(void* const* d_in, const int* in_sizes, int n_in,
                              void* d_out, int out_size) {
    const float* x    = (const float*)d_in[0];
    const int*   eidx = (const int*)d_in[1];
    const int*   batch= (const int*)d_in[2];
    const float* W[3]  = { (const float*)d_in[3], (const float*)d_in[7],  (const float*)d_in[11] };
    const float* al[3] = { (const float*)d_in[4], (const float*)d_in[8],  (const float*)d_in[12] };
    const float* ar[3] = { (const float*)d_in[5], (const float*)d_in[9],  (const float*)d_in[13] };
    const float* bb[3] = { (const float*)d_in[6], (const float*)d_in[10], (const float*)d_in[14] };
    const float* lin1w = (const float*)d_in[15];
    const float* lin1b = (const float*)d_in[16];
    const float* lin2w = (const float*)d_in[17];
    const float* lin2b = (const float*)d_in[18];

    int n = in_sizes[0] / DF;
    int E = in_sizes[1] / 2;
    const int* src = eidx;
    const int* dst = eidx + E;

    float* out_logits = (float*)d_out;
    float* out_last   = (float*)d_out + NG * NCLS;

    float* hh; cudaGetSymbolAddress((void**)&hh, g_H);
    uint4* wh; cudaGetSymbolAddress((void**)&wh, g_WhT);
    uint4* wl; cudaGetSymbolAddress((void**)&wl, g_WlT);

    static int smemSet = 0;
    if (!smemSet) {
        cudaFuncSetAttribute(gemm_mma, cudaFuncAttributeMaxDynamicSharedMemorySize, GS_TOT);
        smemSet = 1;
    }

    int warpNB = (n * 32 + 255) / 256;
    int edgeTB = (E + 255) / 256;
    int nodeTB = (n + 255) / 256;
    int nScanB = (n + SCANB - 1) / SCANB;
    int gemmB  = (n + 63) / 64;

    prep_all<<<24, 256>>>(W[0], W[1], W[2]);                              // 0
    zero_deg<<<nodeTB, 256>>>(n);                                         // 1
    count_deg<<<edgeTB, 256>>>(dst, E);                                   // 2
    gemm_mma<<<gemmB, 256, GS_TOT>>>(x, wh, wl, al[0], ar[0], n, 0);      // 3 <- profiled
    almax<<<148, 256>>>(n, 0);                                            // 4
    scanA<<<nScanB, SCANB>>>(n);                                          // 5
    scanB<<<1, 256>>>(nScanB);                                            // 6
    scanC<<<nodeTB, 256>>>(n, E);                                         // 7
    csr_fill<<<edgeTB, 256>>>(src, dst, E);                               // 8
    gat_node<<<warpNB, 256>>>(bb[0], n, 0);                               // 9

    for (int L = 1; L < 3; L++) {
        gemm_mma<<<gemmB, 256, GS_TOT>>>(hh, wh + L * 2048, wl + L * 2048,
                                         al[L], ar[L], n, 1);
        almax<<<148, 256>>>(n, L);
        gat_node<<<warpNB, 256>>>(bb[L], n, L);
    }

    zero_pool<<<(NG * DF + 255) / 256, 256>>>();
    pool_copy<<<warpNB, 256>>>(batch, out_last, n);
    mlp_kernel<<<NG, 128>>>(lin1w, lin1b, lin2w, lin2b, out_logits);
}

// round 8
// speedup vs baseline: 2.8770x; 1.0286x over previous
#include <cuda_runtime.h>
#include <cuda_bf16.h>
#include <cuda_fp16.h>
#include <cstdint>
#include <math.h>

#define NND 100000
#define NE  1600000
#define DF  128
#define HEADS 4
#define NG  64
#define NCLS 10
#define NEG 0.2f
#define SCANB 512

// ---------------- scratch ----------------------------------------------------
__device__ __align__(16) __half g_XWh[NND * DF];   // fp16 x@W (messages+self)
__device__ __align__(16) float  g_H  [NND * DF];   // layer output fp32
__device__ __align__(16) float  g_al[NND * HEADS];
__device__ __align__(16) float  g_ar[NND * HEADS];
__device__ unsigned g_gmaxenc[3][HEADS];
__device__ int   g_deg[NND];
__device__ int   g_rowptr[NND + 1];
__device__ int   g_pos[NND];
__device__ int   g_bsum[(NND + SCANB - 1) / SCANB];
__device__ int   g_csr[NE];
__device__ float g_pool[NG * DF];
__device__ int   g_cnt[NG];
__device__ __align__(16) uint4 g_WhT[3][2048];
__device__ __align__(16) uint4 g_WlT[3][2048];

// ---------------- helpers ----------------------------------------------------
__device__ __forceinline__ float lrelu(float x) { return x > 0.f ? x : NEG * x; }
__device__ __forceinline__ unsigned fenc(float f) {
    unsigned u = __float_as_uint(f);
    return (u & 0x80000000u) ? ~u : (u | 0x80000000u);
}
__device__ __forceinline__ float fdec(unsigned u) {
    return (u & 0x80000000u) ? __uint_as_float(u & 0x7FFFFFFFu)
                             : __uint_as_float(~u);
}
__device__ __forceinline__ float sel4(float4 v, int h) {
    return h == 0 ? v.x : h == 1 ? v.y : h == 2 ? v.z : v.w;
}
__device__ __forceinline__ void redAdd4(float* p, float4 v) {
    asm volatile("red.global.add.v4.f32 [%0], {%1,%2,%3,%4};"
                 :: "l"(p), "f"(v.x), "f"(v.y), "f"(v.z), "f"(v.w) : "memory");
}
__device__ __forceinline__ void stcs4(float* p, float4 v) {
    asm volatile("st.global.cs.v4.f32 [%0], {%1,%2,%3,%4};"
                 :: "l"(p), "f"(v.x), "f"(v.y), "f"(v.z), "f"(v.w) : "memory");
}
__device__ __forceinline__ uint32_t smem_u32(const void* p) {
    uint32_t a;
    asm("{ .reg .u64 t; cvta.to.shared.u64 t, %1; cvt.u32.u64 %0, t; }" : "=r"(a) : "l"(p));
    return a;
}
__device__ __forceinline__ void ldm4(uint32_t& r0, uint32_t& r1, uint32_t& r2,
                                     uint32_t& r3, uint32_t addr) {
    asm volatile("ldmatrix.sync.aligned.m8n8.x4.shared.b16 {%0,%1,%2,%3}, [%4];"
                 : "=r"(r0), "=r"(r1), "=r"(r2), "=r"(r3) : "r"(addr));
}
__device__ __forceinline__ void mma16816(float* d, uint32_t a0, uint32_t a1,
                                         uint32_t a2, uint32_t a3,
                                         uint32_t b0, uint32_t b1) {
    asm volatile(
        "mma.sync.aligned.m16n8k16.row.col.f32.bf16.bf16.f32 "
        "{%0,%1,%2,%3}, {%4,%5,%6,%7}, {%8,%9}, {%0,%1,%2,%3};"
        : "+f"(d[0]), "+f"(d[1]), "+f"(d[2]), "+f"(d[3])
        : "r"(a0), "r"(a1), "r"(a2), "r"(a3), "r"(b0), "r"(b1));
}

union B16x8 { __nv_bfloat16 b[8]; uint4 u; };

// ---------------- weight prep (all layers, one launch) ------------------------
__global__ void prep_all(const float* __restrict__ W0, const float* __restrict__ W1,
                         const float* __restrict__ W2) {
    int L = blockIdx.x >> 3;
    int i = (blockIdx.x & 7) * 256 + threadIdx.x;
    const float* W = (L == 0) ? W0 : (L == 1) ? W1 : W2;
    int nn = i >> 4, c = i & 15;
    B16x8 H, Lo;
#pragma unroll
    for (int j = 0; j < 8; j++) {
        float wv = W[(c * 8 + j) * 128 + nn];
        __nv_bfloat16 h = __float2bfloat16(wv);
        H.b[j] = h;
        Lo.b[j] = __float2bfloat16(wv - __bfloat162float(h));
    }
    int off = nn * 16 + (c ^ (nn & 7));
    g_WhT[L][off] = H.u;
    g_WlT[L][off] = Lo.u;
}

// ---------------- HMMA GEMM (256 thr) + fused al/ar + fused almax ------------
#define GS_AH 0
#define GS_AL 16384
#define GS_WH 32768
#define GS_WL 65536
#define GS_TOT 98304

__global__ void __launch_bounds__(256, 2) gemm_mma(
    const float* __restrict__ A, const uint4* __restrict__ WhT,
    const uint4* __restrict__ WlT,
    const float* __restrict__ attl, const float* __restrict__ attr,
    int n, int reluIn, int Lidx) {
    extern __shared__ char smem[];
    __shared__ unsigned smax[4];
    uint32_t sb = smem_u32(smem);
    int tid = threadIdx.x, w = tid >> 5, l = tid & 31;
    int rg = w & 3, ch = w >> 2;
    int row0 = blockIdx.x * 64;

    {
        uint4* wh = (uint4*)(smem + GS_WH);
        uint4* wl = (uint4*)(smem + GS_WL);
        for (int i = tid; i < 2048; i += 256) { wh[i] = WhT[i]; wl[i] = WlT[i]; }
    }
    for (int i = tid; i < 1024; i += 256) {
        int r = i >> 4, c = i & 15;
        int row = row0 + r;
        float4 v0 = make_float4(0.f, 0.f, 0.f, 0.f), v1 = v0;
        if (row < n) {
            v0 = __ldcs((const float4*)&A[row * 128 + c * 8]);
            v1 = __ldcs((const float4*)&A[row * 128 + c * 8 + 4]);
        }
        if (reluIn) {
            v0.x = fmaxf(v0.x, 0.f); v0.y = fmaxf(v0.y, 0.f);
            v0.z = fmaxf(v0.z, 0.f); v0.w = fmaxf(v0.w, 0.f);
            v1.x = fmaxf(v1.x, 0.f); v1.y = fmaxf(v1.y, 0.f);
            v1.z = fmaxf(v1.z, 0.f); v1.w = fmaxf(v1.w, 0.f);
        }
        B16x8 H, L;
        float vv[8] = { v0.x, v0.y, v0.z, v0.w, v1.x, v1.y, v1.z, v1.w };
#pragma unroll
        for (int j = 0; j < 8; j++) {
            __nv_bfloat16 h = __float2bfloat16(vv[j]);
            H.b[j] = h;
            L.b[j] = __float2bfloat16(vv[j] - __bfloat162float(h));
        }
        int off = r * 256 + ((c ^ (r & 7)) << 4);
        *(uint4*)(smem + GS_AH + off) = H.u;
        *(uint4*)(smem + GS_AL + off) = L.u;
    }
    __syncthreads();

    int aRow = rg * 16 + ((l >> 3) & 1) * 8 + (l & 7);
    int aChk = (l >> 4) & 1;
    uint32_t aBase = sb + GS_AH + aRow * 256;
    int aXor = aRow & 7;
    int bRowL = ((l >> 4) & 1) * 8 + (l & 7);
    int bChk = (l >> 3) & 1;

    float acc[32];
#pragma unroll
    for (int i = 0; i < 32; i++) acc[i] = 0.f;

#pragma unroll
    for (int ks = 0; ks < 8; ks++) {
        uint32_t ah0, ah1, ah2, ah3, al0, al1, al2, al3;
        uint32_t aOff = (((2 * ks + aChk) ^ aXor) << 4);
        ldm4(ah0, ah1, ah2, ah3, aBase + aOff);
        ldm4(al0, al1, al2, al3, aBase + 16384 + aOff);
#pragma unroll
        for (int p = 0; p < 4; p++) {
            int bRow = ch * 64 + p * 16 + bRowL;
            uint32_t bAddr = sb + GS_WH + bRow * 256
                           + (((2 * ks + bChk) ^ (bRow & 7)) << 4);
            uint32_t bh0, bh1, bh2, bh3, bl0, bl1, bl2, bl3;
            ldm4(bh0, bh1, bh2, bh3, bAddr);
            ldm4(bl0, bl1, bl2, bl3, bAddr + 32768);
            float* d0 = &acc[(2 * p) * 4];
            float* d1 = &acc[(2 * p + 1) * 4];
            mma16816(d0, ah0, ah1, ah2, ah3, bh0, bh1);
            mma16816(d0, al0, al1, al2, al3, bh0, bh1);
            mma16816(d0, ah0, ah1, ah2, ah3, bl0, bl1);
            mma16816(d1, ah0, ah1, ah2, ah3, bh2, bh3);
            mma16816(d1, al0, al1, al2, al3, bh2, bh3);
            mma16816(d1, ah0, ah1, ah2, ah3, bl2, bl3);
        }
    }
    __syncthreads();

    float* Cs = (float*)smem;              // 64 x 132 floats
    float* att = (float*)(smem + GS_WL);
    att[tid] = (tid < 128) ? attl[tid] : attr[tid - 128];
    if (tid < 4) smax[tid] = 0u;
    {
        int r1 = rg * 16 + (l >> 2);
#pragma unroll
        for (int nt = 0; nt < 8; nt++) {
            int p = nt >> 1, t = nt & 1;
            int col = ch * 64 + p * 16 + t * 8 + (l & 3) * 2;
            float* d = &acc[nt * 4];
            Cs[r1 * 132 + col]           = d[0];
            Cs[r1 * 132 + col + 1]       = d[1];
            Cs[(r1 + 8) * 132 + col]     = d[2];
            Cs[(r1 + 8) * 132 + col + 1] = d[3];
        }
    }
    __syncthreads();

    // fp16 XWh store
    for (int i = tid; i < 2048; i += 256) {
        int r = i >> 5, c4 = i & 31;
        int row = row0 + r;
        if (row < n) {
            float4 v = *(float4*)&Cs[r * 132 + c4 * 4];
            __half2 h0 = __floats2half2_rn(v.x, v.y);
            __half2 h1 = __floats2half2_rn(v.z, v.w);
            uint2 u;
            u.x = *(uint32_t*)&h0; u.y = *(uint32_t*)&h1;
            *(uint2*)&g_XWh[row * 128 + c4 * 4] = u;
        }
    }
    // al / ar dots + block-local al max
    if (tid < 128) {
        int half_ = tid >> 6;
        int r = tid & 63;
        int row = row0 + r;
        if (row < n) {
            const float* av = att + half_ * 128;
            float d0 = 0.f, d1 = 0.f, d2 = 0.f, d3 = 0.f;
#pragma unroll 8
            for (int c = 0; c < 32; c++) {
                d0 += Cs[r * 132 + c]      * av[c];
                d1 += Cs[r * 132 + 32 + c] * av[32 + c];
                d2 += Cs[r * 132 + 64 + c] * av[64 + c];
                d3 += Cs[r * 132 + 96 + c] * av[96 + c];
            }
            float* dst = half_ ? g_ar : g_al;
            *(float4*)&dst[row * 4] = make_float4(d0, d1, d2, d3);
            if (half_ == 0) {
                atomicMax(&smax[0], fenc(d0));
                atomicMax(&smax[1], fenc(d1));
                atomicMax(&smax[2], fenc(d2));
                atomicMax(&smax[3], fenc(d3));
            }
        }
    }
    __syncthreads();
    if (tid < 4) atomicMax(&g_gmaxenc[Lidx][tid], smax[tid]);
}

// ---------------- CSR build --------------------------------------------------
__global__ void zero_deg(int n) {
    int i = blockIdx.x * blockDim.x + threadIdx.x;
    if (i < n) g_deg[i] = 0;
    if (i < 12) ((unsigned*)g_gmaxenc)[i] = 0u;
}
__global__ void count_deg(const int* __restrict__ dst, int E) {
    int e = blockIdx.x * blockDim.x + threadIdx.x;
    if (e < E) atomicAdd(&g_deg[dst[e]], 1);
}
__global__ void scanA(int n) {
    __shared__ int sh[SCANB];
    int i = blockIdx.x * SCANB + threadIdx.x;
    int v = (i < n) ? g_deg[i] : 0;
    sh[threadIdx.x] = v;
    __syncthreads();
    for (int off = 1; off < SCANB; off <<= 1) {
        int t = (threadIdx.x >= off) ? sh[threadIdx.x - off] : 0;
        __syncthreads();
        sh[threadIdx.x] += t;
        __syncthreads();
    }
    if (i < n) g_rowptr[i] = sh[threadIdx.x] - v;
    if (threadIdx.x == SCANB - 1) g_bsum[blockIdx.x] = sh[SCANB - 1];
}
__global__ void scanB(int nb) {
    __shared__ int sh[256];
    int v = (threadIdx.x < nb) ? g_bsum[threadIdx.x] : 0;
    sh[threadIdx.x] = v;
    __syncthreads();
    for (int off = 1; off < 256; off <<= 1) {
        int t = (threadIdx.x >= off) ? sh[threadIdx.x - off] : 0;
        __syncthreads();
        sh[threadIdx.x] += t;
        __syncthreads();
    }
    if (threadIdx.x < nb) g_bsum[threadIdx.x] = sh[threadIdx.x] - v;
}
__global__ void scanC(int n, int E) {
    int i = blockIdx.x * blockDim.x + threadIdx.x;
    if (i < n) {
        int r = g_rowptr[i] + g_bsum[i / SCANB];
        g_rowptr[i] = r;
        g_pos[i] = r;
    }
    if (i == 0) g_rowptr[n] = E;
}
__global__ void csr_fill(const int* __restrict__ src, const int* __restrict__ dst, int E) {
    int e = blockIdx.x * blockDim.x + threadIdx.x;
    if (e >= E) return;
    int p = atomicAdd(&g_pos[dst[e]], 1);
    g_csr[p] = src[e];
}

// ---------------- fused per-node GAT: pipelined single sweep -----------------
__global__ void gat_node(const float* __restrict__ bias, int n, int L) {
    int wid = (blockIdx.x * blockDim.x + threadIdx.x) >> 5;
    int l = threadIdx.x & 31;
    if (wid >= n) return;
    int rp = g_rowptr[wid], re = g_rowptr[wid + 1];

    float4 ad = *(const float4*)&g_al[wid * 4];
    float4 bd = *(const float4*)&g_ar[wid * 4];

    int h = l >> 3;
    int eo = l & 7;
    float arh  = sel4(bd, h);
    float mh   = lrelu(fdec(g_gmaxenc[L][h]) + arh);
    float slgh = lrelu(sel4(ad, h) + arh);

    float zacc = 0.f;
    float4 acc = make_float4(0.f, 0.f, 0.f, 0.f);

    // prologue: load batch-0 csr index + al value
    int s_cur = wid; float als_cur = 0.f;
    if (rp + eo < re) {
        s_cur = g_csr[rp + eo];
        als_cur = __ldg(&g_al[s_cur * 4 + h]);
    }
    for (int j0 = rp; j0 < re; j0 += 8) {
        // prefetch next batch's index + al gather (latency hidden under rows)
        int s_nxt = wid; float als_nxt = 0.f;
        if (j0 + 8 + eo < re) {
            s_nxt = g_csr[j0 + 8 + eo];
            als_nxt = __ldg(&g_al[s_nxt * 4 + h]);
        }
        float e_l = 0.f;
        if (j0 + eo < re) {
            e_l = __expf(lrelu(als_cur + arh) - mh);
            zacc += e_l;
        }
        int kmax = min(8, re - j0);
#pragma unroll 8
        for (int k = 0; k < kmax; k++) {
            int s = __shfl_sync(0xFFFFFFFFu, s_cur, k);
            float ek = __shfl_sync(0xFFFFFFFFu, e_l, (l & 24) | k);
            uint2 u = *(const uint2*)&g_XWh[s * 128 + 4 * l];
            __half2 p0 = *(__half2*)&u.x, p1 = *(__half2*)&u.y;
            float2 f0 = __half22float2(p0), f1 = __half22float2(p1);
            acc.x += ek * f0.x; acc.y += ek * f0.y;
            acc.z += ek * f1.x; acc.w += ek * f1.y;
        }
        s_cur = s_nxt; als_cur = als_nxt;
    }
#pragma unroll
    for (int o = 1; o < 8; o <<= 1) zacc += __shfl_xor_sync(0xFFFFFFFFu, zacc, o);

    float eself = __expf(slgh - mh);
    float rz = 1.f / (zacc + eself);
    uint2 us = *(const uint2*)&g_XWh[wid * 128 + 4 * l];
    __half2 s0 = *(__half2*)&us.x, s1 = *(__half2*)&us.y;
    float2 fs0 = __half22float2(s0), fs1 = __half22float2(s1);
    acc.x = (acc.x + eself * fs0.x) * rz;
    acc.y = (acc.y + eself * fs0.y) * rz;
    acc.z = (acc.z + eself * fs1.x) * rz;
    acc.w = (acc.w + eself * fs1.y) * rz;
    float4 bv = *(const float4*)&bias[4 * l];
    acc.x += bv.x; acc.y += bv.y; acc.z += bv.z; acc.w += bv.w;
    stcs4(&g_H[wid * 128 + 4 * l], acc);
}

// ---------------- pooling / MLP ----------------------------------------------
__global__ void zero_pool() {
    int i = blockIdx.x * blockDim.x + threadIdx.x;
    if (i < NG * DF) g_pool[i] = 0.f;
    if (i < NG) g_cnt[i] = 0;
}
__global__ void pool_copy(const int* __restrict__ batch, float* __restrict__ outLast, int n) {
    int wid = (blockIdx.x * blockDim.x + threadIdx.x) >> 5;
    int l = threadIdx.x & 31;
    if (wid >= n) return;
    float4 v = __ldcs((const float4*)&g_H[wid * 128 + 4 * l]);
    v.x = fmaxf(v.x, 0.f); v.y = fmaxf(v.y, 0.f);
    v.z = fmaxf(v.z, 0.f); v.w = fmaxf(v.w, 0.f);
    stcs4(&outLast[wid * 128 + 4 * l], v);
    int b = batch[wid];
    redAdd4(&g_pool[b * 128 + 4 * l], v);
    if (l == 0) atomicAdd(&g_cnt[b], 1);
}
__global__ void mlp_kernel(const float* __restrict__ lin1w, const float* __restrict__ lin1b,
                           const float* __restrict__ lin2w, const float* __restrict__ lin2b,
                           float* __restrict__ out) {
    __shared__ float pr[128];
    __shared__ float gg[128];
    __shared__ float lo[NCLS];
    int gr = blockIdx.x;
    int c = threadIdx.x;
    float cnt = (float)max(g_cnt[gr], 1);
    pr[c] = g_pool[gr * 128 + c] / cnt;
    __syncthreads();
    float acc = lin1b[c];
#pragma unroll 8
    for (int k = 0; k < 128; k++) acc += pr[k] * lin1w[k * 128 + c];
    gg[c] = fmaxf(acc, 0.f);
    __syncthreads();
    if (c < NCLS) {
        float a = lin2b[c];
#pragma unroll 8
        for (int k = 0; k < 128; k++) a += gg[k] * lin2w[k * NCLS + c];
        lo[c] = a;
    }
    __syncthreads();
    if (c == 0) {
        float mx = lo[0];
#pragma unroll
        for (int j = 1; j < NCLS; j++) mx = fmaxf(mx, lo[j]);
        float s = 0.f;
#pragma unroll
        for (int j = 0; j < NCLS; j++) s += expf(lo[j] - mx);
        float lse = mx + logf(s);
#pragma unroll
        for (int j = 0; j < NCLS; j++) out[gr * NCLS + j] = lo[j] - lse;
    }
}

// ---------------- host launcher ---------------------------------------------
extern "C" void kernel_launch(void* const* d_in, const int* in_sizes, int n_in,
                              void* d_out, int out_size) {
    const float* x    = (const float*)d_in[0];
    const int*   eidx = (const int*)d_in[1];
    const int*   batch= (const int*)d_in[2];
    const float* W[3]  = { (const float*)d_in[3], (const float*)d_in[7],  (const float*)d_in[11] };
    const float* al[3] = { (const float*)d_in[4], (const float*)d_in[8],  (const float*)d_in[12] };
    const float* ar[3] = { (const float*)d_in[5], (const float*)d_in[9],  (const float*)d_in[13] };
    const float* bb[3] = { (const float*)d_in[6], (const float*)d_in[10], (const float*)d_in[14] };
    const float* lin1w = (const float*)d_in[15];
    const float* lin1b = (const float*)d_in[16];
    const float* lin2w = (const float*)d_in[17];
    const float* lin2b = (const float*)d_in[18];

    int n = in_sizes[0] / DF;
    int E = in_sizes[1] / 2;
    const int* src = eidx;
    const int* dst = eidx + E;

    float* out_logits = (float*)d_out;
    float* out_last   = (float*)d_out + NG * NCLS;

    float* hh; cudaGetSymbolAddress((void**)&hh, g_H);
    uint4* wh; cudaGetSymbolAddress((void**)&wh, g_WhT);
    uint4* wl; cudaGetSymbolAddress((void**)&wl, g_WlT);

    static int smemSet = 0;
    if (!smemSet) {
        cudaFuncSetAttribute(gemm_mma, cudaFuncAttributeMaxDynamicSharedMemorySize, GS_TOT);
        smemSet = 1;
    }

    int warpNB = (n * 32 + 255) / 256;
    int edgeTB = (E + 255) / 256;
    int nodeTB = (n + 255) / 256;
    int nScanB = (n + SCANB - 1) / SCANB;
    int gemmB  = (n + 63) / 64;

    prep_all<<<24, 256>>>(W[0], W[1], W[2]);                              // 0
    zero_deg<<<nodeTB, 256>>>(n);                                         // 1
    count_deg<<<edgeTB, 256>>>(dst, E);                                   // 2
    gemm_mma<<<gemmB, 256, GS_TOT>>>(x, wh, wl, al[0], ar[0], n, 0, 0);   // 3 <- profiled
    scanA<<<nScanB, SCANB>>>(n);                                          // 4
    scanB<<<1, 256>>>(nScanB);                                            // 5
    scanC<<<nodeTB, 256>>>(n, E);                                         // 6
    csr_fill<<<edgeTB, 256>>>(src, dst, E);                               // 7
    gat_node<<<warpNB, 256>>>(bb[0], n, 0);                               // 8

    for (int L = 1; L < 3; L++) {
        gemm_mma<<<gemmB, 256, GS_TOT>>>(hh, wh + L * 2048, wl + L * 2048,
                                         al[L], ar[L], n, 1, L);
        gat_node<<<warpNB, 256>>>(bb[L], n, L);
    }

    zero_pool<<<(NG * DF + 255) / 256, 256>>>();
    pool_copy<<<warpNB, 256>>>(batch, out_last, n);
    mlp_kernel<<<NG, 128>>>(lin1w, lin1b, lin2w, lin2b, out_logits);
}

// round 9
// speedup vs baseline: 3.2189x; 1.1189x over previous
#include <cuda_runtime.h>
#include <cuda_bf16.h>
#include <cuda_fp16.h>
#include <cstdint>
#include <math.h>

#define NND 100000
#define NE  1600000
#define DF  128
#define HEADS 4
#define NG  64
#define NCLS 10
#define NEG 0.2f
#define SCANB 512

// ---------------- scratch ----------------------------------------------------
__device__ __align__(16) __half g_XWh[NND * DF];   // fp16 x@W (messages+self)
__device__ __align__(16) float  g_H  [NND * DF];   // layer output fp32
__device__ __align__(16) float  g_al[NND * HEADS];
__device__ __align__(16) float  g_ar[NND * HEADS];
__device__ unsigned g_gmaxenc[3][HEADS];
__device__ int   g_deg[NND];
__device__ int   g_rowptr[NND + 1];
__device__ int   g_pos[NND];
__device__ int   g_bsum[(NND + SCANB - 1) / SCANB];
__device__ int   g_csr[NE];
__device__ float g_pool[NG * DF];
__device__ int   g_cnt[NG];
__device__ __align__(16) uint4 g_WfT[3][2048];     // fp16 W^T swizzled

// ---------------- helpers ----------------------------------------------------
__device__ __forceinline__ float lrelu(float x) { return x > 0.f ? x : NEG * x; }
__device__ __forceinline__ unsigned fenc(float f) {
    unsigned u = __float_as_uint(f);
    return (u & 0x80000000u) ? ~u : (u | 0x80000000u);
}
__device__ __forceinline__ float fdec(unsigned u) {
    return (u & 0x80000000u) ? __uint_as_float(u & 0x7FFFFFFFu)
                             : __uint_as_float(~u);
}
__device__ __forceinline__ float sel4(float4 v, int h) {
    return h == 0 ? v.x : h == 1 ? v.y : h == 2 ? v.z : v.w;
}
__device__ __forceinline__ void redAdd4(float* p, float4 v) {
    asm volatile("red.global.add.v4.f32 [%0], {%1,%2,%3,%4};"
                 :: "l"(p), "f"(v.x), "f"(v.y), "f"(v.z), "f"(v.w) : "memory");
}
__device__ __forceinline__ void stcs4(float* p, float4 v) {
    asm volatile("st.global.cs.v4.f32 [%0], {%1,%2,%3,%4};"
                 :: "l"(p), "f"(v.x), "f"(v.y), "f"(v.z), "f"(v.w) : "memory");
}
__device__ __forceinline__ uint32_t smem_u32(const void* p) {
    uint32_t a;
    asm("{ .reg .u64 t; cvta.to.shared.u64 t, %1; cvt.u32.u64 %0, t; }" : "=r"(a) : "l"(p));
    return a;
}
__device__ __forceinline__ void ldm4(uint32_t& r0, uint32_t& r1, uint32_t& r2,
                                     uint32_t& r3, uint32_t addr) {
    asm volatile("ldmatrix.sync.aligned.m8n8.x4.shared.b16 {%0,%1,%2,%3}, [%4];"
                 : "=r"(r0), "=r"(r1), "=r"(r2), "=r"(r3) : "r"(addr));
}
__device__ __forceinline__ void mma16816f(float* d, uint32_t a0, uint32_t a1,
                                          uint32_t a2, uint32_t a3,
                                          uint32_t b0, uint32_t b1) {
    asm volatile(
        "mma.sync.aligned.m16n8k16.row.col.f32.f16.f16.f32 "
        "{%0,%1,%2,%3}, {%4,%5,%6,%7}, {%8,%9}, {%0,%1,%2,%3};"
        : "+f"(d[0]), "+f"(d[1]), "+f"(d[2]), "+f"(d[3])
        : "r"(a0), "r"(a1), "r"(a2), "r"(a3), "r"(b0), "r"(b1));
}

union H16x8 { __half h[8]; uint4 u; };

// ---------------- weight prep: fp32 W -> fp16 W^T swizzled --------------------
__global__ void prep_all(const float* __restrict__ W0, const float* __restrict__ W1,
                         const float* __restrict__ W2) {
    int L = blockIdx.x >> 3;
    int i = (blockIdx.x & 7) * 256 + threadIdx.x;   // 0..2047
    const float* W = (L == 0) ? W0 : (L == 1) ? W1 : W2;
    int nn = i >> 4, c = i & 15;
    H16x8 F;
#pragma unroll
    for (int j = 0; j < 8; j++)
        F.h[j] = __float2half(W[(c * 8 + j) * 128 + nn]);
    g_WfT[L][nn * 16 + (c ^ (nn & 7))] = F.u;
}

// ---------------- fp16 HMMA GEMM + fused al/ar + almax -----------------------
#define GS_A   0
#define GS_W   16384
#define GS_ATT 49152
#define GS_TOT 50176

__global__ void __launch_bounds__(256, 3) gemm_mma(
    const float* __restrict__ A, const uint4* __restrict__ WfT,
    const float* __restrict__ attl, const float* __restrict__ attr,
    int n, int reluIn, int Lidx) {
    extern __shared__ char smem[];
    __shared__ unsigned smax[4];
    uint32_t sb = smem_u32(smem);
    int tid = threadIdx.x, w = tid >> 5, l = tid & 31;
    int rg = w & 3, ch = w >> 2;
    int row0 = blockIdx.x * 64;

    {
        uint4* wf = (uint4*)(smem + GS_W);
        for (int i = tid; i < 2048; i += 256) wf[i] = WfT[i];
    }
    // A tile: fp32 -> fp16, swizzled (64 rows x 256 B)
    for (int i = tid; i < 1024; i += 256) {
        int r = i >> 4, c = i & 15;
        int row = row0 + r;
        float4 v0 = make_float4(0.f, 0.f, 0.f, 0.f), v1 = v0;
        if (row < n) {
            v0 = __ldcs((const float4*)&A[row * 128 + c * 8]);
            v1 = __ldcs((const float4*)&A[row * 128 + c * 8 + 4]);
        }
        if (reluIn) {
            v0.x = fmaxf(v0.x, 0.f); v0.y = fmaxf(v0.y, 0.f);
            v0.z = fmaxf(v0.z, 0.f); v0.w = fmaxf(v0.w, 0.f);
            v1.x = fmaxf(v1.x, 0.f); v1.y = fmaxf(v1.y, 0.f);
            v1.z = fmaxf(v1.z, 0.f); v1.w = fmaxf(v1.w, 0.f);
        }
        H16x8 F;
        F.h[0] = __float2half(v0.x); F.h[1] = __float2half(v0.y);
        F.h[2] = __float2half(v0.z); F.h[3] = __float2half(v0.w);
        F.h[4] = __float2half(v1.x); F.h[5] = __float2half(v1.y);
        F.h[6] = __float2half(v1.z); F.h[7] = __float2half(v1.w);
        *(uint4*)(smem + GS_A + r * 256 + ((c ^ (r & 7)) << 4)) = F.u;
    }
    __syncthreads();

    int aRow = rg * 16 + ((l >> 3) & 1) * 8 + (l & 7);
    int aChk = (l >> 4) & 1;
    uint32_t aBase = sb + GS_A + aRow * 256;
    int aXor = aRow & 7;
    int bRowL = ((l >> 4) & 1) * 8 + (l & 7);
    int bChk = (l >> 3) & 1;

    float acc[32];
#pragma unroll
    for (int i = 0; i < 32; i++) acc[i] = 0.f;

#pragma unroll
    for (int ks = 0; ks < 8; ks++) {
        uint32_t a0, a1, a2, a3;
        ldm4(a0, a1, a2, a3, aBase + (((2 * ks + aChk) ^ aXor) << 4));
#pragma unroll
        for (int p = 0; p < 4; p++) {
            int bRow = ch * 64 + p * 16 + bRowL;
            uint32_t bAddr = sb + GS_W + bRow * 256
                           + (((2 * ks + bChk) ^ (bRow & 7)) << 4);
            uint32_t b0, b1, b2, b3;
            ldm4(b0, b1, b2, b3, bAddr);
            mma16816f(&acc[(2 * p) * 4],     a0, a1, a2, a3, b0, b1);
            mma16816f(&acc[(2 * p + 1) * 4], a0, a1, a2, a3, b2, b3);
        }
    }
    __syncthreads();

    float* Cs = (float*)smem;              // 64 x 132 floats (A/W regions dead)
    float* att = (float*)(smem + GS_ATT);
    att[tid] = (tid < 128) ? attl[tid] : attr[tid - 128];
    if (tid < 4) smax[tid] = 0u;
    {
        int r1 = rg * 16 + (l >> 2);
#pragma unroll
        for (int nt = 0; nt < 8; nt++) {
            int p = nt >> 1, t = nt & 1;
            int col = ch * 64 + p * 16 + t * 8 + (l & 3) * 2;
            float* d = &acc[nt * 4];
            Cs[r1 * 132 + col]           = d[0];
            Cs[r1 * 132 + col + 1]       = d[1];
            Cs[(r1 + 8) * 132 + col]     = d[2];
            Cs[(r1 + 8) * 132 + col + 1] = d[3];
        }
    }
    __syncthreads();

    // fp16 XWh store
    for (int i = tid; i < 2048; i += 256) {
        int r = i >> 5, c4 = i & 31;
        int row = row0 + r;
        if (row < n) {
            float4 v = *(float4*)&Cs[r * 132 + c4 * 4];
            __half2 h0 = __floats2half2_rn(v.x, v.y);
            __half2 h1 = __floats2half2_rn(v.z, v.w);
            uint2 u;
            u.x = *(uint32_t*)&h0; u.y = *(uint32_t*)&h1;
            *(uint2*)&g_XWh[row * 128 + c4 * 4] = u;
        }
    }
    // al / ar dots + block-local al max
    if (tid < 128) {
        int half_ = tid >> 6;
        int r = tid & 63;
        int row = row0 + r;
        if (row < n) {
            const float* av = att + half_ * 128;
            float d0 = 0.f, d1 = 0.f, d2 = 0.f, d3 = 0.f;
#pragma unroll 8
            for (int c = 0; c < 32; c++) {
                d0 += Cs[r * 132 + c]      * av[c];
                d1 += Cs[r * 132 + 32 + c] * av[32 + c];
                d2 += Cs[r * 132 + 64 + c] * av[64 + c];
                d3 += Cs[r * 132 + 96 + c] * av[96 + c];
            }
            float* dst = half_ ? g_ar : g_al;
            *(float4*)&dst[row * 4] = make_float4(d0, d1, d2, d3);
            if (half_ == 0) {
                atomicMax(&smax[0], fenc(d0));
                atomicMax(&smax[1], fenc(d1));
                atomicMax(&smax[2], fenc(d2));
                atomicMax(&smax[3], fenc(d3));
            }
        }
    }
    __syncthreads();
    if (tid < 4) atomicMax(&g_gmaxenc[Lidx][tid], smax[tid]);
}

// ---------------- CSR build --------------------------------------------------
__global__ void zero_deg(int n) {
    int i = blockIdx.x * blockDim.x + threadIdx.x;
    if (i < n) g_deg[i] = 0;
    if (i < 12) ((unsigned*)g_gmaxenc)[i] = 0u;
}
__global__ void count_deg(const int* __restrict__ dst, int E) {
    int e = blockIdx.x * blockDim.x + threadIdx.x;
    if (e < E) atomicAdd(&g_deg[dst[e]], 1);
}
__global__ void scanA(int n) {
    __shared__ int sh[SCANB];
    int i = blockIdx.x * SCANB + threadIdx.x;
    int v = (i < n) ? g_deg[i] : 0;
    sh[threadIdx.x] = v;
    __syncthreads();
    for (int off = 1; off < SCANB; off <<= 1) {
        int t = (threadIdx.x >= off) ? sh[threadIdx.x - off] : 0;
        __syncthreads();
        sh[threadIdx.x] += t;
        __syncthreads();
    }
    if (i < n) g_rowptr[i] = sh[threadIdx.x] - v;
    if (threadIdx.x == SCANB - 1) g_bsum[blockIdx.x] = sh[SCANB - 1];
}
__global__ void scanB(int nb) {
    __shared__ int sh[256];
    int v = (threadIdx.x < nb) ? g_bsum[threadIdx.x] : 0;
    sh[threadIdx.x] = v;
    __syncthreads();
    for (int off = 1; off < 256; off <<= 1) {
        int t = (threadIdx.x >= off) ? sh[threadIdx.x - off] : 0;
        __syncthreads();
        sh[threadIdx.x] += t;
        __syncthreads();
    }
    if (threadIdx.x < nb) g_bsum[threadIdx.x] = sh[threadIdx.x] - v;
}
__global__ void scanC(int n, int E) {
    int i = blockIdx.x * blockDim.x + threadIdx.x;
    if (i < n) {
        int r = g_rowptr[i] + g_bsum[i / SCANB];
        g_rowptr[i] = r;
        g_pos[i] = r;
    }
    if (i == 0) g_rowptr[n] = E;
}
__global__ void csr_fill(const int* __restrict__ src, const int* __restrict__ dst, int E) {
    int e = blockIdx.x * blockDim.x + threadIdx.x;
    if (e >= E) return;
    int p = atomicAdd(&g_pos[dst[e]], 1);
    g_csr[p] = src[e];
}

// ---------------- fused per-node GAT: pipelined single sweep -----------------
__global__ void gat_node(const float* __restrict__ bias, int n, int L) {
    int wid = (blockIdx.x * blockDim.x + threadIdx.x) >> 5;
    int l = threadIdx.x & 31;
    if (wid >= n) return;
    int rp = g_rowptr[wid], re = g_rowptr[wid + 1];

    float4 ad = *(const float4*)&g_al[wid * 4];
    float4 bd = *(const float4*)&g_ar[wid * 4];

    int h = l >> 3;
    int eo = l & 7;
    float arh  = sel4(bd, h);
    float mh   = lrelu(fdec(g_gmaxenc[L][h]) + arh);
    float slgh = lrelu(sel4(ad, h) + arh);

    float zacc = 0.f;
    float4 acc = make_float4(0.f, 0.f, 0.f, 0.f);

    int s_cur = wid; float als_cur = 0.f;
    if (rp + eo < re) {
        s_cur = g_csr[rp + eo];
        als_cur = __ldg(&g_al[s_cur * 4 + h]);
    }
    for (int j0 = rp; j0 < re; j0 += 8) {
        int s_nxt = wid; float als_nxt = 0.f;
        if (j0 + 8 + eo < re) {
            s_nxt = g_csr[j0 + 8 + eo];
            als_nxt = __ldg(&g_al[s_nxt * 4 + h]);
        }
        float e_l = 0.f;
        if (j0 + eo < re) {
            e_l = __expf(lrelu(als_cur + arh) - mh);
            zacc += e_l;
        }
        int kmax = min(8, re - j0);
#pragma unroll 8
        for (int k = 0; k < kmax; k++) {
            int s = __shfl_sync(0xFFFFFFFFu, s_cur, k);
            float ek = __shfl_sync(0xFFFFFFFFu, e_l, (l & 24) | k);
            uint2 u = *(const uint2*)&g_XWh[s * 128 + 4 * l];
            __half2 p0 = *(__half2*)&u.x, p1 = *(__half2*)&u.y;
            float2 f0 = __half22float2(p0), f1 = __half22float2(p1);
            acc.x += ek * f0.x; acc.y += ek * f0.y;
            acc.z += ek * f1.x; acc.w += ek * f1.y;
        }
        s_cur = s_nxt; als_cur = als_nxt;
    }
#pragma unroll
    for (int o = 1; o < 8; o <<= 1) zacc += __shfl_xor_sync(0xFFFFFFFFu, zacc, o);

    float eself = __expf(slgh - mh);
    float rz = 1.f / (zacc + eself);
    uint2 us = *(const uint2*)&g_XWh[wid * 128 + 4 * l];
    __half2 s0 = *(__half2*)&us.x, s1 = *(__half2*)&us.y;
    float2 fs0 = __half22float2(s0), fs1 = __half22float2(s1);
    acc.x = (acc.x + eself * fs0.x) * rz;
    acc.y = (acc.y + eself * fs0.y) * rz;
    acc.z = (acc.z + eself * fs1.x) * rz;
    acc.w = (acc.w + eself * fs1.y) * rz;
    float4 bv = *(const float4*)&bias[4 * l];
    acc.x += bv.x; acc.y += bv.y; acc.z += bv.z; acc.w += bv.w;
    stcs4(&g_H[wid * 128 + 4 * l], acc);
}

// ---------------- pooling / MLP ----------------------------------------------
__global__ void zero_pool() {
    int i = blockIdx.x * blockDim.x + threadIdx.x;
    if (i < NG * DF) g_pool[i] = 0.f;
    if (i < NG) g_cnt[i] = 0;
}
__global__ void pool_copy(const int* __restrict__ batch, float* __restrict__ outLast, int n) {
    int wid = (blockIdx.x * blockDim.x + threadIdx.x) >> 5;
    int l = threadIdx.x & 31;
    if (wid >= n) return;
    float4 v = __ldcs((const float4*)&g_H[wid * 128 + 4 * l]);
    v.x = fmaxf(v.x, 0.f); v.y = fmaxf(v.y, 0.f);
    v.z = fmaxf(v.z, 0.f); v.w = fmaxf(v.w, 0.f);
    stcs4(&outLast[wid * 128 + 4 * l], v);
    int b = batch[wid];
    redAdd4(&g_pool[b * 128 + 4 * l], v);
    if (l == 0) atomicAdd(&g_cnt[b], 1);
}
__global__ void mlp_kernel(const float* __restrict__ lin1w, const float* __restrict__ lin1b,
                           const float* __restrict__ lin2w, const float* __restrict__ lin2b,
                           float* __restrict__ out) {
    __shared__ float pr[128];
    __shared__ float gg[128];
    __shared__ float lo[NCLS];
    int gr = blockIdx.x;
    int c = threadIdx.x;
    float cnt = (float)max(g_cnt[gr], 1);
    pr[c] = g_pool[gr * 128 + c] / cnt;
    __syncthreads();
    float acc = lin1b[c];
#pragma unroll 8
    for (int k = 0; k < 128; k++) acc += pr[k] * lin1w[k * 128 + c];
    gg[c] = fmaxf(acc, 0.f);
    __syncthreads();
    if (c < NCLS) {
        float a = lin2b[c];
#pragma unroll 8
        for (int k = 0; k < 128; k++) a += gg[k] * lin2w[k * NCLS + c];
        lo[c] = a;
    }
    __syncthreads();
    if (c == 0) {
        float mx = lo[0];
#pragma unroll
        for (int j = 1; j < NCLS; j++) mx = fmaxf(mx, lo[j]);
        float s = 0.f;
#pragma unroll
        for (int j = 0; j < NCLS; j++) s += expf(lo[j] - mx);
        float lse = mx + logf(s);
#pragma unroll
        for (int j = 0; j < NCLS; j++) out[gr * NCLS + j] = lo[j] - lse;
    }
}

// ---------------- host launcher ---------------------------------------------
extern "C" void kernel_launch(void* const* d_in, const int* in_sizes, int n_in,
                              void* d_out, int out_size) {
    const float* x    = (const float*)d_in[0];
    const int*   eidx = (const int*)d_in[1];
    const int*   batch= (const int*)d_in[2];
    const float* W[3]  = { (const float*)d_in[3], (const float*)d_in[7],  (const float*)d_in[11] };
    const float* al[3] = { (const float*)d_in[4], (const float*)d_in[8],  (const float*)d_in[12] };
    const float* ar[3] = { (const float*)d_in[5], (const float*)d_in[9],  (const float*)d_in[13] };
    const float* bb[3] = { (const float*)d_in[6], (const float*)d_in[10], (const float*)d_in[14] };
    const float* lin1w = (const float*)d_in[15];
    const float* lin1b = (const float*)d_in[16];
    const float* lin2w = (const float*)d_in[17];
    const float* lin2b = (const float*)d_in[18];

    int n = in_sizes[0] / DF;
    int E = in_sizes[1] / 2;
    const int* src = eidx;
    const int* dst = eidx + E;

    float* out_logits = (float*)d_out;
    float* out_last   = (float*)d_out + NG * NCLS;

    float* hh; cudaGetSymbolAddress((void**)&hh, g_H);
    uint4* wf; cudaGetSymbolAddress((void**)&wf, g_WfT);

    static int smemSet = 0;
    if (!smemSet) {
        cudaFuncSetAttribute(gemm_mma, cudaFuncAttributeMaxDynamicSharedMemorySize, GS_TOT);
        smemSet = 1;
    }

    int warpNB = (n * 32 + 255) / 256;
    int edgeTB = (E + 255) / 256;
    int nodeTB = (n + 255) / 256;
    int nScanB = (n + SCANB - 1) / SCANB;
    int gemmB  = (n + 63) / 64;

    prep_all<<<24, 256>>>(W[0], W[1], W[2]);                              // 0
    zero_deg<<<nodeTB, 256>>>(n);                                         // 1
    count_deg<<<edgeTB, 256>>>(dst, E);                                   // 2
    gemm_mma<<<gemmB, 256, GS_TOT>>>(x, wf, al[0], ar[0], n, 0, 0);       // 3 <- profiled
    scanA<<<nScanB, SCANB>>>(n);                                          // 4
    scanB<<<1, 256>>>(nScanB);                                            // 5
    scanC<<<nodeTB, 256>>>(n, E);                                         // 6
    csr_fill<<<edgeTB, 256>>>(src, dst, E);                               // 7
    gat_node<<<warpNB, 256>>>(bb[0], n, 0);                               // 8

    for (int L = 1; L < 3; L++) {
        gemm_mma<<<gemmB, 256, GS_TOT>>>(hh, wf + L * 2048, al[L], ar[L], n, 1, L);
        gat_node<<<warpNB, 256>>>(bb[L], n, L);
    }

    zero_pool<<<(NG * DF + 255) / 256, 256>>>();
    pool_copy<<<warpNB, 256>>>(batch, out_last, n);
    mlp_kernel<<<NG, 128>>>(lin1w, lin1b, lin2w, lin2b, out_logits);
}

// round 10
// speedup vs baseline: 3.2697x; 1.0158x over previous
#include <cuda_runtime.h>
#include <cuda_bf16.h>
#include <cuda_fp16.h>
#include <cstdint>
#include <math.h>

#define NND 100000
#define NE  1600000
#define DF  128
#define HEADS 4
#define NG  64
#define NCLS 10
#define NEG 0.2f
#define SCANB 512

// ---------------- scratch ----------------------------------------------------
__device__ __align__(16) __half g_XWh[NND * DF];   // fp16 x@W (messages+self)
__device__ __align__(16) float  g_H  [NND * DF];   // layer output fp32
__device__ __align__(16) float  g_al[NND * HEADS];
__device__ __align__(16) float  g_ar[NND * HEADS];
__device__ unsigned g_gmaxenc[3][HEADS];
__device__ int   g_deg[NND];
__device__ int   g_rowptr[NND + 1];
__device__ int   g_pos[NND];
__device__ int   g_bsum[(NND + SCANB - 1) / SCANB];
__device__ int   g_csr[NE];
__device__ float g_pool[NG * DF];
__device__ int   g_cnt[NG];
__device__ __align__(16) uint4 g_WfT[3][2048];     // fp16 W^T swizzled

// ---------------- helpers ----------------------------------------------------
__device__ __forceinline__ float lrelu(float x) { return x > 0.f ? x : NEG * x; }
__device__ __forceinline__ unsigned fenc(float f) {
    unsigned u = __float_as_uint(f);
    return (u & 0x80000000u) ? ~u : (u | 0x80000000u);
}
__device__ __forceinline__ float fdec(unsigned u) {
    return (u & 0x80000000u) ? __uint_as_float(u & 0x7FFFFFFFu)
                             : __uint_as_float(~u);
}
__device__ __forceinline__ float sel4(float4 v, int h) {
    return h == 0 ? v.x : h == 1 ? v.y : h == 2 ? v.z : v.w;
}
__device__ __forceinline__ void redAdd4(float* p, float4 v) {
    asm volatile("red.global.add.v4.f32 [%0], {%1,%2,%3,%4};"
                 :: "l"(p), "f"(v.x), "f"(v.y), "f"(v.z), "f"(v.w) : "memory");
}
__device__ __forceinline__ void stcs4(float* p, float4 v) {
    asm volatile("st.global.cs.v4.f32 [%0], {%1,%2,%3,%4};"
                 :: "l"(p), "f"(v.x), "f"(v.y), "f"(v.z), "f"(v.w) : "memory");
}
__device__ __forceinline__ uint32_t smem_u32(const void* p) {
    uint32_t a;
    asm("{ .reg .u64 t; cvta.to.shared.u64 t, %1; cvt.u32.u64 %0, t; }" : "=r"(a) : "l"(p));
    return a;
}
__device__ __forceinline__ void ldm4(uint32_t& r0, uint32_t& r1, uint32_t& r2,
                                     uint32_t& r3, uint32_t addr) {
    asm volatile("ldmatrix.sync.aligned.m8n8.x4.shared.b16 {%0,%1,%2,%3}, [%4];"
                 : "=r"(r0), "=r"(r1), "=r"(r2), "=r"(r3) : "r"(addr));
}
__device__ __forceinline__ void mma16816f(float* d, uint32_t a0, uint32_t a1,
                                          uint32_t a2, uint32_t a3,
                                          uint32_t b0, uint32_t b1) {
    asm volatile(
        "mma.sync.aligned.m16n8k16.row.col.f32.f16.f16.f32 "
        "{%0,%1,%2,%3}, {%4,%5,%6,%7}, {%8,%9}, {%0,%1,%2,%3};"
        : "+f"(d[0]), "+f"(d[1]), "+f"(d[2]), "+f"(d[3])
        : "r"(a0), "r"(a1), "r"(a2), "r"(a3), "r"(b0), "r"(b1));
}

union H16x8 { __half h[8]; uint4 u; };

// ---------------- weight prep + gmax zero (all layers, one launch) ------------
__global__ void prep_all(const float* __restrict__ W0, const float* __restrict__ W1,
                         const float* __restrict__ W2) {
    if (blockIdx.x == 0 && threadIdx.x < 12)
        ((unsigned*)g_gmaxenc)[threadIdx.x] = 0u;   // moved here (race-free vs gemm)
    int L = blockIdx.x >> 3;
    int i = (blockIdx.x & 7) * 256 + threadIdx.x;   // 0..2047
    const float* W = (L == 0) ? W0 : (L == 1) ? W1 : W2;
    int nn = i >> 4, c = i & 15;
    H16x8 F;
#pragma unroll
    for (int j = 0; j < 8; j++)
        F.h[j] = __float2half(W[(c * 8 + j) * 128 + nn]);
    g_WfT[L][nn * 16 + (c ^ (nn & 7))] = F.u;
}

// ---------------- fp16 HMMA GEMM + fused al/ar + almax -----------------------
#define GS_A   0
#define GS_W   16384
#define GS_ATT 49152
#define GS_TOT 50176

__global__ void __launch_bounds__(256, 3) gemm_mma(
    const float* __restrict__ A, const uint4* __restrict__ WfT,
    const float* __restrict__ attl, const float* __restrict__ attr,
    int n, int reluIn, int Lidx) {
    extern __shared__ char smem[];
    __shared__ unsigned smax[4];
    uint32_t sb = smem_u32(smem);
    int tid = threadIdx.x, w = tid >> 5, l = tid & 31;
    int rg = w & 3, ch = w >> 2;
    int row0 = blockIdx.x * 64;

    {
        uint4* wf = (uint4*)(smem + GS_W);
        for (int i = tid; i < 2048; i += 256) wf[i] = WfT[i];
    }
    for (int i = tid; i < 1024; i += 256) {
        int r = i >> 4, c = i & 15;
        int row = row0 + r;
        float4 v0 = make_float4(0.f, 0.f, 0.f, 0.f), v1 = v0;
        if (row < n) {
            v0 = __ldcs((const float4*)&A[row * 128 + c * 8]);
            v1 = __ldcs((const float4*)&A[row * 128 + c * 8 + 4]);
        }
        if (reluIn) {
            v0.x = fmaxf(v0.x, 0.f); v0.y = fmaxf(v0.y, 0.f);
            v0.z = fmaxf(v0.z, 0.f); v0.w = fmaxf(v0.w, 0.f);
            v1.x = fmaxf(v1.x, 0.f); v1.y = fmaxf(v1.y, 0.f);
            v1.z = fmaxf(v1.z, 0.f); v1.w = fmaxf(v1.w, 0.f);
        }
        H16x8 F;
        F.h[0] = __float2half(v0.x); F.h[1] = __float2half(v0.y);
        F.h[2] = __float2half(v0.z); F.h[3] = __float2half(v0.w);
        F.h[4] = __float2half(v1.x); F.h[5] = __float2half(v1.y);
        F.h[6] = __float2half(v1.z); F.h[7] = __float2half(v1.w);
        *(uint4*)(smem + GS_A + r * 256 + ((c ^ (r & 7)) << 4)) = F.u;
    }
    __syncthreads();

    int aRow = rg * 16 + ((l >> 3) & 1) * 8 + (l & 7);
    int aChk = (l >> 4) & 1;
    uint32_t aBase = sb + GS_A + aRow * 256;
    int aXor = aRow & 7;
    int bRowL = ((l >> 4) & 1) * 8 + (l & 7);
    int bChk = (l >> 3) & 1;

    float acc[32];
#pragma unroll
    for (int i = 0; i < 32; i++) acc[i] = 0.f;

#pragma unroll
    for (int ks = 0; ks < 8; ks++) {
        uint32_t a0, a1, a2, a3;
        ldm4(a0, a1, a2, a3, aBase + (((2 * ks + aChk) ^ aXor) << 4));
#pragma unroll
        for (int p = 0; p < 4; p++) {
            int bRow = ch * 64 + p * 16 + bRowL;
            uint32_t bAddr = sb + GS_W + bRow * 256
                           + (((2 * ks + bChk) ^ (bRow & 7)) << 4);
            uint32_t b0, b1, b2, b3;
            ldm4(b0, b1, b2, b3, bAddr);
            mma16816f(&acc[(2 * p) * 4],     a0, a1, a2, a3, b0, b1);
            mma16816f(&acc[(2 * p + 1) * 4], a0, a1, a2, a3, b2, b3);
        }
    }
    __syncthreads();

    float* Cs = (float*)smem;
    float* att = (float*)(smem + GS_ATT);
    att[tid] = (tid < 128) ? attl[tid] : attr[tid - 128];
    if (tid < 4) smax[tid] = 0u;
    {
        int r1 = rg * 16 + (l >> 2);
#pragma unroll
        for (int nt = 0; nt < 8; nt++) {
            int p = nt >> 1, t = nt & 1;
            int col = ch * 64 + p * 16 + t * 8 + (l & 3) * 2;
            float* d = &acc[nt * 4];
            Cs[r1 * 132 + col]           = d[0];
            Cs[r1 * 132 + col + 1]       = d[1];
            Cs[(r1 + 8) * 132 + col]     = d[2];
            Cs[(r1 + 8) * 132 + col + 1] = d[3];
        }
    }
    __syncthreads();

    for (int i = tid; i < 2048; i += 256) {
        int r = i >> 5, c4 = i & 31;
        int row = row0 + r;
        if (row < n) {
            float4 v = *(float4*)&Cs[r * 132 + c4 * 4];
            __half2 h0 = __floats2half2_rn(v.x, v.y);
            __half2 h1 = __floats2half2_rn(v.z, v.w);
            uint2 u;
            u.x = *(uint32_t*)&h0; u.y = *(uint32_t*)&h1;
            *(uint2*)&g_XWh[row * 128 + c4 * 4] = u;
        }
    }
    if (tid < 128) {
        int half_ = tid >> 6;
        int r = tid & 63;
        int row = row0 + r;
        if (row < n) {
            const float* av = att + half_ * 128;
            float d0 = 0.f, d1 = 0.f, d2 = 0.f, d3 = 0.f;
#pragma unroll 8
            for (int c = 0; c < 32; c++) {
                d0 += Cs[r * 132 + c]      * av[c];
                d1 += Cs[r * 132 + 32 + c] * av[32 + c];
                d2 += Cs[r * 132 + 64 + c] * av[64 + c];
                d3 += Cs[r * 132 + 96 + c] * av[96 + c];
            }
            float* dst = half_ ? g_ar : g_al;
            *(float4*)&dst[row * 4] = make_float4(d0, d1, d2, d3);
            if (half_ == 0) {
                atomicMax(&smax[0], fenc(d0));
                atomicMax(&smax[1], fenc(d1));
                atomicMax(&smax[2], fenc(d2));
                atomicMax(&smax[3], fenc(d3));
            }
        }
    }
    __syncthreads();
    if (tid < 4) atomicMax(&g_gmaxenc[Lidx][tid], smax[tid]);
}

// ---------------- CSR build --------------------------------------------------
__global__ void zero_deg(int n) {
    int i = blockIdx.x * blockDim.x + threadIdx.x;
    if (i < n) g_deg[i] = 0;
}
__global__ void count_deg(const int* __restrict__ dst, int E) {
    int e = blockIdx.x * blockDim.x + threadIdx.x;
    if (e < E) atomicAdd(&g_deg[dst[e]], 1);
}
__global__ void scanA(int n) {
    __shared__ int sh[SCANB];
    int i = blockIdx.x * SCANB + threadIdx.x;
    int v = (i < n) ? g_deg[i] : 0;
    sh[threadIdx.x] = v;
    __syncthreads();
    for (int off = 1; off < SCANB; off <<= 1) {
        int t = (threadIdx.x >= off) ? sh[threadIdx.x - off] : 0;
        __syncthreads();
        sh[threadIdx.x] += t;
        __syncthreads();
    }
    if (i < n) g_rowptr[i] = sh[threadIdx.x] - v;
    if (threadIdx.x == SCANB - 1) g_bsum[blockIdx.x] = sh[SCANB - 1];
}
__global__ void scanB(int nb) {
    __shared__ int sh[256];
    int v = (threadIdx.x < nb) ? g_bsum[threadIdx.x] : 0;
    sh[threadIdx.x] = v;
    __syncthreads();
    for (int off = 1; off < 256; off <<= 1) {
        int t = (threadIdx.x >= off) ? sh[threadIdx.x - off] : 0;
        __syncthreads();
        sh[threadIdx.x] += t;
        __syncthreads();
    }
    if (threadIdx.x < nb) g_bsum[threadIdx.x] = sh[threadIdx.x] - v;
}
__global__ void scanC(int n, int E) {
    int i = blockIdx.x * blockDim.x + threadIdx.x;
    if (i < n) {
        int r = g_rowptr[i] + g_bsum[i / SCANB];
        g_rowptr[i] = r;
        g_pos[i] = r;
    }
    if (i == 0) g_rowptr[n] = E;
}
__global__ void csr_fill(const int* __restrict__ src, const int* __restrict__ dst, int E) {
    int e = blockIdx.x * blockDim.x + threadIdx.x;
    if (e >= E) return;
    int p = atomicAdd(&g_pos[dst[e]], 1);
    g_csr[p] = src[e];
}

// ---------------- fused per-node GAT: pipelined single sweep -----------------
__global__ void gat_node(const float* __restrict__ bias, int n, int L) {
    int wid = (blockIdx.x * blockDim.x + threadIdx.x) >> 5;
    int l = threadIdx.x & 31;
    if (wid >= n) return;
    int rp = g_rowptr[wid], re = g_rowptr[wid + 1];

    float4 ad = *(const float4*)&g_al[wid * 4];
    float4 bd = *(const float4*)&g_ar[wid * 4];

    int h = l >> 3;
    int eo = l & 7;
    float arh  = sel4(bd, h);
    float mh   = lrelu(fdec(g_gmaxenc[L][h]) + arh);
    float slgh = lrelu(sel4(ad, h) + arh);

    float zacc = 0.f;
    float4 acc = make_float4(0.f, 0.f, 0.f, 0.f);

    int s_cur = wid; float als_cur = 0.f;
    if (rp + eo < re) {
        s_cur = g_csr[rp + eo];
        als_cur = __ldg(&g_al[s_cur * 4 + h]);
    }
    for (int j0 = rp; j0 < re; j0 += 8) {
        int s_nxt = wid; float als_nxt = 0.f;
        if (j0 + 8 + eo < re) {
            s_nxt = g_csr[j0 + 8 + eo];
            als_nxt = __ldg(&g_al[s_nxt * 4 + h]);
        }
        float e_l = 0.f;
        if (j0 + eo < re) {
            e_l = __expf(lrelu(als_cur + arh) - mh);
            zacc += e_l;
        }
        int kmax = min(8, re - j0);
#pragma unroll 8
        for (int k = 0; k < kmax; k++) {
            int s = __shfl_sync(0xFFFFFFFFu, s_cur, k);
            float ek = __shfl_sync(0xFFFFFFFFu, e_l, (l & 24) | k);
            uint2 u = *(const uint2*)&g_XWh[s * 128 + 4 * l];
            __half2 p0 = *(__half2*)&u.x, p1 = *(__half2*)&u.y;
            float2 f0 = __half22float2(p0), f1 = __half22float2(p1);
            acc.x += ek * f0.x; acc.y += ek * f0.y;
            acc.z += ek * f1.x; acc.w += ek * f1.y;
        }
        s_cur = s_nxt; als_cur = als_nxt;
    }
#pragma unroll
    for (int o = 1; o < 8; o <<= 1) zacc += __shfl_xor_sync(0xFFFFFFFFu, zacc, o);

    float eself = __expf(slgh - mh);
    float rz = 1.f / (zacc + eself);
    uint2 us = *(const uint2*)&g_XWh[wid * 128 + 4 * l];
    __half2 s0 = *(__half2*)&us.x, s1 = *(__half2*)&us.y;
    float2 fs0 = __half22float2(s0), fs1 = __half22float2(s1);
    acc.x = (acc.x + eself * fs0.x) * rz;
    acc.y = (acc.y + eself * fs0.y) * rz;
    acc.z = (acc.z + eself * fs1.x) * rz;
    acc.w = (acc.w + eself * fs1.y) * rz;
    float4 bv = *(const float4*)&bias[4 * l];
    acc.x += bv.x; acc.y += bv.y; acc.z += bv.z; acc.w += bv.w;
    stcs4(&g_H[wid * 128 + 4 * l], acc);
}

// ---------------- pooling / MLP ----------------------------------------------
__global__ void zero_pool() {
    int i = blockIdx.x * blockDim.x + threadIdx.x;
    if (i < NG * DF) g_pool[i] = 0.f;
    if (i < NG) g_cnt[i] = 0;
}
__global__ void pool_copy(const int* __restrict__ batch, float* __restrict__ outLast, int n) {
    int wid = (blockIdx.x * blockDim.x + threadIdx.x) >> 5;
    int l = threadIdx.x & 31;
    if (wid >= n) return;
    float4 v = __ldcs((const float4*)&g_H[wid * 128 + 4 * l]);
    v.x = fmaxf(v.x, 0.f); v.y = fmaxf(v.y, 0.f);
    v.z = fmaxf(v.z, 0.f); v.w = fmaxf(v.w, 0.f);
    stcs4(&outLast[wid * 128 + 4 * l], v);
    int b = batch[wid];
    redAdd4(&g_pool[b * 128 + 4 * l], v);
    if (l == 0) atomicAdd(&g_cnt[b], 1);
}
__global__ void mlp_kernel(const float* __restrict__ lin1w, const float* __restrict__ lin1b,
                           const float* __restrict__ lin2w, const float* __restrict__ lin2b,
                           float* __restrict__ out) {
    __shared__ float pr[128];
    __shared__ float gg[128];
    __shared__ float lo[NCLS];
    int gr = blockIdx.x;
    int c = threadIdx.x;
    float cnt = (float)max(g_cnt[gr], 1);
    pr[c] = g_pool[gr * 128 + c] / cnt;
    __syncthreads();
    float acc = lin1b[c];
#pragma unroll 8
    for (int k = 0; k < 128; k++) acc += pr[k] * lin1w[k * 128 + c];
    gg[c] = fmaxf(acc, 0.f);
    __syncthreads();
    if (c < NCLS) {
        float a = lin2b[c];
#pragma unroll 8
        for (int k = 0; k < 128; k++) a += gg[k] * lin2w[k * NCLS + c];
        lo[c] = a;
    }
    __syncthreads();
    if (c == 0) {
        float mx = lo[0];
#pragma unroll
        for (int j = 1; j < NCLS; j++) mx = fmaxf(mx, lo[j]);
        float s = 0.f;
#pragma unroll
        for (int j = 0; j < NCLS; j++) s += expf(lo[j] - mx);
        float lse = mx + logf(s);
#pragma unroll
        for (int j = 0; j < NCLS; j++) out[gr * NCLS + j] = lo[j] - lse;
    }
}

// ---------------- host launcher ---------------------------------------------
extern "C" void kernel_launch(void* const* d_in, const int* in_sizes, int n_in,
                              void* d_out, int out_size) {
    const float* x    = (const float*)d_in[0];
    const int*   eidx = (const int*)d_in[1];
    const int*   batch= (const int*)d_in[2];
    const float* W[3]  = { (const float*)d_in[3], (const float*)d_in[7],  (const float*)d_in[11] };
    const float* al[3] = { (const float*)d_in[4], (const float*)d_in[8],  (const float*)d_in[12] };
    const float* ar[3] = { (const float*)d_in[5], (const float*)d_in[9],  (const float*)d_in[13] };
    const float* bb[3] = { (const float*)d_in[6], (const float*)d_in[10], (const float*)d_in[14] };
    const float* lin1w = (const float*)d_in[15];
    const float* lin1b = (const float*)d_in[16];
    const float* lin2w = (const float*)d_in[17];
    const float* lin2b = (const float*)d_in[18];

    int n = in_sizes[0] / DF;
    int E = in_sizes[1] / 2;
    const int* src = eidx;
    const int* dst = eidx + E;

    float* out_logits = (float*)d_out;
    float* out_last   = (float*)d_out + NG * NCLS;

    float* hh; cudaGetSymbolAddress((void**)&hh, g_H);
    uint4* wf; cudaGetSymbolAddress((void**)&wf, g_WfT);

    static int inited = 0;
    static cudaStream_t sB;
    static cudaEvent_t evF, evJ;
    if (!inited) {
        cudaFuncSetAttribute(gemm_mma, cudaFuncAttributeMaxDynamicSharedMemorySize, GS_TOT);
        cudaStreamCreateWithFlags(&sB, cudaStreamNonBlocking);
        cudaEventCreateWithFlags(&evF, cudaEventDisableTiming);
        cudaEventCreateWithFlags(&evJ, cudaEventDisableTiming);
        inited = 1;
    }

    int warpNB = (n * 32 + 255) / 256;
    int edgeTB = (E + 255) / 256;
    int nodeTB = (n + 255) / 256;
    int nScanB = (n + SCANB - 1) / SCANB;
    int gemmB  = (n + 63) / 64;

    // fork: CSR-build chain on sB, GEMM path on main stream
    cudaEventRecord(evF, 0);
    cudaStreamWaitEvent(sB, evF, 0);

    // side stream: CSR build + pool zero (independent of gemm L0)
    zero_deg<<<nodeTB, 256, 0, sB>>>(n);
    count_deg<<<edgeTB, 256, 0, sB>>>(dst, E);
    scanA<<<nScanB, SCANB, 0, sB>>>(n);
    scanB<<<1, 256, 0, sB>>>(nScanB);
    scanC<<<nodeTB, 256, 0, sB>>>(n, E);
    csr_fill<<<edgeTB, 256, 0, sB>>>(src, dst, E);
    zero_pool<<<(NG * DF + 255) / 256, 256, 0, sB>>>();

    // main stream: weight prep + layer-0 GEMM
    prep_all<<<24, 256>>>(W[0], W[1], W[2]);
    gemm_mma<<<gemmB, 256, GS_TOT>>>(x, wf, al[0], ar[0], n, 0, 0);

    // join: gat_node L0 needs both
    cudaEventRecord(evJ, sB);
    cudaStreamWaitEvent(0, evJ, 0);

    gat_node<<<warpNB, 256>>>(bb[0], n, 0);
    for (int L = 1; L < 3; L++) {
        gemm_mma<<<gemmB, 256, GS_TOT>>>(hh, wf + L * 2048, al[L], ar[L], n, 1, L);
        gat_node<<<warpNB, 256>>>(bb[L], n, L);
    }

    pool_copy<<<warpNB, 256>>>(batch, out_last, n);
    mlp_kernel<<<NG, 128>>>(lin1w, lin1b, lin2w, lin2b, out_logits);
}

// round 11
// speedup vs baseline: 3.4772x; 1.0635x over previous
#include <cuda_runtime.h>
#include <cuda_bf16.h>
#include <cuda_fp16.h>
#include <cstdint>
#include <math.h>

#define NND 100000
#define NE  1600000
#define DF  128
#define HEADS 4
#define NG  64
#define NCLS 10
#define NEG 0.2f
#define SCANB 512

// ---------------- scratch ----------------------------------------------------
__device__ __align__(16) __half g_XWh[NND * DF];   // fp16 x@W (messages+self)
__device__ __align__(16) __half g_Hh [NND * DF];   // fp16 relu(layer output)
__device__ __align__(16) float  g_al[NND * HEADS];
__device__ __align__(16) float  g_ar[NND * HEADS];
__device__ unsigned g_gmaxenc[3][HEADS];
__device__ int   g_deg[NND];
__device__ int   g_rowptr[NND + 1];
__device__ int   g_pos[NND];
__device__ int   g_bsum[(NND + SCANB - 1) / SCANB];
__device__ int   g_csr[NE];
__device__ float g_pool[NG * DF];
__device__ int   g_cnt[NG];
__device__ __align__(16) uint4 g_WfT[3][2048];     // fp16 W^T swizzled

// ---------------- helpers ----------------------------------------------------
__device__ __forceinline__ float lrelu(float x) { return x > 0.f ? x : NEG * x; }
__device__ __forceinline__ unsigned fenc(float f) {
    unsigned u = __float_as_uint(f);
    return (u & 0x80000000u) ? ~u : (u | 0x80000000u);
}
__device__ __forceinline__ float fdec(unsigned u) {
    return (u & 0x80000000u) ? __uint_as_float(u & 0x7FFFFFFFu)
                             : __uint_as_float(~u);
}
__device__ __forceinline__ float sel4(float4 v, int h) {
    return h == 0 ? v.x : h == 1 ? v.y : h == 2 ? v.z : v.w;
}
__device__ __forceinline__ void redAdd4(float* p, float4 v) {
    asm volatile("red.global.add.v4.f32 [%0], {%1,%2,%3,%4};"
                 :: "l"(p), "f"(v.x), "f"(v.y), "f"(v.z), "f"(v.w) : "memory");
}
__device__ __forceinline__ void stcs4(float* p, float4 v) {
    asm volatile("st.global.cs.v4.f32 [%0], {%1,%2,%3,%4};"
                 :: "l"(p), "f"(v.x), "f"(v.y), "f"(v.z), "f"(v.w) : "memory");
}
__device__ __forceinline__ void stcs2u(void* p, uint2 u) {
    asm volatile("st.global.cs.v2.u32 [%0], {%1,%2};"
                 :: "l"(p), "r"(u.x), "r"(u.y) : "memory");
}
__device__ __forceinline__ uint32_t smem_u32(const void* p) {
    uint32_t a;
    asm("{ .reg .u64 t; cvta.to.shared.u64 t, %1; cvt.u32.u64 %0, t; }" : "=r"(a) : "l"(p));
    return a;
}
__device__ __forceinline__ void ldm4(uint32_t& r0, uint32_t& r1, uint32_t& r2,
                                     uint32_t& r3, uint32_t addr) {
    asm volatile("ldmatrix.sync.aligned.m8n8.x4.shared.b16 {%0,%1,%2,%3}, [%4];"
                 : "=r"(r0), "=r"(r1), "=r"(r2), "=r"(r3) : "r"(addr));
}
__device__ __forceinline__ void mma16816f(float* d, uint32_t a0, uint32_t a1,
                                          uint32_t a2, uint32_t a3,
                                          uint32_t b0, uint32_t b1) {
    asm volatile(
        "mma.sync.aligned.m16n8k16.row.col.f32.f16.f16.f32 "
        "{%0,%1,%2,%3}, {%4,%5,%6,%7}, {%8,%9}, {%0,%1,%2,%3};"
        : "+f"(d[0]), "+f"(d[1]), "+f"(d[2]), "+f"(d[3])
        : "r"(a0), "r"(a1), "r"(a2), "r"(a3), "r"(b0), "r"(b1));
}

union H16x8 { __half h[8]; uint4 u; };

// ---------------- weight prep + gmax zero (all layers, one launch) ------------
__global__ void prep_all(const float* __restrict__ W0, const float* __restrict__ W1,
                         const float* __restrict__ W2) {
    if (blockIdx.x == 0 && threadIdx.x < 12)
        ((unsigned*)g_gmaxenc)[threadIdx.x] = 0u;
    int L = blockIdx.x >> 3;
    int i = (blockIdx.x & 7) * 256 + threadIdx.x;
    const float* W = (L == 0) ? W0 : (L == 1) ? W1 : W2;
    int nn = i >> 4, c = i & 15;
    H16x8 F;
#pragma unroll
    for (int j = 0; j < 8; j++)
        F.h[j] = __float2half(W[(c * 8 + j) * 128 + nn]);
    g_WfT[L][nn * 16 + (c ^ (nn & 7))] = F.u;
}

// ---------------- fp16 HMMA GEMM + fused al/ar + almax -----------------------
#define GS_A   0
#define GS_W   16384
#define GS_ATT 49152
#define GS_TOT 50176

__global__ void __launch_bounds__(256, 3) gemm_mma(
    const void* __restrict__ Ain, int aHalf, const uint4* __restrict__ WfT,
    const float* __restrict__ attl, const float* __restrict__ attr,
    int n, int Lidx) {
    extern __shared__ char smem[];
    __shared__ unsigned smax[4];
    uint32_t sb = smem_u32(smem);
    int tid = threadIdx.x, w = tid >> 5, l = tid & 31;
    int rg = w & 3, ch = w >> 2;
    int row0 = blockIdx.x * 64;

    {
        uint4* wf = (uint4*)(smem + GS_W);
        for (int i = tid; i < 2048; i += 256) wf[i] = WfT[i];
    }
    if (aHalf) {
        const __half* Ah = (const __half*)Ain;   // already relu'd fp16
        for (int i = tid; i < 1024; i += 256) {
            int r = i >> 4, c = i & 15;
            int row = row0 + r;
            uint4 u = make_uint4(0u, 0u, 0u, 0u);
            if (row < n) u = __ldcs((const uint4*)&Ah[row * 128 + c * 8]);
            *(uint4*)(smem + GS_A + r * 256 + ((c ^ (r & 7)) << 4)) = u;
        }
    } else {
        const float* A = (const float*)Ain;      // layer 0: raw fp32 x
        for (int i = tid; i < 1024; i += 256) {
            int r = i >> 4, c = i & 15;
            int row = row0 + r;
            float4 v0 = make_float4(0.f, 0.f, 0.f, 0.f), v1 = v0;
            if (row < n) {
                v0 = __ldcs((const float4*)&A[row * 128 + c * 8]);
                v1 = __ldcs((const float4*)&A[row * 128 + c * 8 + 4]);
            }
            H16x8 F;
            F.h[0] = __float2half(v0.x); F.h[1] = __float2half(v0.y);
            F.h[2] = __float2half(v0.z); F.h[3] = __float2half(v0.w);
            F.h[4] = __float2half(v1.x); F.h[5] = __float2half(v1.y);
            F.h[6] = __float2half(v1.z); F.h[7] = __float2half(v1.w);
            *(uint4*)(smem + GS_A + r * 256 + ((c ^ (r & 7)) << 4)) = F.u;
        }
    }
    __syncthreads();

    int aRow = rg * 16 + ((l >> 3) & 1) * 8 + (l & 7);
    int aChk = (l >> 4) & 1;
    uint32_t aBase = sb + GS_A + aRow * 256;
    int aXor = aRow & 7;
    int bRowL = ((l >> 4) & 1) * 8 + (l & 7);
    int bChk = (l >> 3) & 1;

    float acc[32];
#pragma unroll
    for (int i = 0; i < 32; i++) acc[i] = 0.f;

#pragma unroll
    for (int ks = 0; ks < 8; ks++) {
        uint32_t a0, a1, a2, a3;
        ldm4(a0, a1, a2, a3, aBase + (((2 * ks + aChk) ^ aXor) << 4));
#pragma unroll
        for (int p = 0; p < 4; p++) {
            int bRow = ch * 64 + p * 16 + bRowL;
            uint32_t bAddr = sb + GS_W + bRow * 256
                           + (((2 * ks + bChk) ^ (bRow & 7)) << 4);
            uint32_t b0, b1, b2, b3;
            ldm4(b0, b1, b2, b3, bAddr);
            mma16816f(&acc[(2 * p) * 4],     a0, a1, a2, a3, b0, b1);
            mma16816f(&acc[(2 * p + 1) * 4], a0, a1, a2, a3, b2, b3);
        }
    }
    __syncthreads();

    float* Cs = (float*)smem;
    float* att = (float*)(smem + GS_ATT);
    att[tid] = (tid < 128) ? attl[tid] : attr[tid - 128];
    if (tid < 4) smax[tid] = 0u;
    {
        int r1 = rg * 16 + (l >> 2);
#pragma unroll
        for (int nt = 0; nt < 8; nt++) {
            int p = nt >> 1, t = nt & 1;
            int col = ch * 64 + p * 16 + t * 8 + (l & 3) * 2;
            float* d = &acc[nt * 4];
            Cs[r1 * 132 + col]           = d[0];
            Cs[r1 * 132 + col + 1]       = d[1];
            Cs[(r1 + 8) * 132 + col]     = d[2];
            Cs[(r1 + 8) * 132 + col + 1] = d[3];
        }
    }
    __syncthreads();

    for (int i = tid; i < 2048; i += 256) {
        int r = i >> 5, c4 = i & 31;
        int row = row0 + r;
        if (row < n) {
            float4 v = *(float4*)&Cs[r * 132 + c4 * 4];
            __half2 h0 = __floats2half2_rn(v.x, v.y);
            __half2 h1 = __floats2half2_rn(v.z, v.w);
            uint2 u;
            u.x = *(uint32_t*)&h0; u.y = *(uint32_t*)&h1;
            *(uint2*)&g_XWh[row * 128 + c4 * 4] = u;
        }
    }
    if (tid < 128) {
        int half_ = tid >> 6;
        int r = tid & 63;
        int row = row0 + r;
        if (row < n) {
            const float* av = att + half_ * 128;
            float d0 = 0.f, d1 = 0.f, d2 = 0.f, d3 = 0.f;
#pragma unroll 8
            for (int c = 0; c < 32; c++) {
                d0 += Cs[r * 132 + c]      * av[c];
                d1 += Cs[r * 132 + 32 + c] * av[32 + c];
                d2 += Cs[r * 132 + 64 + c] * av[64 + c];
                d3 += Cs[r * 132 + 96 + c] * av[96 + c];
            }
            float* dst = half_ ? g_ar : g_al;
            *(float4*)&dst[row * 4] = make_float4(d0, d1, d2, d3);
            if (half_ == 0) {
                atomicMax(&smax[0], fenc(d0));
                atomicMax(&smax[1], fenc(d1));
                atomicMax(&smax[2], fenc(d2));
                atomicMax(&smax[3], fenc(d3));
            }
        }
    }
    __syncthreads();
    if (tid < 4) atomicMax(&g_gmaxenc[Lidx][tid], smax[tid]);
}

// ---------------- CSR build --------------------------------------------------
__global__ void zero_deg(int n) {
    int i = blockIdx.x * blockDim.x + threadIdx.x;
    if (i < n) g_deg[i] = 0;
}
__global__ void count_deg(const int* __restrict__ dst, int E) {
    int e = blockIdx.x * blockDim.x + threadIdx.x;
    if (e < E) atomicAdd(&g_deg[dst[e]], 1);
}
__global__ void scanA(int n) {
    __shared__ int sh[SCANB];
    int i = blockIdx.x * SCANB + threadIdx.x;
    int v = (i < n) ? g_deg[i] : 0;
    sh[threadIdx.x] = v;
    __syncthreads();
    for (int off = 1; off < SCANB; off <<= 1) {
        int t = (threadIdx.x >= off) ? sh[threadIdx.x - off] : 0;
        __syncthreads();
        sh[threadIdx.x] += t;
        __syncthreads();
    }
    if (i < n) g_rowptr[i] = sh[threadIdx.x] - v;
    if (threadIdx.x == SCANB - 1) g_bsum[blockIdx.x] = sh[SCANB - 1];
}
__global__ void scanB(int nb) {
    __shared__ int sh[256];
    int v = (threadIdx.x < nb) ? g_bsum[threadIdx.x] : 0;
    sh[threadIdx.x] = v;
    __syncthreads();
    for (int off = 1; off < 256; off <<= 1) {
        int t = (threadIdx.x >= off) ? sh[threadIdx.x - off] : 0;
        __syncthreads();
        sh[threadIdx.x] += t;
        __syncthreads();
    }
    if (threadIdx.x < nb) g_bsum[threadIdx.x] = sh[threadIdx.x] - v;
}
__global__ void scanC(int n, int E) {
    int i = blockIdx.x * blockDim.x + threadIdx.x;
    if (i < n) {
        int r = g_rowptr[i] + g_bsum[i / SCANB];
        g_rowptr[i] = r;
        g_pos[i] = r;
    }
    if (i == 0) g_rowptr[n] = E;
}
__global__ void csr_fill(const int* __restrict__ src, const int* __restrict__ dst, int E) {
    int e = blockIdx.x * blockDim.x + threadIdx.x;
    if (e >= E) return;
    int p = atomicAdd(&g_pos[dst[e]], 1);
    g_csr[p] = src[e];
}

// ---------------- fused per-node GAT ------------------------------------------
// last==0: writes relu(out) fp16 -> g_Hh.
// last==1: writes relu(out) fp32 -> lastOut, accumulates g_pool/g_cnt.
__global__ void gat_node(const float* __restrict__ bias, int n, int L, int last,
                         const int* __restrict__ batch, float* __restrict__ lastOut) {
    int wid = (blockIdx.x * blockDim.x + threadIdx.x) >> 5;
    int l = threadIdx.x & 31;
    if (wid >= n) return;
    int rp = g_rowptr[wid], re = g_rowptr[wid + 1];

    float4 ad = *(const float4*)&g_al[wid * 4];
    float4 bd = *(const float4*)&g_ar[wid * 4];

    int h = l >> 3;
    int eo = l & 7;
    float arh  = sel4(bd, h);
    float mh   = lrelu(fdec(g_gmaxenc[L][h]) + arh);
    float slgh = lrelu(sel4(ad, h) + arh);

    float zacc = 0.f;
    float4 acc = make_float4(0.f, 0.f, 0.f, 0.f);

    int s_cur = wid; float als_cur = 0.f;
    if (rp + eo < re) {
        s_cur = g_csr[rp + eo];
        als_cur = __ldg(&g_al[s_cur * 4 + h]);
    }
    for (int j0 = rp; j0 < re; j0 += 8) {
        int s_nxt = wid; float als_nxt = 0.f;
        if (j0 + 8 + eo < re) {
            s_nxt = g_csr[j0 + 8 + eo];
            als_nxt = __ldg(&g_al[s_nxt * 4 + h]);
        }
        float e_l = 0.f;
        if (j0 + eo < re) {
            e_l = __expf(lrelu(als_cur + arh) - mh);
            zacc += e_l;
        }
        int kmax = min(8, re - j0);
#pragma unroll 8
        for (int k = 0; k < kmax; k++) {
            int s = __shfl_sync(0xFFFFFFFFu, s_cur, k);
            float ek = __shfl_sync(0xFFFFFFFFu, e_l, (l & 24) | k);
            uint2 u = *(const uint2*)&g_XWh[s * 128 + 4 * l];
            __half2 p0 = *(__half2*)&u.x, p1 = *(__half2*)&u.y;
            float2 f0 = __half22float2(p0), f1 = __half22float2(p1);
            acc.x += ek * f0.x; acc.y += ek * f0.y;
            acc.z += ek * f1.x; acc.w += ek * f1.y;
        }
        s_cur = s_nxt; als_cur = als_nxt;
    }
#pragma unroll
    for (int o = 1; o < 8; o <<= 1) zacc += __shfl_xor_sync(0xFFFFFFFFu, zacc, o);

    float eself = __expf(slgh - mh);
    float rz = 1.f / (zacc + eself);
    uint2 us = *(const uint2*)&g_XWh[wid * 128 + 4 * l];
    __half2 s0 = *(__half2*)&us.x, s1 = *(__half2*)&us.y;
    float2 fs0 = __half22float2(s0), fs1 = __half22float2(s1);
    float4 bv = *(const float4*)&bias[4 * l];
    float4 o;
    o.x = fmaxf((acc.x + eself * fs0.x) * rz + bv.x, 0.f);
    o.y = fmaxf((acc.y + eself * fs0.y) * rz + bv.y, 0.f);
    o.z = fmaxf((acc.z + eself * fs1.x) * rz + bv.z, 0.f);
    o.w = fmaxf((acc.w + eself * fs1.y) * rz + bv.w, 0.f);

    if (!last) {
        __half2 h0 = __floats2half2_rn(o.x, o.y);
        __half2 h1 = __floats2half2_rn(o.z, o.w);
        uint2 u;
        u.x = *(uint32_t*)&h0; u.y = *(uint32_t*)&h1;
        stcs2u(&g_Hh[wid * 128 + 4 * l], u);
    } else {
        stcs4(&lastOut[wid * 128 + 4 * l], o);
        int b = batch[wid];
        redAdd4(&g_pool[b * 128 + 4 * l], o);
        if (l == 0) atomicAdd(&g_cnt[b], 1);
    }
}

// ---------------- pooling / MLP ----------------------------------------------
__global__ void zero_pool() {
    int i = blockIdx.x * blockDim.x + threadIdx.x;
    if (i < NG * DF) g_pool[i] = 0.f;
    if (i < NG) g_cnt[i] = 0;
}
__global__ void mlp_kernel(const float* __restrict__ lin1w, const float* __restrict__ lin1b,
                           const float* __restrict__ lin2w, const float* __restrict__ lin2b,
                           float* __restrict__ out) {
    __shared__ float pr[128];
    __shared__ float gg[128];
    __shared__ float lo[NCLS];
    int gr = blockIdx.x;
    int c = threadIdx.x;
    float cnt = (float)max(g_cnt[gr], 1);
    pr[c] = g_pool[gr * 128 + c] / cnt;
    __syncthreads();
    float acc = lin1b[c];
#pragma unroll 8
    for (int k = 0; k < 128; k++) acc += pr[k] * lin1w[k * 128 + c];
    gg[c] = fmaxf(acc, 0.f);
    __syncthreads();
    if (c < NCLS) {
        float a = lin2b[c];
#pragma unroll 8
        for (int k = 0; k < 128; k++) a += gg[k] * lin2w[k * NCLS + c];
        lo[c] = a;
    }
    __syncthreads();
    if (c == 0) {
        float mx = lo[0];
#pragma unroll
        for (int j = 1; j < NCLS; j++) mx = fmaxf(mx, lo[j]);
        float s = 0.f;
#pragma unroll
        for (int j = 0; j < NCLS; j++) s += expf(lo[j] - mx);
        float lse = mx + logf(s);
#pragma unroll
        for (int j = 0; j < NCLS; j++) out[gr * NCLS + j] = lo[j] - lse;
    }
}

// ---------------- host launcher ---------------------------------------------
extern "C" void kernel_launch(void* const* d_in, const int* in_sizes, int n_in,
                              void* d_out, int out_size) {
    const float* x    = (const float*)d_in[0];
    const int*   eidx = (const int*)d_in[1];
    const int*   batch= (const int*)d_in[2];
    const float* W[3]  = { (const float*)d_in[3], (const float*)d_in[7],  (const float*)d_in[11] };
    const float* al[3] = { (const float*)d_in[4], (const float*)d_in[8],  (const float*)d_in[12] };
    const float* ar[3] = { (const float*)d_in[5], (const float*)d_in[9],  (const float*)d_in[13] };
    const float* bb[3] = { (const float*)d_in[6], (const float*)d_in[10], (const float*)d_in[14] };
    const float* lin1w = (const float*)d_in[15];
    const float* lin1b = (const float*)d_in[16];
    const float* lin2w = (const float*)d_in[17];
    const float* lin2b = (const float*)d_in[18];

    int n = in_sizes[0] / DF;
    int E = in_sizes[1] / 2;
    const int* src = eidx;
    const int* dst = eidx + E;

    float* out_logits = (float*)d_out;
    float* out_last   = (float*)d_out + NG * NCLS;

    __half* hh; cudaGetSymbolAddress((void**)&hh, g_Hh);
    uint4* wf; cudaGetSymbolAddress((void**)&wf, g_WfT);

    static int inited = 0;
    static cudaStream_t sB;
    static cudaEvent_t evF, evJ;
    if (!inited) {
        cudaFuncSetAttribute(gemm_mma, cudaFuncAttributeMaxDynamicSharedMemorySize, GS_TOT);
        cudaStreamCreateWithFlags(&sB, cudaStreamNonBlocking);
        cudaEventCreateWithFlags(&evF, cudaEventDisableTiming);
        cudaEventCreateWithFlags(&evJ, cudaEventDisableTiming);
        inited = 1;
    }

    int warpNB = (n * 32 + 255) / 256;
    int edgeTB = (E + 255) / 256;
    int nodeTB = (n + 255) / 256;
    int nScanB = (n + SCANB - 1) / SCANB;
    int gemmB  = (n + 63) / 64;

    // fork: CSR-build chain on sB, GEMM path on main stream
    cudaEventRecord(evF, 0);
    cudaStreamWaitEvent(sB, evF, 0);

    zero_deg<<<nodeTB, 256, 0, sB>>>(n);
    count_deg<<<edgeTB, 256, 0, sB>>>(dst, E);
    scanA<<<nScanB, SCANB, 0, sB>>>(n);
    scanB<<<1, 256, 0, sB>>>(nScanB);
    scanC<<<nodeTB, 256, 0, sB>>>(n, E);
    csr_fill<<<edgeTB, 256, 0, sB>>>(src, dst, E);
    zero_pool<<<(NG * DF + 255) / 256, 256, 0, sB>>>();

    prep_all<<<24, 256>>>(W[0], W[1], W[2]);
    gemm_mma<<<gemmB, 256, GS_TOT>>>(x, 0, wf, al[0], ar[0], n, 0);

    cudaEventRecord(evJ, sB);
    cudaStreamWaitEvent(0, evJ, 0);

    gat_node<<<warpNB, 256>>>(bb[0], n, 0, 0, batch, out_last);
    for (int L = 1; L < 3; L++) {
        gemm_mma<<<gemmB, 256, GS_TOT>>>(hh, 1, wf + L * 2048, al[L], ar[L], n, L);
        gat_node<<<warpNB, 256>>>(bb[L], n, L, (L == 2) ? 1 : 0, batch, out_last);
    }

    mlp_kernel<<<NG, 128>>>(lin1w, lin1b, lin2w, lin2b, out_logits);
}

// round 12
// speedup vs baseline: 3.4919x; 1.0042x over previous
#include <cuda_runtime.h>
#include <cuda_bf16.h>
#include <cuda_fp16.h>
#include <cstdint>
#include <math.h>

#define NND 100000
#define NE  1600000
#define DF  128
#define HEADS 4
#define NG  64
#define NCLS 10
#define NEG 0.2f
#define SCANB 512

// ---------------- scratch ----------------------------------------------------
__device__ __align__(16) __half g_XWh[NND * DF];   // fp16 x@W (messages+self)
__device__ __align__(16) __half g_Hh [NND * DF];   // fp16 relu(layer output)
__device__ __align__(16) float  g_al[NND * HEADS];
__device__ __align__(16) float  g_ar[NND * HEADS];
__device__ unsigned g_gmaxenc[3][HEADS];
__device__ int   g_deg[NND];
__device__ int   g_rowptr[NND + 1];
__device__ int   g_pos[NND];
__device__ int   g_bsum[(NND + SCANB - 1) / SCANB];
__device__ int   g_csr[NE];
__device__ float g_pool[NG * DF];
__device__ int   g_cnt[NG];
__device__ __align__(16) uint4 g_WfT[3][2048];     // fp16 W^T swizzled

// ---------------- helpers ----------------------------------------------------
__device__ __forceinline__ float lrelu(float x) { return x > 0.f ? x : NEG * x; }
__device__ __forceinline__ unsigned fenc(float f) {
    unsigned u = __float_as_uint(f);
    return (u & 0x80000000u) ? ~u : (u | 0x80000000u);
}
__device__ __forceinline__ float fdec(unsigned u) {
    return (u & 0x80000000u) ? __uint_as_float(u & 0x7FFFFFFFu)
                             : __uint_as_float(~u);
}
__device__ __forceinline__ float sel4(float4 v, int h) {
    return h == 0 ? v.x : h == 1 ? v.y : h == 2 ? v.z : v.w;
}
__device__ __forceinline__ void redAdd4(float* p, float4 v) {
    asm volatile("red.global.add.v4.f32 [%0], {%1,%2,%3,%4};"
                 :: "l"(p), "f"(v.x), "f"(v.y), "f"(v.z), "f"(v.w) : "memory");
}
__device__ __forceinline__ void stcs4(float* p, float4 v) {
    asm volatile("st.global.cs.v4.f32 [%0], {%1,%2,%3,%4};"
                 :: "l"(p), "f"(v.x), "f"(v.y), "f"(v.z), "f"(v.w) : "memory");
}
__device__ __forceinline__ void stcs2u(void* p, uint2 u) {
    asm volatile("st.global.cs.v2.u32 [%0], {%1,%2};"
                 :: "l"(p), "r"(u.x), "r"(u.y) : "memory");
}
__device__ __forceinline__ uint32_t smem_u32(const void* p) {
    uint32_t a;
    asm("{ .reg .u64 t; cvta.to.shared.u64 t, %1; cvt.u32.u64 %0, t; }" : "=r"(a) : "l"(p));
    return a;
}
__device__ __forceinline__ void ldm4(uint32_t& r0, uint32_t& r1, uint32_t& r2,
                                     uint32_t& r3, uint32_t addr) {
    asm volatile("ldmatrix.sync.aligned.m8n8.x4.shared.b16 {%0,%1,%2,%3}, [%4];"
                 : "=r"(r0), "=r"(r1), "=r"(r2), "=r"(r3) : "r"(addr));
}
__device__ __forceinline__ void mma16816f(float* d, uint32_t a0, uint32_t a1,
                                          uint32_t a2, uint32_t a3,
                                          uint32_t b0, uint32_t b1) {
    asm volatile(
        "mma.sync.aligned.m16n8k16.row.col.f32.f16.f16.f32 "
        "{%0,%1,%2,%3}, {%4,%5,%6,%7}, {%8,%9}, {%0,%1,%2,%3};"
        : "+f"(d[0]), "+f"(d[1]), "+f"(d[2]), "+f"(d[3])
        : "r"(a0), "r"(a1), "r"(a2), "r"(a3), "r"(b0), "r"(b1));
}

union H16x8 { __half h[8]; uint4 u; };

// ---------------- weight prep + gmax zero (all layers, one launch) ------------
__global__ void prep_all(const float* __restrict__ W0, const float* __restrict__ W1,
                         const float* __restrict__ W2) {
    if (blockIdx.x == 0 && threadIdx.x < 12)
        ((unsigned*)g_gmaxenc)[threadIdx.x] = 0u;
    int L = blockIdx.x >> 3;
    int i = (blockIdx.x & 7) * 256 + threadIdx.x;
    const float* W = (L == 0) ? W0 : (L == 1) ? W1 : W2;
    int nn = i >> 4, c = i & 15;
    H16x8 F;
#pragma unroll
    for (int j = 0; j < 8; j++)
        F.h[j] = __float2half(W[(c * 8 + j) * 128 + nn]);
    g_WfT[L][nn * 16 + (c ^ (nn & 7))] = F.u;
}

// ---------------- fp16 HMMA GEMM + fused al/ar + almax -----------------------
// smem: mainloop A 16KB + W 32KB; epilogue reuses as fp16 staged C (64x136 half)
#define GS_A   0
#define GS_W   16384
#define GS_ATT 49152
#define GS_TOT 50176
#define HS_STRIDE 136   // halfs per row (272 B, 16B-aligned)

__global__ void __launch_bounds__(256, 3) gemm_mma(
    const void* __restrict__ Ain, int aHalf, const uint4* __restrict__ WfT,
    const float* __restrict__ attl, const float* __restrict__ attr,
    int n, int Lidx) {
    extern __shared__ char smem[];
    __shared__ unsigned smax[4];
    uint32_t sb = smem_u32(smem);
    int tid = threadIdx.x, w = tid >> 5, l = tid & 31;
    int rg = w & 3, ch = w >> 2;
    int row0 = blockIdx.x * 64;

    {
        uint4* wf = (uint4*)(smem + GS_W);
        for (int i = tid; i < 2048; i += 256) wf[i] = WfT[i];
    }
    if (aHalf) {
        const __half* Ah = (const __half*)Ain;   // already relu'd fp16
        for (int i = tid; i < 1024; i += 256) {
            int r = i >> 4, c = i & 15;
            int row = row0 + r;
            uint4 u = make_uint4(0u, 0u, 0u, 0u);
            if (row < n) u = __ldcs((const uint4*)&Ah[row * 128 + c * 8]);
            *(uint4*)(smem + GS_A + r * 256 + ((c ^ (r & 7)) << 4)) = u;
        }
    } else {
        const float* A = (const float*)Ain;      // layer 0: raw fp32 x
        for (int i = tid; i < 1024; i += 256) {
            int r = i >> 4, c = i & 15;
            int row = row0 + r;
            float4 v0 = make_float4(0.f, 0.f, 0.f, 0.f), v1 = v0;
            if (row < n) {
                v0 = __ldcs((const float4*)&A[row * 128 + c * 8]);
                v1 = __ldcs((const float4*)&A[row * 128 + c * 8 + 4]);
            }
            H16x8 F;
            F.h[0] = __float2half(v0.x); F.h[1] = __float2half(v0.y);
            F.h[2] = __float2half(v0.z); F.h[3] = __float2half(v0.w);
            F.h[4] = __float2half(v1.x); F.h[5] = __float2half(v1.y);
            F.h[6] = __float2half(v1.z); F.h[7] = __float2half(v1.w);
            *(uint4*)(smem + GS_A + r * 256 + ((c ^ (r & 7)) << 4)) = F.u;
        }
    }
    __syncthreads();

    int aRow = rg * 16 + ((l >> 3) & 1) * 8 + (l & 7);
    int aChk = (l >> 4) & 1;
    uint32_t aBase = sb + GS_A + aRow * 256;
    int aXor = aRow & 7;
    int bRowL = ((l >> 4) & 1) * 8 + (l & 7);
    int bChk = (l >> 3) & 1;

    float acc[32];
#pragma unroll
    for (int i = 0; i < 32; i++) acc[i] = 0.f;

#pragma unroll
    for (int ks = 0; ks < 8; ks++) {
        uint32_t a0, a1, a2, a3;
        ldm4(a0, a1, a2, a3, aBase + (((2 * ks + aChk) ^ aXor) << 4));
#pragma unroll
        for (int p = 0; p < 4; p++) {
            int bRow = ch * 64 + p * 16 + bRowL;
            uint32_t bAddr = sb + GS_W + bRow * 256
                           + (((2 * ks + bChk) ^ (bRow & 7)) << 4);
            uint32_t b0, b1, b2, b3;
            ldm4(b0, b1, b2, b3, bAddr);
            mma16816f(&acc[(2 * p) * 4],     a0, a1, a2, a3, b0, b1);
            mma16816f(&acc[(2 * p + 1) * 4], a0, a1, a2, a3, b2, b3);
        }
    }
    __syncthreads();

    // ---- epilogue: stage fp16 C in smem (64 x HS_STRIDE halfs) ----
    __half* Hs = (__half*)smem;
    float* att = (float*)(smem + GS_ATT);
    att[tid] = (tid < 128) ? attl[tid] : attr[tid - 128];
    if (tid < 4) smax[tid] = 0u;
    {
        int r1 = rg * 16 + (l >> 2);
#pragma unroll
        for (int nt = 0; nt < 8; nt++) {
            int p = nt >> 1, t = nt & 1;
            int col = ch * 64 + p * 16 + t * 8 + (l & 3) * 2;
            float* d = &acc[nt * 4];
            __half2 lo = __floats2half2_rn(d[0], d[1]);
            __half2 hi = __floats2half2_rn(d[2], d[3]);
            *(__half2*)&Hs[r1 * HS_STRIDE + col]       = lo;
            *(__half2*)&Hs[(r1 + 8) * HS_STRIDE + col] = hi;
        }
    }
    __syncthreads();

    // XWh store: 64 rows x 256 B, uint4 coalesced
    for (int i = tid; i < 1024; i += 256) {
        int r = i >> 4, c = i & 15;
        int row = row0 + r;
        if (row < n)
            *(uint4*)&g_XWh[row * 128 + c * 8] =
                *(uint4*)&Hs[r * HS_STRIDE + c * 8];
    }
    // al / ar dots (fp16 inputs, fp32 accumulate) + block-local al max
    if (tid < 128) {
        int half_ = tid >> 6;
        int r = tid & 63;
        int row = row0 + r;
        if (row < n) {
            const float* av = att + half_ * 128;
            const __half2* hr = (const __half2*)&Hs[r * HS_STRIDE];
            float d0 = 0.f, d1 = 0.f, d2 = 0.f, d3 = 0.f;
#pragma unroll 8
            for (int c = 0; c < 16; c++) {
                float2 f0 = __half22float2(hr[c]);
                float2 f1 = __half22float2(hr[16 + c]);
                float2 f2 = __half22float2(hr[32 + c]);
                float2 f3 = __half22float2(hr[48 + c]);
                d0 += f0.x * av[2 * c]      + f0.y * av[2 * c + 1];
                d1 += f1.x * av[32 + 2 * c] + f1.y * av[32 + 2 * c + 1];
                d2 += f2.x * av[64 + 2 * c] + f2.y * av[64 + 2 * c + 1];
                d3 += f3.x * av[96 + 2 * c] + f3.y * av[96 + 2 * c + 1];
            }
            float* dst = half_ ? g_ar : g_al;
            *(float4*)&dst[row * 4] = make_float4(d0, d1, d2, d3);
            if (half_ == 0) {
                atomicMax(&smax[0], fenc(d0));
                atomicMax(&smax[1], fenc(d1));
                atomicMax(&smax[2], fenc(d2));
                atomicMax(&smax[3], fenc(d3));
            }
        }
    }
    __syncthreads();
    if (tid < 4) atomicMax(&g_gmaxenc[Lidx][tid], smax[tid]);
}

// ---------------- CSR build --------------------------------------------------
__global__ void zero_deg(int n) {
    int i = blockIdx.x * blockDim.x + threadIdx.x;
    if (i < n) g_deg[i] = 0;
}
__global__ void count_deg(const int* __restrict__ dst, int E) {
    int e = blockIdx.x * blockDim.x + threadIdx.x;
    if (e < E) atomicAdd(&g_deg[dst[e]], 1);
}
__global__ void scanA(int n) {
    __shared__ int sh[SCANB];
    int i = blockIdx.x * SCANB + threadIdx.x;
    int v = (i < n) ? g_deg[i] : 0;
    sh[threadIdx.x] = v;
    __syncthreads();
    for (int off = 1; off < SCANB; off <<= 1) {
        int t = (threadIdx.x >= off) ? sh[threadIdx.x - off] : 0;
        __syncthreads();
        sh[threadIdx.x] += t;
        __syncthreads();
    }
    if (i < n) g_rowptr[i] = sh[threadIdx.x] - v;
    if (threadIdx.x == SCANB - 1) g_bsum[blockIdx.x] = sh[SCANB - 1];
}
__global__ void scanB(int nb) {
    __shared__ int sh[256];
    int v = (threadIdx.x < nb) ? g_bsum[threadIdx.x] : 0;
    sh[threadIdx.x] = v;
    __syncthreads();
    for (int off = 1; off < 256; off <<= 1) {
        int t = (threadIdx.x >= off) ? sh[threadIdx.x - off] : 0;
        __syncthreads();
        sh[threadIdx.x] += t;
        __syncthreads();
    }
    if (threadIdx.x < nb) g_bsum[threadIdx.x] = sh[threadIdx.x] - v;
}
__global__ void scanC(int n, int E) {
    int i = blockIdx.x * blockDim.x + threadIdx.x;
    if (i < NG * DF) g_pool[i] = 0.f;     // fused pool zero
    if (i < NG) g_cnt[i] = 0;
    if (i < n) {
        int r = g_rowptr[i] + g_bsum[i / SCANB];
        g_rowptr[i] = r;
        g_pos[i] = r;
    }
    if (i == 0) g_rowptr[n] = E;
}
__global__ void csr_fill(const int* __restrict__ src, const int* __restrict__ dst, int E) {
    int e = blockIdx.x * blockDim.x + threadIdx.x;
    if (e >= E) return;
    int p = atomicAdd(&g_pos[dst[e]], 1);
    g_csr[p] = src[e];
}

// ---------------- fused per-node GAT ------------------------------------------
__global__ void gat_node(const float* __restrict__ bias, int n, int L, int last,
                         const int* __restrict__ batch, float* __restrict__ lastOut) {
    int wid = (blockIdx.x * blockDim.x + threadIdx.x) >> 5;
    int l = threadIdx.x & 31;
    if (wid >= n) return;
    int rp = g_rowptr[wid], re = g_rowptr[wid + 1];

    float4 ad = *(const float4*)&g_al[wid * 4];
    float4 bd = *(const float4*)&g_ar[wid * 4];

    int h = l >> 3;
    int eo = l & 7;
    float arh  = sel4(bd, h);
    float mh   = lrelu(fdec(g_gmaxenc[L][h]) + arh);
    float slgh = lrelu(sel4(ad, h) + arh);

    float zacc = 0.f;
    float4 acc = make_float4(0.f, 0.f, 0.f, 0.f);

    int s_cur = wid; float als_cur = 0.f;
    if (rp + eo < re) {
        s_cur = g_csr[rp + eo];
        als_cur = __ldg(&g_al[s_cur * 4 + h]);
    }
    for (int j0 = rp; j0 < re; j0 += 8) {
        int s_nxt = wid; float als_nxt = 0.f;
        if (j0 + 8 + eo < re) {
            s_nxt = g_csr[j0 + 8 + eo];
            als_nxt = __ldg(&g_al[s_nxt * 4 + h]);
        }
        float e_l = 0.f;
        if (j0 + eo < re) {
            e_l = __expf(lrelu(als_cur + arh) - mh);
            zacc += e_l;
        }
        int kmax = min(8, re - j0);
#pragma unroll 8
        for (int k = 0; k < kmax; k++) {
            int s = __shfl_sync(0xFFFFFFFFu, s_cur, k);
            float ek = __shfl_sync(0xFFFFFFFFu, e_l, (l & 24) | k);
            uint2 u = *(const uint2*)&g_XWh[s * 128 + 4 * l];
            __half2 p0 = *(__half2*)&u.x, p1 = *(__half2*)&u.y;
            float2 f0 = __half22float2(p0), f1 = __half22float2(p1);
            acc.x += ek * f0.x; acc.y += ek * f0.y;
            acc.z += ek * f1.x; acc.w += ek * f1.y;
        }
        s_cur = s_nxt; als_cur = als_nxt;
    }
#pragma unroll
    for (int o = 1; o < 8; o <<= 1) zacc += __shfl_xor_sync(0xFFFFFFFFu, zacc, o);

    float eself = __expf(slgh - mh);
    float rz = 1.f / (zacc + eself);
    uint2 us = *(const uint2*)&g_XWh[wid * 128 + 4 * l];
    __half2 s0 = *(__half2*)&us.x, s1 = *(__half2*)&us.y;
    float2 fs0 = __half22float2(s0), fs1 = __half22float2(s1);
    float4 bv = *(const float4*)&bias[4 * l];
    float4 o;
    o.x = fmaxf((acc.x + eself * fs0.x) * rz + bv.x, 0.f);
    o.y = fmaxf((acc.y + eself * fs0.y) * rz + bv.y, 0.f);
    o.z = fmaxf((acc.z + eself * fs1.x) * rz + bv.z, 0.f);
    o.w = fmaxf((acc.w + eself * fs1.y) * rz + bv.w, 0.f);

    if (!last) {
        __half2 h0 = __floats2half2_rn(o.x, o.y);
        __half2 h1 = __floats2half2_rn(o.z, o.w);
        uint2 u;
        u.x = *(uint32_t*)&h0; u.y = *(uint32_t*)&h1;
        stcs2u(&g_Hh[wid * 128 + 4 * l], u);
    } else {
        stcs4(&lastOut[wid * 128 + 4 * l], o);
        int b = batch[wid];
        redAdd4(&g_pool[b * 128 + 4 * l], o);
        if (l == 0) atomicAdd(&g_cnt[b], 1);
    }
}

// ---------------- MLP head ----------------------------------------------------
__global__ void mlp_kernel(const float* __restrict__ lin1w, const float* __restrict__ lin1b,
                           const float* __restrict__ lin2w, const float* __restrict__ lin2b,
                           float* __restrict__ out) {
    __shared__ float pr[128];
    __shared__ float gg[128];
    __shared__ float lo[NCLS];
    int gr = blockIdx.x;
    int c = threadIdx.x;
    float cnt = (float)max(g_cnt[gr], 1);
    pr[c] = g_pool[gr * 128 + c] / cnt;
    __syncthreads();
    float acc = lin1b[c];
#pragma unroll 8
    for (int k = 0; k < 128; k++) acc += pr[k] * lin1w[k * 128 + c];
    gg[c] = fmaxf(acc, 0.f);
    __syncthreads();
    if (c < NCLS) {
        float a = lin2b[c];
#pragma unroll 8
        for (int k = 0; k < 128; k++) a += gg[k] * lin2w[k * NCLS + c];
        lo[c] = a;
    }
    __syncthreads();
    if (c == 0) {
        float mx = lo[0];
#pragma unroll
        for (int j = 1; j < NCLS; j++) mx = fmaxf(mx, lo[j]);
        float s = 0.f;
#pragma unroll
        for (int j = 0; j < NCLS; j++) s += expf(lo[j] - mx);
        float lse = mx + logf(s);
#pragma unroll
        for (int j = 0; j < NCLS; j++) out[gr * NCLS + j] = lo[j] - lse;
    }
}

// ---------------- host launcher ---------------------------------------------
extern "C" void kernel_launch(void* const* d_in, const int* in_sizes, int n_in,
                              void* d_out, int out_size) {
    const float* x    = (const float*)d_in[0];
    const int*   eidx = (const int*)d_in[1];
    const int*   batch= (const int*)d_in[2];
    const float* W[3]  = { (const float*)d_in[3], (const float*)d_in[7],  (const float*)d_in[11] };
    const float* al[3] = { (const float*)d_in[4], (const float*)d_in[8],  (const float*)d_in[12] };
    const float* ar[3] = { (const float*)d_in[5], (const float*)d_in[9],  (const float*)d_in[13] };
    const float* bb[3] = { (const float*)d_in[6], (const float*)d_in[10], (const float*)d_in[14] };
    const float* lin1w = (const float*)d_in[15];
    const float* lin1b = (const float*)d_in[16];
    const float* lin2w = (const float*)d_in[17];
    const float* lin2b = (const float*)d_in[18];

    int n = in_sizes[0] / DF;
    int E = in_sizes[1] / 2;
    const int* src = eidx;
    const int* dst = eidx + E;

    float* out_logits = (float*)d_out;
    float* out_last   = (float*)d_out + NG * NCLS;

    __half* hh; cudaGetSymbolAddress((void**)&hh, g_Hh);
    uint4* wf; cudaGetSymbolAddress((void**)&wf, g_WfT);

    static int inited = 0;
    static cudaStream_t sB;
    static cudaEvent_t evF, evJ;
    if (!inited) {
        cudaFuncSetAttribute(gemm_mma, cudaFuncAttributeMaxDynamicSharedMemorySize, GS_TOT);
        cudaStreamCreateWithFlags(&sB, cudaStreamNonBlocking);
        cudaEventCreateWithFlags(&evF, cudaEventDisableTiming);
        cudaEventCreateWithFlags(&evJ, cudaEventDisableTiming);
        inited = 1;
    }

    int warpNB = (n * 32 + 255) / 256;
    int edgeTB = (E + 255) / 256;
    int nodeTB = (n + 255) / 256;
    int nScanB = (n + SCANB - 1) / SCANB;
    int gemmB  = (n + 63) / 64;

    // main: prep (0); fork side CSR chain; gemm L0 at launch idx 3 (profiled)
    prep_all<<<24, 256>>>(W[0], W[1], W[2]);                              // 0
    cudaEventRecord(evF, 0);
    cudaStreamWaitEvent(sB, evF, 0);
    zero_deg<<<nodeTB, 256, 0, sB>>>(n);                                  // 1
    count_deg<<<edgeTB, 256, 0, sB>>>(dst, E);                            // 2
    gemm_mma<<<gemmB, 256, GS_TOT>>>(x, 0, wf, al[0], ar[0], n, 0);       // 3 <- profiled
    scanA<<<nScanB, SCANB, 0, sB>>>(n);                                   // 4
    scanB<<<1, 256, 0, sB>>>(nScanB);                                     // 5
    scanC<<<nodeTB, 256, 0, sB>>>(n, E);                                  // 6 (+pool zero)
    csr_fill<<<edgeTB, 256, 0, sB>>>(src, dst, E);                        // 7

    cudaEventRecord(evJ, sB);
    cudaStreamWaitEvent(0, evJ, 0);

    gat_node<<<warpNB, 256>>>(bb[0], n, 0, 0, batch, out_last);           // 8
    for (int L = 1; L < 3; L++) {
        gemm_mma<<<gemmB, 256, GS_TOT>>>(hh, 1, wf + L * 2048, al[L], ar[L], n, L);
        gat_node<<<warpNB, 256>>>(bb[L], n, L, (L == 2) ? 1 : 0, batch, out_last);
    }

    mlp_kernel<<<NG, 128>>>(lin1w, lin1b, lin2w, lin2b, out_logits);
}